// round 1
// baseline (speedup 1.0000x reference)
#include <cuda_runtime.h>
#include <math.h>

#define BB 2
#define LL 4096
#define DDIM 2048
#define HH 8
#define DH 256
#define BT 64
#define NC 64          // LL / BT
#define BLD (BB*LL*DDIM)

// -------------------- scratch (device globals; no allocation) --------------------
__device__ float g_preq[BLD];
__device__ float g_prek[BLD];
__device__ float g_prev[BLD];
__device__ float g_qt[BLD];      // [B,H,L,DH]  l2norm * dk^-0.5
__device__ float g_kt[BLD];      // [B,H,L,DH]  l2norm
__device__ float g_vt[BLD];      // [B,H,L,DH]
__device__ float g_wt[BLD];      // W = T @ (k*beta)
__device__ float g_ut[BLD];      // U = T @ (v*beta)
__device__ float g_beta[BB*HH*LL];
__device__ float g_att[(size_t)BB*HH*NC*BT*BT];  // tril(q k^T) per chunk, 16MB
__device__ float g_og[BLD];      // scan output [B,L,H,DH] == [B,L,D]
__device__ float g_on[BLD];      // rmsnormed

// -------------------- GEMM: C[M,N] = A[M,K] * B[N,K]^T (NT, fp32) --------------------
__global__ __launch_bounds__(256) void sgemm_nt(
    const float* __restrict__ A, const float* __restrict__ B,
    float* __restrict__ C, int M, int N, int K)
{
  __shared__ float As[16 * 132];
  __shared__ float Bs[16 * 132];
  const int tid = threadIdx.x;
  const int bm = blockIdx.y * 128;
  const int bn = blockIdx.x * 128;
  const int tx = tid & 15, ty = tid >> 4;

  float acc[8][8];
#pragma unroll
  for (int i = 0; i < 8; i++)
#pragma unroll
    for (int j = 0; j < 8; j++) acc[i][j] = 0.f;

  for (int k0 = 0; k0 < K; k0 += 16) {
#pragma unroll
    for (int it = 0; it < 2; it++) {
      int f = tid + it * 256;          // 512 float4 loads per tile
      int r = f >> 2;
      int c4 = (f & 3) * 4;
      float4 va = *(const float4*)(A + (size_t)(bm + r) * K + k0 + c4);
      As[(c4 + 0) * 132 + r] = va.x;
      As[(c4 + 1) * 132 + r] = va.y;
      As[(c4 + 2) * 132 + r] = va.z;
      As[(c4 + 3) * 132 + r] = va.w;
      float4 vb = *(const float4*)(B + (size_t)(bn + r) * K + k0 + c4);
      Bs[(c4 + 0) * 132 + r] = vb.x;
      Bs[(c4 + 1) * 132 + r] = vb.y;
      Bs[(c4 + 2) * 132 + r] = vb.z;
      Bs[(c4 + 3) * 132 + r] = vb.w;
    }
    __syncthreads();
#pragma unroll
    for (int kk = 0; kk < 16; kk++) {
      float4 a0 = *(const float4*)&As[kk * 132 + ty * 4];
      float4 a1 = *(const float4*)&As[kk * 132 + 64 + ty * 4];
      float4 b0 = *(const float4*)&Bs[kk * 132 + tx * 4];
      float4 b1 = *(const float4*)&Bs[kk * 132 + 64 + tx * 4];
      float a[8] = {a0.x, a0.y, a0.z, a0.w, a1.x, a1.y, a1.z, a1.w};
      float b[8] = {b0.x, b0.y, b0.z, b0.w, b1.x, b1.y, b1.z, b1.w};
#pragma unroll
      for (int i = 0; i < 8; i++)
#pragma unroll
        for (int j = 0; j < 8; j++) acc[i][j] += a[i] * b[j];
    }
    __syncthreads();
  }
#pragma unroll
  for (int i = 0; i < 8; i++) {
    int m = bm + ((i < 4) ? (ty * 4 + i) : (64 + ty * 4 + i - 4));
    float4 c0 = make_float4(acc[i][0], acc[i][1], acc[i][2], acc[i][3]);
    float4 c1 = make_float4(acc[i][4], acc[i][5], acc[i][6], acc[i][7]);
    *(float4*)(C + (size_t)m * N + bn + tx * 4) = c0;
    *(float4*)(C + (size_t)m * N + bn + 64 + tx * 4) = c1;
  }
}

// -------------------- beta = sigmoid(hs @ Wb^T), [B,H,L] --------------------
__global__ __launch_bounds__(256) void beta_kernel(
    const float* __restrict__ hs, const float* __restrict__ Wb, float* __restrict__ beta)
{
  int bl = blockIdx.x;                  // b*LL + l
  int b = bl / LL, l = bl % LL;
  int w = threadIdx.x >> 5, lane = threadIdx.x & 31;   // warp = head
  const float* x = hs + (size_t)bl * DDIM;
  const float* wb = Wb + (size_t)w * DDIM;
  float s = 0.f;
  for (int d = lane; d < DDIM; d += 32) s += x[d] * wb[d];
#pragma unroll
  for (int o = 16; o; o >>= 1) s += __shfl_xor_sync(0xffffffffu, s, o);
  if (lane == 0)
    beta[((size_t)b * HH + w) * LL + l] = 1.f / (1.f + expf(-s));
}

// -------------------- causal depthwise conv + SiLU (+optional l2norm), to [B,H,L,DH] ----
// mode 0: q (l2norm * dk^-0.5), mode 1: k (l2norm), mode 2: v (plain)
__global__ __launch_bounds__(256) void conv_kernel(
    const float* __restrict__ pre, const float* __restrict__ cw,
    float* __restrict__ out, int mode)
{
  __shared__ float red[256];
  int idx = blockIdx.x;                 // (b*LL + l)*HH + h
  int h = idx % HH;
  int l = (idx / HH) % LL;
  int b = idx / (HH * LL);
  int dd = threadIdx.x;
  int c = h * DH + dd;
  float w0 = cw[c * 4 + 0], w1 = cw[c * 4 + 1], w2 = cw[c * 4 + 2], w3 = cw[c * 4 + 3];
  const float* base = pre + (size_t)b * LL * DDIM + c;
  float y = base[(size_t)l * DDIM] * w3;
  if (l >= 1) y += base[(size_t)(l - 1) * DDIM] * w2;
  if (l >= 2) y += base[(size_t)(l - 2) * DDIM] * w1;
  if (l >= 3) y += base[(size_t)(l - 3) * DDIM] * w0;
  y = y / (1.f + expf(-y));            // silu
  float scale = 1.f;
  if (mode < 2) {
    red[dd] = y * y;
    __syncthreads();
    for (int s = 128; s; s >>= 1) { if (dd < s) red[dd] += red[dd + s]; __syncthreads(); }
    scale = rsqrtf(red[0] + 1e-6f);
    if (mode == 0) scale *= 0.0625f;   // dk^-0.5, dk = 256
  }
  out[(((size_t)b * HH + h) * LL + l) * DH + dd] = y * scale;
}

// -------------------- per-chunk triangular solve: W = T kb, U = T vb ----------------
__global__ __launch_bounds__(512) void solve_kernel(
    const float* __restrict__ kt, const float* __restrict__ vt,
    const float* __restrict__ beta, float* __restrict__ Wt, float* __restrict__ Ut)
{
  extern __shared__ float sh[];
  float* sk = sh;                 // [64][257]  k
  float* sw = sk + 64 * 257;      // [64][257]  k*beta -> W
  float* su = sw + 64 * 257;      // [64][257]  v*beta -> U
  float* sM = su + 64 * 257;      // [64][64]
  float* sb = sM + 64 * 64;       // [64]
  int blk = blockIdx.x;
  int c = blk % NC, bh = blk / NC;
  size_t base = ((size_t)bh * LL + (size_t)c * BT) * DH;
  int tid = threadIdx.x;

  if (tid < 64) sb[tid] = beta[(size_t)bh * LL + c * BT + tid];
  __syncthreads();
  for (int i = tid; i < BT * DH; i += 512) {
    int t = i >> 8, d = i & 255;
    float kv = kt[base + i];
    float bt = sb[t];
    sk[t * 257 + d] = kv;
    sw[t * 257 + d] = kv * bt;
    su[t * 257 + d] = vt[base + i] * bt;
  }
  __syncthreads();
  // M = strict_lower(kb @ k^T)
  for (int e = tid; e < BT * BT; e += 512) {
    int t = e >> 6, s = e & 63;
    float acc = 0.f;
    if (s < t) {
      const float* kb = &sw[t * 257];
      const float* kk = &sk[s * 257];
#pragma unroll 8
      for (int d = 0; d < DH; d++) acc += kb[d] * kk[d];
    }
    sM[e] = acc;
  }
  __syncthreads();
  // unit-lower forward substitution: row t -= sum_{s<t} M[t,s]*row s  (per-column threads)
  if (tid < 256) {
    int d = tid;
    for (int t = 1; t < BT; t++) {
      float aw = 0.f;
      const float* Mr = &sM[t * 64];
      for (int s = 0; s < t; s++) aw += Mr[s] * sw[s * 257 + d];
      sw[t * 257 + d] -= aw;
    }
  } else {
    int d = tid - 256;
    for (int t = 1; t < BT; t++) {
      float au = 0.f;
      const float* Mr = &sM[t * 64];
      for (int s = 0; s < t; s++) au += Mr[s] * su[s * 257 + d];
      su[t * 257 + d] -= au;
    }
  }
  __syncthreads();
  for (int i = tid; i < BT * DH; i += 512) {
    int t = i >> 8, d = i & 255;
    Wt[base + i] = sw[t * 257 + d];
    Ut[base + i] = su[t * 257 + d];
  }
}

// -------------------- attn = tril(q k^T) per (bh, chunk) --------------------
__global__ __launch_bounds__(256) void attn_kernel(
    const float* __restrict__ qt, const float* __restrict__ kt, float* __restrict__ att)
{
  extern __shared__ float sh[];
  float* sq = sh;                // [64][257]
  float* sk = sq + 64 * 257;     // [64][257]
  int blk = blockIdx.x;
  int c = blk % NC, bh = blk / NC;
  size_t base = ((size_t)bh * LL + (size_t)c * BT) * DH;
  int tid = threadIdx.x;
  for (int i = tid; i < BT * DH; i += 256) {
    int t = i >> 8, d = i & 255;
    sq[t * 257 + d] = qt[base + i];
    sk[t * 257 + d] = kt[base + i];
  }
  __syncthreads();
  float* ap = att + (size_t)blk * (BT * BT);
  for (int e = tid; e < BT * BT; e += 256) {
    int t = e >> 6, s = e & 63;
    float acc = 0.f;
    if (s <= t) {
      const float* q = &sq[t * 257];
      const float* k = &sk[s * 257];
#pragma unroll 8
      for (int d = 0; d < DH; d++) acc += q[d] * k[d];
    }
    ap[e] = acc;
  }
}

// -------------------- sequential chunk scan, dv split 8 ways --------------------
// grid = B*H*8, 256 threads. S slice [256][32] in smem.
__global__ __launch_bounds__(256) void scan_kernel(
    const float* __restrict__ qt, const float* __restrict__ kt,
    const float* __restrict__ wt, const float* __restrict__ ut,
    const float* __restrict__ att, float* __restrict__ og)
{
  extern __shared__ float sh[];
  float* S  = sh;                 // [256][36]
  float* Aq = S + 256 * 36;       // [64][257]  q, then w
  float* Bk = Aq + 64 * 257;      // [64][257]  k
  float* Tt = Bk + 64 * 257;      // [64][64]   attn
  float* Un = Tt + 64 * 64;       // [64][36]   u_new
  int blk = blockIdx.x;
  int vb = blk & 7;
  int bh = blk >> 3;
  int b = bh / HH, h = bh % HH;
  int tid = threadIdx.x;
  int tx = tid & 7;               // v float4 group (v = tx*4, slice of 32)
  int ty = tid >> 3;              // 0..31
  int t0 = ty * 2, t1 = t0 + 1;
  int v0 = tx * 4;

  for (int i = tid; i < 256 * 36; i += 256) S[i] = 0.f;
  __syncthreads();

  for (int c = 0; c < NC; c++) {
    size_t base = ((size_t)bh * LL + (size_t)c * BT) * DH;
    const float* ap = att + ((size_t)bh * NC + c) * (BT * BT);
    // load q, k, attn tiles
    for (int i = tid; i < BT * DH; i += 256) {
      int t = i >> 8, d = i & 255;
      Aq[t * 257 + d] = qt[base + i];
      Bk[t * 257 + d] = kt[base + i];
    }
    for (int i = tid; i < BT * BT; i += 256) Tt[i] = ap[i];
    __syncthreads();

    // o1 = q @ S
    float4 r0 = make_float4(0, 0, 0, 0), r1 = make_float4(0, 0, 0, 0);
    for (int d = 0; d < DH; d++) {
      float4 sv = *(float4*)&S[d * 36 + v0];
      float q0 = Aq[t0 * 257 + d], q1 = Aq[t1 * 257 + d];
      r0.x += q0 * sv.x; r0.y += q0 * sv.y; r0.z += q0 * sv.z; r0.w += q0 * sv.w;
      r1.x += q1 * sv.x; r1.y += q1 * sv.y; r1.z += q1 * sv.z; r1.w += q1 * sv.w;
    }
    __syncthreads();
    // load w -> Aq
    for (int i = tid; i < BT * DH; i += 256) {
      int t = i >> 8, d = i & 255;
      Aq[t * 257 + d] = wt[base + i];
    }
    __syncthreads();
    // u_new = u - w @ S
    {
      float4 a0 = make_float4(0, 0, 0, 0), a1 = make_float4(0, 0, 0, 0);
      for (int d = 0; d < DH; d++) {
        float4 sv = *(float4*)&S[d * 36 + v0];
        float w0 = Aq[t0 * 257 + d], w1 = Aq[t1 * 257 + d];
        a0.x += w0 * sv.x; a0.y += w0 * sv.y; a0.z += w0 * sv.z; a0.w += w0 * sv.w;
        a1.x += w1 * sv.x; a1.y += w1 * sv.y; a1.z += w1 * sv.z; a1.w += w1 * sv.w;
      }
      float4 u0 = *(const float4*)&ut[base + (size_t)t0 * DH + vb * 32 + v0];
      float4 u1 = *(const float4*)&ut[base + (size_t)t1 * DH + vb * 32 + v0];
      *(float4*)&Un[t0 * 36 + v0] = make_float4(u0.x - a0.x, u0.y - a0.y, u0.z - a0.z, u0.w - a0.w);
      *(float4*)&Un[t1 * 36 + v0] = make_float4(u1.x - a1.x, u1.y - a1.y, u1.z - a1.z, u1.w - a1.w);
    }
    __syncthreads();
    // o += attn @ u_new, write out
    for (int s = 0; s <= t1; s++) {
      float4 u4 = *(float4*)&Un[s * 36 + v0];
      float av1 = Tt[t1 * 64 + s];
      r1.x += av1 * u4.x; r1.y += av1 * u4.y; r1.z += av1 * u4.z; r1.w += av1 * u4.w;
      if (s <= t0) {
        float av0 = Tt[t0 * 64 + s];
        r0.x += av0 * u4.x; r0.y += av0 * u4.y; r0.z += av0 * u4.z; r0.w += av0 * u4.w;
      }
    }
    {
      size_t o0 = (((size_t)b * LL + c * BT + t0) * HH + h) * DH + vb * 32 + v0;
      size_t o1 = (((size_t)b * LL + c * BT + t1) * HH + h) * DH + vb * 32 + v0;
      *(float4*)&og[o0] = r0;
      *(float4*)&og[o1] = r1;
    }
    // S += k^T @ u_new  (thread owns S row d = tid)
    {
      int d = tid;
      float4 sa[8];
#pragma unroll
      for (int j = 0; j < 8; j++) sa[j] = *(float4*)&S[d * 36 + j * 4];
      for (int t = 0; t < BT; t++) {
        float kv = Bk[t * 257 + d];
#pragma unroll
        for (int j = 0; j < 8; j++) {
          float4 u4 = *(float4*)&Un[t * 36 + j * 4];
          sa[j].x += kv * u4.x; sa[j].y += kv * u4.y;
          sa[j].z += kv * u4.z; sa[j].w += kv * u4.w;
        }
      }
#pragma unroll
      for (int j = 0; j < 8; j++) *(float4*)&S[d * 36 + j * 4] = sa[j];
    }
    __syncthreads();
  }
}

// -------------------- per-head RMSNorm * g_norm --------------------
__global__ __launch_bounds__(256) void rms_kernel(
    const float* __restrict__ og, const float* __restrict__ gn, float* __restrict__ on)
{
  __shared__ float red[256];
  int idx = blockIdx.x;            // (b*LL + l)*HH + h
  int d = threadIdx.x;
  float v = og[(size_t)idx * DH + d];
  red[d] = v * v;
  __syncthreads();
  for (int s = 128; s; s >>= 1) { if (d < s) red[d] += red[d + s]; __syncthreads(); }
  float scale = rsqrtf(red[0] * (1.f / DH) + 1e-5f);
  on[(size_t)idx * DH + d] = v * scale * gn[d];
}

// -------------------- host launch --------------------
#define SOLVE_SMEM ((3*64*257 + 64*64 + 64) * 4)
#define ATTN_SMEM  ((2*64*257) * 4)
#define SCAN_SMEM  ((256*36 + 2*64*257 + 64*64 + 64*36) * 4)

extern "C" void kernel_launch(void* const* d_in, const int* in_sizes, int n_in,
                              void* d_out, int out_size)
{
  const float* hs = (const float*)d_in[0];
  const float* Wq = (const float*)d_in[1];
  const float* Wk = (const float*)d_in[2];
  const float* Wv = (const float*)d_in[3];
  const float* Wb = (const float*)d_in[4];
  const float* cq = (const float*)d_in[5];
  const float* ck = (const float*)d_in[6];
  const float* cv = (const float*)d_in[7];
  const float* gn = (const float*)d_in[8];
  const float* Wo = (const float*)d_in[9];
  float* out = (float*)d_out;

  float *preq, *prek, *prev, *qt, *kt, *vt, *wt, *ut, *beta, *att, *og, *on;
  cudaGetSymbolAddress((void**)&preq, g_preq);
  cudaGetSymbolAddress((void**)&prek, g_prek);
  cudaGetSymbolAddress((void**)&prev, g_prev);
  cudaGetSymbolAddress((void**)&qt, g_qt);
  cudaGetSymbolAddress((void**)&kt, g_kt);
  cudaGetSymbolAddress((void**)&vt, g_vt);
  cudaGetSymbolAddress((void**)&wt, g_wt);
  cudaGetSymbolAddress((void**)&ut, g_ut);
  cudaGetSymbolAddress((void**)&beta, g_beta);
  cudaGetSymbolAddress((void**)&att, g_att);
  cudaGetSymbolAddress((void**)&og, g_og);
  cudaGetSymbolAddress((void**)&on, g_on);

  cudaFuncSetAttribute(solve_kernel, cudaFuncAttributeMaxDynamicSharedMemorySize, SOLVE_SMEM);
  cudaFuncSetAttribute(attn_kernel, cudaFuncAttributeMaxDynamicSharedMemorySize, ATTN_SMEM);
  cudaFuncSetAttribute(scan_kernel, cudaFuncAttributeMaxDynamicSharedMemorySize, SCAN_SMEM);

  dim3 gg(DDIM / 128, (BB * LL) / 128);   // (16, 64)

  sgemm_nt<<<gg, 256>>>(hs, Wq, preq, BB * LL, DDIM, DDIM);
  sgemm_nt<<<gg, 256>>>(hs, Wk, prek, BB * LL, DDIM, DDIM);
  sgemm_nt<<<gg, 256>>>(hs, Wv, prev, BB * LL, DDIM, DDIM);
  beta_kernel<<<BB * LL, 256>>>(hs, Wb, beta);

  conv_kernel<<<BB * LL * HH, 256>>>(preq, cq, qt, 0);
  conv_kernel<<<BB * LL * HH, 256>>>(prek, ck, kt, 1);
  conv_kernel<<<BB * LL * HH, 256>>>(prev, cv, vt, 2);

  solve_kernel<<<BB * HH * NC, 512, SOLVE_SMEM>>>(kt, vt, beta, wt, ut);
  attn_kernel<<<BB * HH * NC, 256, ATTN_SMEM>>>(qt, kt, att);
  scan_kernel<<<BB * HH * 8, 256, SCAN_SMEM>>>(qt, kt, wt, ut, att, og);

  rms_kernel<<<BB * LL * HH, 256>>>(og, gn, on);
  sgemm_nt<<<gg, 256>>>(on, Wo, out, BB * LL, DDIM, DDIM);
}

// round 2
// speedup vs baseline: 1.5569x; 1.5569x over previous
#include <cuda_runtime.h>
#include <cuda_bf16.h>
#include <math.h>
#include <stdint.h>

#define BB 2
#define LL 4096
#define DDIM 2048
#define HH 8
#define DH 256
#define BT 64
#define NC 64          // LL / BT
#define BLD (BB*LL*DDIM)

// -------------------- scratch (device globals; no allocation) --------------------
__device__ float g_preq[BLD];
__device__ float g_prek[BLD];
__device__ float g_prev[BLD];
__device__ float g_qt[BLD];      // [B,H,L,DH]  l2norm * dk^-0.5
__device__ float g_kt[BLD];      // [B,H,L,DH]  l2norm
__device__ float g_vt[BLD];      // [B,H,L,DH]
__device__ float g_wt[BLD];      // W = T @ (k*beta)
__device__ float g_ut[BLD];      // U = T @ (v*beta)
__device__ float g_beta[BB*HH*LL];
__device__ float g_att[(size_t)BB*HH*NC*BT*BT];  // tril(q k^T) per chunk
__device__ float g_og[BLD];      // scan output [B,L,H,DH] == [B,L,D]
__device__ float g_on[BLD];      // rmsnormed

// ==================== bf16x3-split tensor-core GEMM ====================
// C[M,N] = A[M,K] @ B[N,K]^T in ~fp32 precision:
//   a = a_hi + a_lo (bf16 pair), C = Ahi*Bhi + Ahi*Blo + Alo*Bhi (fp32 accum)
// 128x128x32 CTA tile, 8 warps (2x4), warp tile 64x32, mma.m16n8k16.

#define GSTRIDE 40                     // padded bf16 row stride (80B, 16B aligned)
#define GTILE (128*GSTRIDE)            // elems per tile matrix
#define STAGE_ELEMS (4*GTILE)          // Ahi,Alo,Bhi,Blo
#define GEMM_SMEM (2*STAGE_ELEMS*2)    // bytes, 2 stages

__device__ __forceinline__ void ldsm4(uint32_t* r, uint32_t addr) {
  asm volatile("ldmatrix.sync.aligned.m8n8.x4.shared.b16 {%0,%1,%2,%3}, [%4];"
    : "=r"(r[0]), "=r"(r[1]), "=r"(r[2]), "=r"(r[3]) : "r"(addr));
}
__device__ __forceinline__ void mma16816(float* d, const uint32_t* a, uint32_t b0, uint32_t b1) {
  asm volatile("mma.sync.aligned.m16n8k16.row.col.f32.bf16.bf16.f32 "
    "{%0,%1,%2,%3}, {%4,%5,%6,%7}, {%8,%9}, {%0,%1,%2,%3};"
    : "+f"(d[0]), "+f"(d[1]), "+f"(d[2]), "+f"(d[3])
    : "r"(a[0]), "r"(a[1]), "r"(a[2]), "r"(a[3]), "r"(b0), "r"(b1));
}

__global__ __launch_bounds__(256) void gemm3_kernel(
    const float* __restrict__ A, const float* __restrict__ B, float* __restrict__ C,
    int M, int N, int K)
{
  extern __shared__ __nv_bfloat16 sm[];
  const int tid = threadIdx.x, lane = tid & 31, wid = tid >> 5;
  const int warp_m = wid >> 2, warp_n = wid & 3;
  const int bm = blockIdx.y * 128, bn = blockIdx.x * 128;

  float acc[4][4][4];
#pragma unroll
  for (int i = 0; i < 4; i++)
#pragma unroll
    for (int j = 0; j < 4; j++)
#pragma unroll
      for (int e = 0; e < 4; e++) acc[i][j][e] = 0.f;

  const int lr = tid >> 3;        // load row base (0..31)
  const int lc = (tid & 7) * 4;   // load col (float4)

  const uint32_t sbase = (uint32_t)__cvta_generic_to_shared(sm);
  const float* Abase = A + (size_t)bm * K;
  const float* Bbase = B + (size_t)bn * K;

  float4 ra[4], rb[4];
  // prologue: load kt=0
#pragma unroll
  for (int p = 0; p < 4; p++) {
    ra[p] = *(const float4*)(Abase + (size_t)(lr + p * 32) * K + lc);
    rb[p] = *(const float4*)(Bbase + (size_t)(lr + p * 32) * K + lc);
  }

  const int NT = K / 32;
  for (int kt = 0; kt < NT; kt++) {
    const int st = kt & 1;
    // split + store to smem
    {
      __nv_bfloat16* sA  = sm + st * STAGE_ELEMS;
      __nv_bfloat16* sAl = sA + GTILE;
      __nv_bfloat16* sB  = sA + 2 * GTILE;
      __nv_bfloat16* sBl = sA + 3 * GTILE;
#pragma unroll
      for (int p = 0; p < 4; p++) {
        int r = lr + p * 32;
        float av[4] = {ra[p].x, ra[p].y, ra[p].z, ra[p].w};
        float bv[4] = {rb[p].x, rb[p].y, rb[p].z, rb[p].w};
#pragma unroll
        for (int j = 0; j < 4; j++) {
          __nv_bfloat16 ha = __float2bfloat16(av[j]);
          sA [r * GSTRIDE + lc + j] = ha;
          sAl[r * GSTRIDE + lc + j] = __float2bfloat16(av[j] - __bfloat162float(ha));
          __nv_bfloat16 hb = __float2bfloat16(bv[j]);
          sB [r * GSTRIDE + lc + j] = hb;
          sBl[r * GSTRIDE + lc + j] = __float2bfloat16(bv[j] - __bfloat162float(hb));
        }
      }
    }
    __syncthreads();
    // prefetch next tile into regs (overlaps with compute below)
    if (kt + 1 < NT) {
      const float* Ab = Abase + (size_t)(kt + 1) * 32 + lc;
      const float* Bb = Bbase + (size_t)(kt + 1) * 32 + lc;
#pragma unroll
      for (int p = 0; p < 4; p++) {
        ra[p] = *(const float4*)(Ab + (size_t)(lr + p * 32) * K);
        rb[p] = *(const float4*)(Bb + (size_t)(lr + p * 32) * K);
      }
    }
    // compute
    const uint32_t stb = sbase + st * (STAGE_ELEMS * 2);
    const uint32_t aoff_hi = stb;
    const uint32_t aoff_lo = stb + GTILE * 2;
    const uint32_t boff_hi = stb + 2 * GTILE * 2;
    const uint32_t boff_lo = stb + 3 * GTILE * 2;
    const int arow  = warp_m * 64 + (lane & 15);
    const int acol0 = (lane >> 4) * 8;
    const int brow  = warp_n * 32 + (lane >> 4) * 8 + (lane & 7);
    const int bcol0 = ((lane >> 3) & 1) * 8;
#pragma unroll
    for (int kk = 0; kk < 32; kk += 16) {
      uint32_t ahi[4][4], alo[4][4], bhi[2][4], blo[2][4];
#pragma unroll
      for (int mt = 0; mt < 4; mt++) {
        uint32_t ab = (uint32_t)(((arow + mt * 16) * GSTRIDE + kk + acol0) * 2);
        ldsm4(ahi[mt], aoff_hi + ab);
        ldsm4(alo[mt], aoff_lo + ab);
      }
#pragma unroll
      for (int p = 0; p < 2; p++) {
        uint32_t bb = (uint32_t)(((brow + p * 16) * GSTRIDE + kk + bcol0) * 2);
        ldsm4(bhi[p], boff_hi + bb);
        ldsm4(blo[p], boff_lo + bb);
      }
#pragma unroll
      for (int mt = 0; mt < 4; mt++)
#pragma unroll
        for (int nt = 0; nt < 4; nt++) {
          const uint32_t* bh = bhi[nt >> 1];
          const uint32_t* bl = blo[nt >> 1];
          int bi = (nt & 1) * 2;
          mma16816(acc[mt][nt], ahi[mt], bh[bi], bh[bi + 1]);
          mma16816(acc[mt][nt], ahi[mt], bl[bi], bl[bi + 1]);
          mma16816(acc[mt][nt], alo[mt], bh[bi], bh[bi + 1]);
        }
    }
    __syncthreads();
  }
  // epilogue
  const int row0 = bm + warp_m * 64 + (lane >> 2);
  const int col0 = bn + warp_n * 32 + (lane & 3) * 2;
#pragma unroll
  for (int mt = 0; mt < 4; mt++)
#pragma unroll
    for (int nt = 0; nt < 4; nt++) {
      int r = row0 + mt * 16;
      int c = col0 + nt * 8;
      *(float2*)(C + (size_t)r * N + c)       = make_float2(acc[mt][nt][0], acc[mt][nt][1]);
      *(float2*)(C + (size_t)(r + 8) * N + c) = make_float2(acc[mt][nt][2], acc[mt][nt][3]);
    }
}

// -------------------- beta = sigmoid(hs @ Wb^T), [B,H,L] --------------------
__global__ __launch_bounds__(256) void beta_kernel(
    const float* __restrict__ hs, const float* __restrict__ Wb, float* __restrict__ beta)
{
  int bl = blockIdx.x;                  // b*LL + l
  int b = bl / LL, l = bl % LL;
  int w = threadIdx.x >> 5, lane = threadIdx.x & 31;   // warp = head
  const float* x = hs + (size_t)bl * DDIM;
  const float* wb = Wb + (size_t)w * DDIM;
  float s = 0.f;
  for (int d = lane; d < DDIM; d += 32) s += x[d] * wb[d];
#pragma unroll
  for (int o = 16; o; o >>= 1) s += __shfl_xor_sync(0xffffffffu, s, o);
  if (lane == 0)
    beta[((size_t)b * HH + w) * LL + l] = 1.f / (1.f + expf(-s));
}

// -------------------- causal depthwise conv + SiLU (+optional l2norm), to [B,H,L,DH] ----
// mode 0: q (l2norm * dk^-0.5), mode 1: k (l2norm), mode 2: v (plain)
__global__ __launch_bounds__(256) void conv_kernel(
    const float* __restrict__ pre, const float* __restrict__ cw,
    float* __restrict__ out, int mode)
{
  __shared__ float red[256];
  int idx = blockIdx.x;                 // (b*LL + l)*HH + h
  int h = idx % HH;
  int l = (idx / HH) % LL;
  int b = idx / (HH * LL);
  int dd = threadIdx.x;
  int c = h * DH + dd;
  float w0 = cw[c * 4 + 0], w1 = cw[c * 4 + 1], w2 = cw[c * 4 + 2], w3 = cw[c * 4 + 3];
  const float* base = pre + (size_t)b * LL * DDIM + c;
  float y = base[(size_t)l * DDIM] * w3;
  if (l >= 1) y += base[(size_t)(l - 1) * DDIM] * w2;
  if (l >= 2) y += base[(size_t)(l - 2) * DDIM] * w1;
  if (l >= 3) y += base[(size_t)(l - 3) * DDIM] * w0;
  y = y / (1.f + expf(-y));            // silu
  float scale = 1.f;
  if (mode < 2) {
    red[dd] = y * y;
    __syncthreads();
    for (int s = 128; s; s >>= 1) { if (dd < s) red[dd] += red[dd + s]; __syncthreads(); }
    scale = rsqrtf(red[0] + 1e-6f);
    if (mode == 0) scale *= 0.0625f;   // dk^-0.5, dk = 256
  }
  out[(((size_t)b * HH + h) * LL + l) * DH + dd] = y * scale;
}

// -------------------- per-chunk triangular solve: W = T kb, U = T vb ----------------
__global__ __launch_bounds__(512) void solve_kernel(
    const float* __restrict__ kt, const float* __restrict__ vt,
    const float* __restrict__ beta, float* __restrict__ Wt, float* __restrict__ Ut)
{
  extern __shared__ float sh[];
  float* sk = sh;                 // [64][257]  k
  float* sw = sk + 64 * 257;      // [64][257]  k*beta -> W
  float* su = sw + 64 * 257;      // [64][257]  v*beta -> U
  float* sM = su + 64 * 257;      // [64][64]
  float* sb = sM + 64 * 64;       // [64]
  int blk = blockIdx.x;
  int c = blk % NC, bh = blk / NC;
  size_t base = ((size_t)bh * LL + (size_t)c * BT) * DH;
  int tid = threadIdx.x;

  if (tid < 64) sb[tid] = beta[(size_t)bh * LL + c * BT + tid];
  __syncthreads();
  for (int i = tid; i < BT * DH; i += 512) {
    int t = i >> 8, d = i & 255;
    float kv = kt[base + i];
    float bt = sb[t];
    sk[t * 257 + d] = kv;
    sw[t * 257 + d] = kv * bt;
    su[t * 257 + d] = vt[base + i] * bt;
  }
  __syncthreads();
  // M = strict_lower(kb @ k^T)
  for (int e = tid; e < BT * BT; e += 512) {
    int t = e >> 6, s = e & 63;
    float acc = 0.f;
    if (s < t) {
      const float* kb = &sw[t * 257];
      const float* kk = &sk[s * 257];
#pragma unroll 8
      for (int d = 0; d < DH; d++) acc += kb[d] * kk[d];
    }
    sM[e] = acc;
  }
  __syncthreads();
  // unit-lower forward substitution
  if (tid < 256) {
    int d = tid;
    for (int t = 1; t < BT; t++) {
      float aw = 0.f;
      const float* Mr = &sM[t * 64];
      for (int s = 0; s < t; s++) aw += Mr[s] * sw[s * 257 + d];
      sw[t * 257 + d] -= aw;
    }
  } else {
    int d = tid - 256;
    for (int t = 1; t < BT; t++) {
      float au = 0.f;
      const float* Mr = &sM[t * 64];
      for (int s = 0; s < t; s++) au += Mr[s] * su[s * 257 + d];
      su[t * 257 + d] -= au;
    }
  }
  __syncthreads();
  for (int i = tid; i < BT * DH; i += 512) {
    int t = i >> 8, d = i & 255;
    Wt[base + i] = sw[t * 257 + d];
    Ut[base + i] = su[t * 257 + d];
  }
}

// -------------------- attn = tril(q k^T) per (bh, chunk) --------------------
__global__ __launch_bounds__(256) void attn_kernel(
    const float* __restrict__ qt, const float* __restrict__ kt, float* __restrict__ att)
{
  extern __shared__ float sh[];
  float* sq = sh;                // [64][257]
  float* sk = sq + 64 * 257;     // [64][257]
  int blk = blockIdx.x;
  int c = blk % NC, bh = blk / NC;
  size_t base = ((size_t)bh * LL + (size_t)c * BT) * DH;
  int tid = threadIdx.x;
  for (int i = tid; i < BT * DH; i += 256) {
    int t = i >> 8, d = i & 255;
    sq[t * 257 + d] = qt[base + i];
    sk[t * 257 + d] = kt[base + i];
  }
  __syncthreads();
  float* ap = att + (size_t)blk * (BT * BT);
  for (int e = tid; e < BT * BT; e += 256) {
    int t = e >> 6, s = e & 63;
    float acc = 0.f;
    if (s <= t) {
      const float* q = &sq[t * 257];
      const float* k = &sk[s * 257];
#pragma unroll 8
      for (int d = 0; d < DH; d++) acc += q[d] * k[d];
    }
    ap[e] = acc;
  }
}

// -------------------- sequential chunk scan, dv split 8 ways --------------------
__global__ __launch_bounds__(256) void scan_kernel(
    const float* __restrict__ qt, const float* __restrict__ kt,
    const float* __restrict__ wt, const float* __restrict__ ut,
    const float* __restrict__ att, float* __restrict__ og)
{
  extern __shared__ float sh[];
  float* S  = sh;                 // [256][36]
  float* Aq = S + 256 * 36;       // [64][257]  q, then w
  float* Bk = Aq + 64 * 257;      // [64][257]  k
  float* Tt = Bk + 64 * 257;      // [64][64]   attn
  float* Un = Tt + 64 * 64;       // [64][36]   u_new
  int blk = blockIdx.x;
  int vb = blk & 7;
  int bh = blk >> 3;
  int b = bh / HH, h = bh % HH;
  int tid = threadIdx.x;
  int tx = tid & 7;
  int ty = tid >> 3;
  int t0 = ty * 2, t1 = t0 + 1;
  int v0 = tx * 4;

  for (int i = tid; i < 256 * 36; i += 256) S[i] = 0.f;
  __syncthreads();

  for (int c = 0; c < NC; c++) {
    size_t base = ((size_t)bh * LL + (size_t)c * BT) * DH;
    const float* ap = att + ((size_t)bh * NC + c) * (BT * BT);
    for (int i = tid; i < BT * DH; i += 256) {
      int t = i >> 8, d = i & 255;
      Aq[t * 257 + d] = qt[base + i];
      Bk[t * 257 + d] = kt[base + i];
    }
    for (int i = tid; i < BT * BT; i += 256) Tt[i] = ap[i];
    __syncthreads();

    float4 r0 = make_float4(0, 0, 0, 0), r1 = make_float4(0, 0, 0, 0);
    for (int d = 0; d < DH; d++) {
      float4 sv = *(float4*)&S[d * 36 + v0];
      float q0 = Aq[t0 * 257 + d], q1 = Aq[t1 * 257 + d];
      r0.x += q0 * sv.x; r0.y += q0 * sv.y; r0.z += q0 * sv.z; r0.w += q0 * sv.w;
      r1.x += q1 * sv.x; r1.y += q1 * sv.y; r1.z += q1 * sv.z; r1.w += q1 * sv.w;
    }
    __syncthreads();
    for (int i = tid; i < BT * DH; i += 256) {
      int t = i >> 8, d = i & 255;
      Aq[t * 257 + d] = wt[base + i];
    }
    __syncthreads();
    {
      float4 a0 = make_float4(0, 0, 0, 0), a1 = make_float4(0, 0, 0, 0);
      for (int d = 0; d < DH; d++) {
        float4 sv = *(float4*)&S[d * 36 + v0];
        float w0 = Aq[t0 * 257 + d], w1 = Aq[t1 * 257 + d];
        a0.x += w0 * sv.x; a0.y += w0 * sv.y; a0.z += w0 * sv.z; a0.w += w0 * sv.w;
        a1.x += w1 * sv.x; a1.y += w1 * sv.y; a1.z += w1 * sv.z; a1.w += w1 * sv.w;
      }
      float4 u0 = *(const float4*)&ut[base + (size_t)t0 * DH + vb * 32 + v0];
      float4 u1 = *(const float4*)&ut[base + (size_t)t1 * DH + vb * 32 + v0];
      *(float4*)&Un[t0 * 36 + v0] = make_float4(u0.x - a0.x, u0.y - a0.y, u0.z - a0.z, u0.w - a0.w);
      *(float4*)&Un[t1 * 36 + v0] = make_float4(u1.x - a1.x, u1.y - a1.y, u1.z - a1.z, u1.w - a1.w);
    }
    __syncthreads();
    for (int s = 0; s <= t1; s++) {
      float4 u4 = *(float4*)&Un[s * 36 + v0];
      float av1 = Tt[t1 * 64 + s];
      r1.x += av1 * u4.x; r1.y += av1 * u4.y; r1.z += av1 * u4.z; r1.w += av1 * u4.w;
      if (s <= t0) {
        float av0 = Tt[t0 * 64 + s];
        r0.x += av0 * u4.x; r0.y += av0 * u4.y; r0.z += av0 * u4.z; r0.w += av0 * u4.w;
      }
    }
    {
      size_t o0 = (((size_t)b * LL + c * BT + t0) * HH + h) * DH + vb * 32 + v0;
      size_t o1 = (((size_t)b * LL + c * BT + t1) * HH + h) * DH + vb * 32 + v0;
      *(float4*)&og[o0] = r0;
      *(float4*)&og[o1] = r1;
    }
    {
      int d = tid;
      float4 sa[8];
#pragma unroll
      for (int j = 0; j < 8; j++) sa[j] = *(float4*)&S[d * 36 + j * 4];
      for (int t = 0; t < BT; t++) {
        float kv = Bk[t * 257 + d];
#pragma unroll
        for (int j = 0; j < 8; j++) {
          float4 u4 = *(float4*)&Un[t * 36 + j * 4];
          sa[j].x += kv * u4.x; sa[j].y += kv * u4.y;
          sa[j].z += kv * u4.z; sa[j].w += kv * u4.w;
        }
      }
#pragma unroll
      for (int j = 0; j < 8; j++) *(float4*)&S[d * 36 + j * 4] = sa[j];
    }
    __syncthreads();
  }
}

// -------------------- per-head RMSNorm * g_norm --------------------
__global__ __launch_bounds__(256) void rms_kernel(
    const float* __restrict__ og, const float* __restrict__ gn, float* __restrict__ on)
{
  __shared__ float red[256];
  int idx = blockIdx.x;            // (b*LL + l)*HH + h
  int d = threadIdx.x;
  float v = og[(size_t)idx * DH + d];
  red[d] = v * v;
  __syncthreads();
  for (int s = 128; s; s >>= 1) { if (d < s) red[d] += red[d + s]; __syncthreads(); }
  float scale = rsqrtf(red[0] * (1.f / DH) + 1e-5f);
  on[(size_t)idx * DH + d] = v * scale * gn[d];
}

// -------------------- host launch --------------------
#define SOLVE_SMEM ((3*64*257 + 64*64 + 64) * 4)
#define ATTN_SMEM  ((2*64*257) * 4)
#define SCAN_SMEM  ((256*36 + 2*64*257 + 64*64 + 64*36) * 4)

extern "C" void kernel_launch(void* const* d_in, const int* in_sizes, int n_in,
                              void* d_out, int out_size)
{
  const float* hs = (const float*)d_in[0];
  const float* Wq = (const float*)d_in[1];
  const float* Wk = (const float*)d_in[2];
  const float* Wv = (const float*)d_in[3];
  const float* Wb = (const float*)d_in[4];
  const float* cq = (const float*)d_in[5];
  const float* ck = (const float*)d_in[6];
  const float* cv = (const float*)d_in[7];
  const float* gn = (const float*)d_in[8];
  const float* Wo = (const float*)d_in[9];
  float* out = (float*)d_out;

  float *preq, *prek, *prev, *qt, *kt, *vt, *wt, *ut, *beta, *att, *og, *on;
  cudaGetSymbolAddress((void**)&preq, g_preq);
  cudaGetSymbolAddress((void**)&prek, g_prek);
  cudaGetSymbolAddress((void**)&prev, g_prev);
  cudaGetSymbolAddress((void**)&qt, g_qt);
  cudaGetSymbolAddress((void**)&kt, g_kt);
  cudaGetSymbolAddress((void**)&vt, g_vt);
  cudaGetSymbolAddress((void**)&wt, g_wt);
  cudaGetSymbolAddress((void**)&ut, g_ut);
  cudaGetSymbolAddress((void**)&beta, g_beta);
  cudaGetSymbolAddress((void**)&att, g_att);
  cudaGetSymbolAddress((void**)&og, g_og);
  cudaGetSymbolAddress((void**)&on, g_on);

  cudaFuncSetAttribute(gemm3_kernel, cudaFuncAttributeMaxDynamicSharedMemorySize, GEMM_SMEM);
  cudaFuncSetAttribute(solve_kernel, cudaFuncAttributeMaxDynamicSharedMemorySize, SOLVE_SMEM);
  cudaFuncSetAttribute(attn_kernel, cudaFuncAttributeMaxDynamicSharedMemorySize, ATTN_SMEM);
  cudaFuncSetAttribute(scan_kernel, cudaFuncAttributeMaxDynamicSharedMemorySize, SCAN_SMEM);

  dim3 gg(DDIM / 128, (BB * LL) / 128);   // (16, 64)

  gemm3_kernel<<<gg, 256, GEMM_SMEM>>>(hs, Wq, preq, BB * LL, DDIM, DDIM);
  gemm3_kernel<<<gg, 256, GEMM_SMEM>>>(hs, Wk, prek, BB * LL, DDIM, DDIM);
  gemm3_kernel<<<gg, 256, GEMM_SMEM>>>(hs, Wv, prev, BB * LL, DDIM, DDIM);
  beta_kernel<<<BB * LL, 256>>>(hs, Wb, beta);

  conv_kernel<<<BB * LL * HH, 256>>>(preq, cq, qt, 0);
  conv_kernel<<<BB * LL * HH, 256>>>(prek, ck, kt, 1);
  conv_kernel<<<BB * LL * HH, 256>>>(prev, cv, vt, 2);

  solve_kernel<<<BB * HH * NC, 512, SOLVE_SMEM>>>(kt, vt, beta, wt, ut);
  attn_kernel<<<BB * HH * NC, 256, ATTN_SMEM>>>(qt, kt, att);
  scan_kernel<<<BB * HH * 8, 256, SCAN_SMEM>>>(qt, kt, wt, ut, att, og);

  rms_kernel<<<BB * LL * HH, 256>>>(og, gn, on);
  gemm3_kernel<<<gg, 256, GEMM_SMEM>>>(on, Wo, out, BB * LL, DDIM, DDIM);
}

// round 4
// speedup vs baseline: 1.5957x; 1.0249x over previous
#include <cuda_runtime.h>
#include <cuda_bf16.h>
#include <math.h>
#include <stdint.h>

#define BB 2
#define LL 4096
#define DDIM 2048
#define HH 8
#define DH 256
#define BT 64
#define NC 64          // LL / BT
#define BLD (BB*LL*DDIM)
#define DD2 (DDIM*DDIM)

// -------------------- scratch (device globals; no allocation) --------------------
__device__ float g_preq[BLD];
__device__ float g_prek[BLD];
__device__ float g_prev[BLD];
__device__ float g_qt[BLD];
__device__ float g_kt[BLD];
__device__ float g_vt[BLD];
__device__ float g_wt[BLD];
__device__ float g_ut[BLD];
__device__ float g_beta[BB*HH*LL];
__device__ float g_att[(size_t)BB*HH*NC*BT*BT];
__device__ float g_og[BLD];
__device__ float g_on[BLD];
// bf16 split scratch (16B aligned for cp.async)
__device__ __align__(128) __nv_bfloat16 g_ah[BLD];     // activation hi
__device__ __align__(128) __nv_bfloat16 g_al[BLD];     // activation lo
__device__ __align__(128) __nv_bfloat16 g_wh[4*DD2];   // Wq,Wk,Wv,Wo hi
__device__ __align__(128) __nv_bfloat16 g_wl[4*DD2];   // lo

// ==================== split fp32 -> bf16 hi/lo ====================
__global__ __launch_bounds__(256) void split_kernel(
    const float* __restrict__ x, __nv_bfloat16* __restrict__ hi,
    __nv_bfloat16* __restrict__ lo, int n4)
{
  int i = blockIdx.x * blockDim.x + threadIdx.x;
  if (i >= n4) return;
  float4 v = *(const float4*)(x + (size_t)i * 4);
  __nv_bfloat16 h0 = __float2bfloat16(v.x), h1 = __float2bfloat16(v.y);
  __nv_bfloat16 h2 = __float2bfloat16(v.z), h3 = __float2bfloat16(v.w);
  __nv_bfloat162* hp = (__nv_bfloat162*)(hi + (size_t)i * 4);
  hp[0] = __nv_bfloat162{h0, h1};
  hp[1] = __nv_bfloat162{h2, h3};
  __nv_bfloat162* lp = (__nv_bfloat162*)(lo + (size_t)i * 4);
  lp[0] = __nv_bfloat162{__float2bfloat16(v.x - __bfloat162float(h0)),
                         __float2bfloat16(v.y - __bfloat162float(h1))};
  lp[1] = __nv_bfloat162{__float2bfloat16(v.z - __bfloat162float(h2)),
                         __float2bfloat16(v.w - __bfloat162float(h3))};
}

// ==================== bf16x3-split HMMA GEMM with cp.async ====================
// C[M,N] = A[M,K]@B[N,K]^T, ~fp32 precision via 3-term bf16 split.
// 128x128x32 CTA tile, 8 warps (2x4), warp tile 64x32, mma.m16n8k16.

#define GSTRIDE 40                     // padded bf16 row stride (80B)
#define GTILE (128*GSTRIDE)            // elems per tile matrix (5120)
#define ABYTES (GTILE*2)               // 10240 B per array
#define STAGEB (4*ABYTES)              // Ahi,Alo,Bhi,Blo  (40960 B)
#define GEMM_SMEM (2*STAGEB)           // 81920 B

__device__ __forceinline__ void cpa16(uint32_t dst, const void* src) {
  asm volatile("cp.async.ca.shared.global [%0], [%1], 16;" :: "r"(dst), "l"(src));
}
#define CP_COMMIT() asm volatile("cp.async.commit_group;" ::: "memory")
#define CP_WAIT(n)  asm volatile("cp.async.wait_group %0;" :: "n"(n) : "memory")

__device__ __forceinline__ void ldsm4(uint32_t* r, uint32_t addr) {
  asm volatile("ldmatrix.sync.aligned.m8n8.x4.shared.b16 {%0,%1,%2,%3}, [%4];"
    : "=r"(r[0]), "=r"(r[1]), "=r"(r[2]), "=r"(r[3]) : "r"(addr));
}
__device__ __forceinline__ void mma16816(float* d, const uint32_t* a, uint32_t b0, uint32_t b1) {
  asm volatile("mma.sync.aligned.m16n8k16.row.col.f32.bf16.bf16.f32 "
    "{%0,%1,%2,%3}, {%4,%5,%6,%7}, {%8,%9}, {%0,%1,%2,%3};"
    : "+f"(d[0]), "+f"(d[1]), "+f"(d[2]), "+f"(d[3])
    : "r"(a[0]), "r"(a[1]), "r"(a[2]), "r"(a[3]), "r"(b0), "r"(b1));
}

__device__ __forceinline__ void load_stage_async(
    const __nv_bfloat16* __restrict__ Ah, const __nv_bfloat16* __restrict__ Al,
    const __nv_bfloat16* __restrict__ Bh, const __nv_bfloat16* __restrict__ Bl,
    int bm, int bn, int K, int k0, uint32_t sb, int tid)
{
  const __nv_bfloat16* srcs[4] = {Ah, Al, Bh, Bl};
  const int rb[4] = {bm, bm, bn, bn};
#pragma unroll
  for (int a = 0; a < 4; a++) {
#pragma unroll
    for (int i = 0; i < 2; i++) {
      int idx = tid + i * 256;          // 0..511
      int r = idx >> 2, ch = idx & 3;   // row, 16B chunk
      const __nv_bfloat16* g = srcs[a] + (size_t)(rb[a] + r) * K + k0 + ch * 8;
      uint32_t dst = sb + a * ABYTES + (uint32_t)(r * 80 + ch * 16);
      cpa16(dst, g);
    }
  }
}

__global__ __launch_bounds__(256) void gemm3_kernel(
    const __nv_bfloat16* __restrict__ Ah, const __nv_bfloat16* __restrict__ Al,
    const __nv_bfloat16* __restrict__ Bh, const __nv_bfloat16* __restrict__ Bl,
    float* __restrict__ C, int M, int N, int K)
{
  extern __shared__ char sm[];
  const int tid = threadIdx.x, lane = tid & 31, wid = tid >> 5;
  const int warp_m = wid >> 2, warp_n = wid & 3;
  const int bm = blockIdx.y * 128, bn = blockIdx.x * 128;
  const uint32_t sbase = (uint32_t)__cvta_generic_to_shared(sm);

  float acc[4][4][4];
#pragma unroll
  for (int i = 0; i < 4; i++)
#pragma unroll
    for (int j = 0; j < 4; j++)
#pragma unroll
      for (int e = 0; e < 4; e++) acc[i][j][e] = 0.f;

  const int NT = K / 32;
  // prologue: stage 0
  load_stage_async(Ah, Al, Bh, Bl, bm, bn, K, 0, sbase, tid);
  CP_COMMIT();

  const int arow  = warp_m * 64 + (lane & 15);
  const int acol0 = (lane >> 4) * 8;
  const int brow  = warp_n * 32 + (lane >> 4) * 8 + (lane & 7);
  const int bcol0 = ((lane >> 3) & 1) * 8;

  for (int kt = 0; kt < NT; kt++) {
    if (kt + 1 < NT) {
      load_stage_async(Ah, Al, Bh, Bl, bm, bn, K, (kt + 1) * 32,
                       sbase + ((kt + 1) & 1) * STAGEB, tid);
      CP_COMMIT();
      CP_WAIT(1);
    } else {
      CP_WAIT(0);
    }
    __syncthreads();

    const uint32_t stb = sbase + (kt & 1) * STAGEB;
    const uint32_t aoff_hi = stb;
    const uint32_t aoff_lo = stb + ABYTES;
    const uint32_t boff_hi = stb + 2 * ABYTES;
    const uint32_t boff_lo = stb + 3 * ABYTES;
#pragma unroll
    for (int kk = 0; kk < 32; kk += 16) {
      uint32_t ahi[4][4], alo[4][4], bhi[2][4], blo[2][4];
#pragma unroll
      for (int mt = 0; mt < 4; mt++) {
        uint32_t ab = (uint32_t)(((arow + mt * 16) * GSTRIDE + kk + acol0) * 2);
        ldsm4(ahi[mt], aoff_hi + ab);
        ldsm4(alo[mt], aoff_lo + ab);
      }
#pragma unroll
      for (int p = 0; p < 2; p++) {
        uint32_t bb = (uint32_t)(((brow + p * 16) * GSTRIDE + kk + bcol0) * 2);
        ldsm4(bhi[p], boff_hi + bb);
        ldsm4(blo[p], boff_lo + bb);
      }
#pragma unroll
      for (int mt = 0; mt < 4; mt++)
#pragma unroll
        for (int nt = 0; nt < 4; nt++) {
          const uint32_t* bh = bhi[nt >> 1];
          const uint32_t* bl = blo[nt >> 1];
          int bi = (nt & 1) * 2;
          mma16816(acc[mt][nt], ahi[mt], bh[bi], bh[bi + 1]);
          mma16816(acc[mt][nt], ahi[mt], bl[bi], bl[bi + 1]);
          mma16816(acc[mt][nt], alo[mt], bh[bi], bh[bi + 1]);
        }
    }
    __syncthreads();
  }
  // epilogue
  const int row0 = bm + warp_m * 64 + (lane >> 2);
  const int col0 = bn + warp_n * 32 + (lane & 3) * 2;
#pragma unroll
  for (int mt = 0; mt < 4; mt++)
#pragma unroll
    for (int nt = 0; nt < 4; nt++) {
      int r = row0 + mt * 16;
      int c = col0 + nt * 8;
      *(float2*)(C + (size_t)r * N + c)       = make_float2(acc[mt][nt][0], acc[mt][nt][1]);
      *(float2*)(C + (size_t)(r + 8) * N + c) = make_float2(acc[mt][nt][2], acc[mt][nt][3]);
    }
}

// -------------------- beta = sigmoid(hs @ Wb^T), [B,H,L] --------------------
__global__ __launch_bounds__(256) void beta_kernel(
    const float* __restrict__ hs, const float* __restrict__ Wb, float* __restrict__ beta)
{
  int bl = blockIdx.x;
  int b = bl / LL, l = bl % LL;
  int w = threadIdx.x >> 5, lane = threadIdx.x & 31;
  const float* x = hs + (size_t)bl * DDIM;
  const float* wb = Wb + (size_t)w * DDIM;
  float s = 0.f;
  for (int d = lane; d < DDIM; d += 32) s += x[d] * wb[d];
#pragma unroll
  for (int o = 16; o; o >>= 1) s += __shfl_xor_sync(0xffffffffu, s, o);
  if (lane == 0)
    beta[((size_t)b * HH + w) * LL + l] = 1.f / (1.f + expf(-s));
}

// -------------------- conv + SiLU (+l2norm) --------------------
__global__ __launch_bounds__(256) void conv_kernel(
    const float* __restrict__ pre, const float* __restrict__ cw,
    float* __restrict__ out, int mode)
{
  __shared__ float red[256];
  int idx = blockIdx.x;
  int h = idx % HH;
  int l = (idx / HH) % LL;
  int b = idx / (HH * LL);
  int dd = threadIdx.x;
  int c = h * DH + dd;
  float w0 = cw[c * 4 + 0], w1 = cw[c * 4 + 1], w2 = cw[c * 4 + 2], w3 = cw[c * 4 + 3];
  const float* base = pre + (size_t)b * LL * DDIM + c;
  float y = base[(size_t)l * DDIM] * w3;
  if (l >= 1) y += base[(size_t)(l - 1) * DDIM] * w2;
  if (l >= 2) y += base[(size_t)(l - 2) * DDIM] * w1;
  if (l >= 3) y += base[(size_t)(l - 3) * DDIM] * w0;
  y = y / (1.f + expf(-y));
  float scale = 1.f;
  if (mode < 2) {
    red[dd] = y * y;
    __syncthreads();
    for (int s = 128; s; s >>= 1) { if (dd < s) red[dd] += red[dd + s]; __syncthreads(); }
    scale = rsqrtf(red[0] + 1e-6f);
    if (mode == 0) scale *= 0.0625f;
  }
  out[(((size_t)b * HH + h) * LL + l) * DH + dd] = y * scale;
}

// -------------------- per-chunk triangular solve --------------------
__global__ __launch_bounds__(512) void solve_kernel(
    const float* __restrict__ kt, const float* __restrict__ vt,
    const float* __restrict__ beta, float* __restrict__ Wt, float* __restrict__ Ut)
{
  extern __shared__ float sh[];
  float* sk = sh;
  float* sw = sk + 64 * 257;
  float* su = sw + 64 * 257;
  float* sM = su + 64 * 257;
  float* sb = sM + 64 * 64;
  int blk = blockIdx.x;
  int c = blk % NC, bh = blk / NC;
  size_t base = ((size_t)bh * LL + (size_t)c * BT) * DH;
  int tid = threadIdx.x;

  if (tid < 64) sb[tid] = beta[(size_t)bh * LL + c * BT + tid];
  __syncthreads();
  for (int i = tid; i < BT * DH; i += 512) {
    int t = i >> 8, d = i & 255;
    float kv = kt[base + i];
    float bt = sb[t];
    sk[t * 257 + d] = kv;
    sw[t * 257 + d] = kv * bt;
    su[t * 257 + d] = vt[base + i] * bt;
  }
  __syncthreads();
  for (int e = tid; e < BT * BT; e += 512) {
    int t = e >> 6, s = e & 63;
    float acc = 0.f;
    if (s < t) {
      const float* kb = &sw[t * 257];
      const float* kk = &sk[s * 257];
#pragma unroll 8
      for (int d = 0; d < DH; d++) acc += kb[d] * kk[d];
    }
    sM[e] = acc;
  }
  __syncthreads();
  if (tid < 256) {
    int d = tid;
    for (int t = 1; t < BT; t++) {
      float aw = 0.f;
      const float* Mr = &sM[t * 64];
      for (int s = 0; s < t; s++) aw += Mr[s] * sw[s * 257 + d];
      sw[t * 257 + d] -= aw;
    }
  } else {
    int d = tid - 256;
    for (int t = 1; t < BT; t++) {
      float au = 0.f;
      const float* Mr = &sM[t * 64];
      for (int s = 0; s < t; s++) au += Mr[s] * su[s * 257 + d];
      su[t * 257 + d] -= au;
    }
  }
  __syncthreads();
  for (int i = tid; i < BT * DH; i += 512) {
    int t = i >> 8, d = i & 255;
    Wt[base + i] = sw[t * 257 + d];
    Ut[base + i] = su[t * 257 + d];
  }
}

// -------------------- attn = tril(q k^T) --------------------
__global__ __launch_bounds__(256) void attn_kernel(
    const float* __restrict__ qt, const float* __restrict__ kt, float* __restrict__ att)
{
  extern __shared__ float sh[];
  float* sq = sh;
  float* sk = sq + 64 * 257;
  int blk = blockIdx.x;
  int c = blk % NC, bh = blk / NC;
  size_t base = ((size_t)bh * LL + (size_t)c * BT) * DH;
  int tid = threadIdx.x;
  for (int i = tid; i < BT * DH; i += 256) {
    int t = i >> 8, d = i & 255;
    sq[t * 257 + d] = qt[base + i];
    sk[t * 257 + d] = kt[base + i];
  }
  __syncthreads();
  float* ap = att + (size_t)blk * (BT * BT);
  for (int e = tid; e < BT * BT; e += 256) {
    int t = e >> 6, s = e & 63;
    float acc = 0.f;
    if (s <= t) {
      const float* q = &sq[t * 257];
      const float* k = &sk[s * 257];
#pragma unroll 8
      for (int d = 0; d < DH; d++) acc += q[d] * k[d];
    }
    ap[e] = acc;
  }
}

// -------------------- sequential chunk scan, dv split 8 ways --------------------
__global__ __launch_bounds__(256) void scan_kernel(
    const float* __restrict__ qt, const float* __restrict__ kt,
    const float* __restrict__ wt, const float* __restrict__ ut,
    const float* __restrict__ att, float* __restrict__ og)
{
  extern __shared__ float sh[];
  float* S  = sh;
  float* Aq = S + 256 * 36;
  float* Bk = Aq + 64 * 257;
  float* Tt = Bk + 64 * 257;
  float* Un = Tt + 64 * 64;
  int blk = blockIdx.x;
  int vb = blk & 7;
  int bh = blk >> 3;
  int b = bh / HH, h = bh % HH;
  int tid = threadIdx.x;
  int tx = tid & 7;
  int ty = tid >> 3;
  int t0 = ty * 2, t1 = t0 + 1;
  int v0 = tx * 4;

  for (int i = tid; i < 256 * 36; i += 256) S[i] = 0.f;
  __syncthreads();

  for (int c = 0; c < NC; c++) {
    size_t base = ((size_t)bh * LL + (size_t)c * BT) * DH;
    const float* ap = att + ((size_t)bh * NC + c) * (BT * BT);
    for (int i = tid; i < BT * DH; i += 256) {
      int t = i >> 8, d = i & 255;
      Aq[t * 257 + d] = qt[base + i];
      Bk[t * 257 + d] = kt[base + i];
    }
    for (int i = tid; i < BT * BT; i += 256) Tt[i] = ap[i];
    __syncthreads();

    float4 r0 = make_float4(0, 0, 0, 0), r1 = make_float4(0, 0, 0, 0);
    for (int d = 0; d < DH; d++) {
      float4 sv = *(float4*)&S[d * 36 + v0];
      float q0 = Aq[t0 * 257 + d], q1 = Aq[t1 * 257 + d];
      r0.x += q0 * sv.x; r0.y += q0 * sv.y; r0.z += q0 * sv.z; r0.w += q0 * sv.w;
      r1.x += q1 * sv.x; r1.y += q1 * sv.y; r1.z += q1 * sv.z; r1.w += q1 * sv.w;
    }
    __syncthreads();
    for (int i = tid; i < BT * DH; i += 256) {
      int t = i >> 8, d = i & 255;
      Aq[t * 257 + d] = wt[base + i];
    }
    __syncthreads();
    {
      float4 a0 = make_float4(0, 0, 0, 0), a1 = make_float4(0, 0, 0, 0);
      for (int d = 0; d < DH; d++) {
        float4 sv = *(float4*)&S[d * 36 + v0];
        float w0 = Aq[t0 * 257 + d], w1 = Aq[t1 * 257 + d];
        a0.x += w0 * sv.x; a0.y += w0 * sv.y; a0.z += w0 * sv.z; a0.w += w0 * sv.w;
        a1.x += w1 * sv.x; a1.y += w1 * sv.y; a1.z += w1 * sv.z; a1.w += w1 * sv.w;
      }
      float4 u0 = *(const float4*)&ut[base + (size_t)t0 * DH + vb * 32 + v0];
      float4 u1 = *(const float4*)&ut[base + (size_t)t1 * DH + vb * 32 + v0];
      *(float4*)&Un[t0 * 36 + v0] = make_float4(u0.x - a0.x, u0.y - a0.y, u0.z - a0.z, u0.w - a0.w);
      *(float4*)&Un[t1 * 36 + v0] = make_float4(u1.x - a1.x, u1.y - a1.y, u1.z - a1.z, u1.w - a1.w);
    }
    __syncthreads();
    for (int s = 0; s <= t1; s++) {
      float4 u4 = *(float4*)&Un[s * 36 + v0];
      float av1 = Tt[t1 * 64 + s];
      r1.x += av1 * u4.x; r1.y += av1 * u4.y; r1.z += av1 * u4.z; r1.w += av1 * u4.w;
      if (s <= t0) {
        float av0 = Tt[t0 * 64 + s];
        r0.x += av0 * u4.x; r0.y += av0 * u4.y; r0.z += av0 * u4.z; r0.w += av0 * u4.w;
      }
    }
    {
      size_t o0 = (((size_t)b * LL + c * BT + t0) * HH + h) * DH + vb * 32 + v0;
      size_t o1 = (((size_t)b * LL + c * BT + t1) * HH + h) * DH + vb * 32 + v0;
      *(float4*)&og[o0] = r0;
      *(float4*)&og[o1] = r1;
    }
    {
      int d = tid;
      float4 sa[8];
#pragma unroll
      for (int j = 0; j < 8; j++) sa[j] = *(float4*)&S[d * 36 + j * 4];
      for (int t = 0; t < BT; t++) {
        float kv = Bk[t * 257 + d];
#pragma unroll
        for (int j = 0; j < 8; j++) {
          float4 u4 = *(float4*)&Un[t * 36 + j * 4];
          sa[j].x += kv * u4.x; sa[j].y += kv * u4.y;
          sa[j].z += kv * u4.z; sa[j].w += kv * u4.w;
        }
      }
#pragma unroll
      for (int j = 0; j < 8; j++) *(float4*)&S[d * 36 + j * 4] = sa[j];
    }
    __syncthreads();
  }
}

// -------------------- per-head RMSNorm * g_norm --------------------
__global__ __launch_bounds__(256) void rms_kernel(
    const float* __restrict__ og, const float* __restrict__ gn, float* __restrict__ on)
{
  __shared__ float red[256];
  int idx = blockIdx.x;
  int d = threadIdx.x;
  float v = og[(size_t)idx * DH + d];
  red[d] = v * v;
  __syncthreads();
  for (int s = 128; s; s >>= 1) { if (d < s) red[d] += red[d + s]; __syncthreads(); }
  float scale = rsqrtf(red[0] * (1.f / DH) + 1e-5f);
  on[(size_t)idx * DH + d] = v * scale * gn[d];
}

// -------------------- host launch --------------------
#define SOLVE_SMEM ((3*64*257 + 64*64 + 64) * 4)
#define ATTN_SMEM  ((2*64*257) * 4)
#define SCAN_SMEM  ((256*36 + 2*64*257 + 64*64 + 64*36) * 4)

extern "C" void kernel_launch(void* const* d_in, const int* in_sizes, int n_in,
                              void* d_out, int out_size)
{
  const float* hs = (const float*)d_in[0];
  const float* Wq = (const float*)d_in[1];
  const float* Wk = (const float*)d_in[2];
  const float* Wv = (const float*)d_in[3];
  const float* Wb = (const float*)d_in[4];
  const float* cq = (const float*)d_in[5];
  const float* ck = (const float*)d_in[6];
  const float* cv = (const float*)d_in[7];
  const float* gn = (const float*)d_in[8];
  const float* Wo = (const float*)d_in[9];
  float* out = (float*)d_out;

  float *preq, *prek, *prev, *qt, *kt, *vt, *wt, *ut, *beta, *att, *og, *on;
  __nv_bfloat16 *ah, *al, *wh, *wl;
  cudaGetSymbolAddress((void**)&preq, g_preq);
  cudaGetSymbolAddress((void**)&prek, g_prek);
  cudaGetSymbolAddress((void**)&prev, g_prev);
  cudaGetSymbolAddress((void**)&qt, g_qt);
  cudaGetSymbolAddress((void**)&kt, g_kt);
  cudaGetSymbolAddress((void**)&vt, g_vt);
  cudaGetSymbolAddress((void**)&wt, g_wt);
  cudaGetSymbolAddress((void**)&ut, g_ut);
  cudaGetSymbolAddress((void**)&beta, g_beta);
  cudaGetSymbolAddress((void**)&att, g_att);
  cudaGetSymbolAddress((void**)&og, g_og);
  cudaGetSymbolAddress((void**)&on, g_on);
  cudaGetSymbolAddress((void**)&ah, g_ah);
  cudaGetSymbolAddress((void**)&al, g_al);
  cudaGetSymbolAddress((void**)&wh, g_wh);
  cudaGetSymbolAddress((void**)&wl, g_wl);

  cudaFuncSetAttribute(gemm3_kernel, cudaFuncAttributeMaxDynamicSharedMemorySize, GEMM_SMEM);
  cudaFuncSetAttribute(solve_kernel, cudaFuncAttributeMaxDynamicSharedMemorySize, SOLVE_SMEM);
  cudaFuncSetAttribute(attn_kernel, cudaFuncAttributeMaxDynamicSharedMemorySize, ATTN_SMEM);
  cudaFuncSetAttribute(scan_kernel, cudaFuncAttributeMaxDynamicSharedMemorySize, SCAN_SMEM);

  dim3 gg(DDIM / 128, (BB * LL) / 128);   // (16, 64)
  const int actN4 = BLD / 4, wN4 = DD2 / 4;

  // pre-splits
  split_kernel<<<(actN4 + 255) / 256, 256>>>(hs, ah, al, actN4);
  split_kernel<<<(wN4 + 255) / 256, 256>>>(Wq, wh + 0 * (size_t)DD2, wl + 0 * (size_t)DD2, wN4);
  split_kernel<<<(wN4 + 255) / 256, 256>>>(Wk, wh + 1 * (size_t)DD2, wl + 1 * (size_t)DD2, wN4);
  split_kernel<<<(wN4 + 255) / 256, 256>>>(Wv, wh + 2 * (size_t)DD2, wl + 2 * (size_t)DD2, wN4);
  split_kernel<<<(wN4 + 255) / 256, 256>>>(Wo, wh + 3 * (size_t)DD2, wl + 3 * (size_t)DD2, wN4);

  gemm3_kernel<<<gg, 256, GEMM_SMEM>>>(ah, al, wh + 0 * (size_t)DD2, wl + 0 * (size_t)DD2, preq, BB * LL, DDIM, DDIM);
  gemm3_kernel<<<gg, 256, GEMM_SMEM>>>(ah, al, wh + 1 * (size_t)DD2, wl + 1 * (size_t)DD2, prek, BB * LL, DDIM, DDIM);
  gemm3_kernel<<<gg, 256, GEMM_SMEM>>>(ah, al, wh + 2 * (size_t)DD2, wl + 2 * (size_t)DD2, prev, BB * LL, DDIM, DDIM);
  beta_kernel<<<BB * LL, 256>>>(hs, Wb, beta);

  conv_kernel<<<BB * LL * HH, 256>>>(preq, cq, qt, 0);
  conv_kernel<<<BB * LL * HH, 256>>>(prek, ck, kt, 1);
  conv_kernel<<<BB * LL * HH, 256>>>(prev, cv, vt, 2);

  solve_kernel<<<BB * HH * NC, 512, SOLVE_SMEM>>>(kt, vt, beta, wt, ut);
  attn_kernel<<<BB * HH * NC, 256, ATTN_SMEM>>>(qt, kt, att);
  scan_kernel<<<BB * HH * 8, 256, SCAN_SMEM>>>(qt, kt, wt, ut, att, og);

  rms_kernel<<<BB * LL * HH, 256>>>(og, gn, on);
  split_kernel<<<(actN4 + 255) / 256, 256>>>(on, ah, al, actN4);
  gemm3_kernel<<<gg, 256, GEMM_SMEM>>>(ah, al, wh + 3 * (size_t)DD2, wl + 3 * (size_t)DD2, out, BB * LL, DDIM, DDIM);
}

// round 5
// speedup vs baseline: 2.0477x; 1.2833x over previous
#include <cuda_runtime.h>
#include <cuda_fp16.h>
#include <math.h>
#include <stdint.h>

#define BB 2
#define LL 4096
#define DDIM 2048
#define HH 8
#define DH 256
#define BT 64
#define NC 64          // LL / BT
#define BLD (BB*LL*DDIM)
#define DD2 (DDIM*DDIM)

// -------------------- scratch (device globals; no allocation) --------------------
__device__ float g_preq[BLD];
__device__ float g_prek[BLD];
__device__ float g_prev[BLD];
__device__ float g_qt[BLD];
__device__ float g_kt[BLD];
__device__ float g_vt[BLD];
__device__ float g_wt[BLD];
__device__ float g_ut[BLD];
__device__ float g_beta[BB*HH*LL];
__device__ float g_att[(size_t)BB*HH*NC*BT*BT];
__device__ float g_og[BLD];
__device__ float g_on[BLD];
// fp16 scratch (16B aligned for cp.async)
__device__ __align__(128) __half g_ah[BLD];     // activation fp16
__device__ __align__(128) __half g_wh[4*DD2];   // Wq,Wk,Wv,Wo fp16

// ==================== convert fp32 -> fp16 ====================
__global__ __launch_bounds__(256) void cvt_kernel(
    const float* __restrict__ x, __half* __restrict__ h, int n4)
{
  int i = blockIdx.x * blockDim.x + threadIdx.x;
  if (i >= n4) return;
  float4 v = *(const float4*)(x + (size_t)i * 4);
  __half2* hp = (__half2*)(h + (size_t)i * 4);
  hp[0] = __floats2half2_rn(v.x, v.y);
  hp[1] = __floats2half2_rn(v.z, v.w);
}

// ==================== fp16 HMMA GEMM with cp.async ====================
// C[M,N] = A[M,K]@B[N,K]^T, fp32 accumulate.
// 128x128x32 CTA tile, 8 warps (2x4), warp tile 64x32, mma.m16n8k16.

#define GSTRIDE 40                     // padded fp16 row stride (80B)
#define GTILE (128*GSTRIDE)            // elems per tile matrix (5120)
#define ABYTES (GTILE*2)               // 10240 B per array
#define STAGEB (2*ABYTES)              // A,B  (20480 B)
#define GEMM_SMEM (2*STAGEB)           // 40960 B (2 stages)

__device__ __forceinline__ void cpa16(uint32_t dst, const void* src) {
  asm volatile("cp.async.ca.shared.global [%0], [%1], 16;" :: "r"(dst), "l"(src));
}
#define CP_COMMIT() asm volatile("cp.async.commit_group;" ::: "memory")
#define CP_WAIT(n)  asm volatile("cp.async.wait_group %0;" :: "n"(n) : "memory")

__device__ __forceinline__ void ldsm4(uint32_t* r, uint32_t addr) {
  asm volatile("ldmatrix.sync.aligned.m8n8.x4.shared.b16 {%0,%1,%2,%3}, [%4];"
    : "=r"(r[0]), "=r"(r[1]), "=r"(r[2]), "=r"(r[3]) : "r"(addr));
}
__device__ __forceinline__ void mma16816(float* d, const uint32_t* a, uint32_t b0, uint32_t b1) {
  asm volatile("mma.sync.aligned.m16n8k16.row.col.f32.f16.f16.f32 "
    "{%0,%1,%2,%3}, {%4,%5,%6,%7}, {%8,%9}, {%0,%1,%2,%3};"
    : "+f"(d[0]), "+f"(d[1]), "+f"(d[2]), "+f"(d[3])
    : "r"(a[0]), "r"(a[1]), "r"(a[2]), "r"(a[3]), "r"(b0), "r"(b1));
}

__device__ __forceinline__ void load_stage_async(
    const __half* __restrict__ A, const __half* __restrict__ B,
    int bm, int bn, int K, int k0, uint32_t sb, int tid)
{
  const __half* srcs[2] = {A, B};
  const int rb[2] = {bm, bn};
#pragma unroll
  for (int a = 0; a < 2; a++) {
#pragma unroll
    for (int i = 0; i < 2; i++) {
      int idx = tid + i * 256;          // 0..511
      int r = idx >> 2, ch = idx & 3;   // row, 16B chunk
      const __half* g = srcs[a] + (size_t)(rb[a] + r) * K + k0 + ch * 8;
      uint32_t dst = sb + a * ABYTES + (uint32_t)(r * 80 + ch * 16);
      cpa16(dst, g);
    }
  }
}

__global__ __launch_bounds__(256) void gemm_h_kernel(
    const __half* __restrict__ A, const __half* __restrict__ B,
    float* __restrict__ C, int M, int N, int K)
{
  extern __shared__ char sm[];
  const int tid = threadIdx.x, lane = tid & 31, wid = tid >> 5;
  const int warp_m = wid >> 2, warp_n = wid & 3;
  const int bm = blockIdx.y * 128, bn = blockIdx.x * 128;
  const uint32_t sbase = (uint32_t)__cvta_generic_to_shared(sm);

  float acc[4][4][4];
#pragma unroll
  for (int i = 0; i < 4; i++)
#pragma unroll
    for (int j = 0; j < 4; j++)
#pragma unroll
      for (int e = 0; e < 4; e++) acc[i][j][e] = 0.f;

  const int NT = K / 32;
  load_stage_async(A, B, bm, bn, K, 0, sbase, tid);
  CP_COMMIT();

  const int arow  = warp_m * 64 + (lane & 15);
  const int acol0 = (lane >> 4) * 8;
  const int brow  = warp_n * 32 + (lane >> 4) * 8 + (lane & 7);
  const int bcol0 = ((lane >> 3) & 1) * 8;

  for (int kt = 0; kt < NT; kt++) {
    if (kt + 1 < NT) {
      load_stage_async(A, B, bm, bn, K, (kt + 1) * 32,
                       sbase + ((kt + 1) & 1) * STAGEB, tid);
      CP_COMMIT();
      CP_WAIT(1);
    } else {
      CP_WAIT(0);
    }
    __syncthreads();

    const uint32_t stb = sbase + (kt & 1) * STAGEB;
    const uint32_t aoff = stb;
    const uint32_t boff = stb + ABYTES;
#pragma unroll
    for (int kk = 0; kk < 32; kk += 16) {
      uint32_t af[4][4], bf[2][4];
#pragma unroll
      for (int mt = 0; mt < 4; mt++) {
        uint32_t ab = (uint32_t)(((arow + mt * 16) * GSTRIDE + kk + acol0) * 2);
        ldsm4(af[mt], aoff + ab);
      }
#pragma unroll
      for (int p = 0; p < 2; p++) {
        uint32_t bb = (uint32_t)(((brow + p * 16) * GSTRIDE + kk + bcol0) * 2);
        ldsm4(bf[p], boff + bb);
      }
#pragma unroll
      for (int mt = 0; mt < 4; mt++)
#pragma unroll
        for (int nt = 0; nt < 4; nt++) {
          const uint32_t* bp = bf[nt >> 1];
          int bi = (nt & 1) * 2;
          mma16816(acc[mt][nt], af[mt], bp[bi], bp[bi + 1]);
        }
    }
    __syncthreads();
  }
  // epilogue
  const int row0 = bm + warp_m * 64 + (lane >> 2);
  const int col0 = bn + warp_n * 32 + (lane & 3) * 2;
#pragma unroll
  for (int mt = 0; mt < 4; mt++)
#pragma unroll
    for (int nt = 0; nt < 4; nt++) {
      int r = row0 + mt * 16;
      int c = col0 + nt * 8;
      *(float2*)(C + (size_t)r * N + c)       = make_float2(acc[mt][nt][0], acc[mt][nt][1]);
      *(float2*)(C + (size_t)(r + 8) * N + c) = make_float2(acc[mt][nt][2], acc[mt][nt][3]);
    }
}

// -------------------- beta = sigmoid(hs @ Wb^T), [B,H,L] --------------------
__global__ __launch_bounds__(256) void beta_kernel(
    const float* __restrict__ hs, const float* __restrict__ Wb, float* __restrict__ beta)
{
  int bl = blockIdx.x;
  int b = bl / LL, l = bl % LL;
  int w = threadIdx.x >> 5, lane = threadIdx.x & 31;
  const float* x = hs + (size_t)bl * DDIM;
  const float* wb = Wb + (size_t)w * DDIM;
  float s = 0.f;
  for (int d = lane; d < DDIM; d += 32) s += x[d] * wb[d];
#pragma unroll
  for (int o = 16; o; o >>= 1) s += __shfl_xor_sync(0xffffffffu, s, o);
  if (lane == 0)
    beta[((size_t)b * HH + w) * LL + l] = 1.f / (1.f + expf(-s));
}

// -------------------- conv + SiLU (+l2norm) --------------------
__global__ __launch_bounds__(256) void conv_kernel(
    const float* __restrict__ pre, const float* __restrict__ cw,
    float* __restrict__ out, int mode)
{
  __shared__ float red[256];
  int idx = blockIdx.x;
  int h = idx % HH;
  int l = (idx / HH) % LL;
  int b = idx / (HH * LL);
  int dd = threadIdx.x;
  int c = h * DH + dd;
  float w0 = cw[c * 4 + 0], w1 = cw[c * 4 + 1], w2 = cw[c * 4 + 2], w3 = cw[c * 4 + 3];
  const float* base = pre + (size_t)b * LL * DDIM + c;
  float y = base[(size_t)l * DDIM] * w3;
  if (l >= 1) y += base[(size_t)(l - 1) * DDIM] * w2;
  if (l >= 2) y += base[(size_t)(l - 2) * DDIM] * w1;
  if (l >= 3) y += base[(size_t)(l - 3) * DDIM] * w0;
  y = y / (1.f + expf(-y));
  float scale = 1.f;
  if (mode < 2) {
    red[dd] = y * y;
    __syncthreads();
    for (int s = 128; s; s >>= 1) { if (dd < s) red[dd] += red[dd + s]; __syncthreads(); }
    scale = rsqrtf(red[0] + 1e-6f);
    if (mode == 0) scale *= 0.0625f;
  }
  out[(((size_t)b * HH + h) * LL + l) * DH + dd] = y * scale;
}

// -------------------- per-chunk triangular solve --------------------
__global__ __launch_bounds__(512) void solve_kernel(
    const float* __restrict__ kt, const float* __restrict__ vt,
    const float* __restrict__ beta, float* __restrict__ Wt, float* __restrict__ Ut)
{
  extern __shared__ float sh[];
  float* sk = sh;
  float* sw = sk + 64 * 257;
  float* su = sw + 64 * 257;
  float* sM = su + 64 * 257;
  float* sb = sM + 64 * 64;
  int blk = blockIdx.x;
  int c = blk % NC, bh = blk / NC;
  size_t base = ((size_t)bh * LL + (size_t)c * BT) * DH;
  int tid = threadIdx.x;

  if (tid < 64) sb[tid] = beta[(size_t)bh * LL + c * BT + tid];
  __syncthreads();
  for (int i = tid; i < BT * DH; i += 512) {
    int t = i >> 8, d = i & 255;
    float kv = kt[base + i];
    float bt = sb[t];
    sk[t * 257 + d] = kv;
    sw[t * 257 + d] = kv * bt;
    su[t * 257 + d] = vt[base + i] * bt;
  }
  __syncthreads();
  for (int e = tid; e < BT * BT; e += 512) {
    int t = e >> 6, s = e & 63;
    float acc = 0.f;
    if (s < t) {
      const float* kb = &sw[t * 257];
      const float* kk = &sk[s * 257];
#pragma unroll 8
      for (int d = 0; d < DH; d++) acc += kb[d] * kk[d];
    }
    sM[e] = acc;
  }
  __syncthreads();
  if (tid < 256) {
    int d = tid;
    for (int t = 1; t < BT; t++) {
      float aw = 0.f;
      const float* Mr = &sM[t * 64];
      for (int s = 0; s < t; s++) aw += Mr[s] * sw[s * 257 + d];
      sw[t * 257 + d] -= aw;
    }
  } else {
    int d = tid - 256;
    for (int t = 1; t < BT; t++) {
      float au = 0.f;
      const float* Mr = &sM[t * 64];
      for (int s = 0; s < t; s++) au += Mr[s] * su[s * 257 + d];
      su[t * 257 + d] -= au;
    }
  }
  __syncthreads();
  for (int i = tid; i < BT * DH; i += 512) {
    int t = i >> 8, d = i & 255;
    Wt[base + i] = sw[t * 257 + d];
    Ut[base + i] = su[t * 257 + d];
  }
}

// -------------------- attn = tril(q k^T) --------------------
__global__ __launch_bounds__(256) void attn_kernel(
    const float* __restrict__ qt, const float* __restrict__ kt, float* __restrict__ att)
{
  extern __shared__ float sh[];
  float* sq = sh;
  float* sk = sq + 64 * 257;
  int blk = blockIdx.x;
  int c = blk % NC, bh = blk / NC;
  size_t base = ((size_t)bh * LL + (size_t)c * BT) * DH;
  int tid = threadIdx.x;
  for (int i = tid; i < BT * DH; i += 256) {
    int t = i >> 8, d = i & 255;
    sq[t * 257 + d] = qt[base + i];
    sk[t * 257 + d] = kt[base + i];
  }
  __syncthreads();
  float* ap = att + (size_t)blk * (BT * BT);
  for (int e = tid; e < BT * BT; e += 256) {
    int t = e >> 6, s = e & 63;
    float acc = 0.f;
    if (s <= t) {
      const float* q = &sq[t * 257];
      const float* k = &sk[s * 257];
#pragma unroll 8
      for (int d = 0; d < DH; d++) acc += q[d] * k[d];
    }
    ap[e] = acc;
  }
}

// -------------------- sequential chunk scan, dv split 8 ways --------------------
__global__ __launch_bounds__(256) void scan_kernel(
    const float* __restrict__ qt, const float* __restrict__ kt,
    const float* __restrict__ wt, const float* __restrict__ ut,
    const float* __restrict__ att, float* __restrict__ og)
{
  extern __shared__ float sh[];
  float* S  = sh;
  float* Aq = S + 256 * 36;
  float* Bk = Aq + 64 * 257;
  float* Tt = Bk + 64 * 257;
  float* Un = Tt + 64 * 64;
  int blk = blockIdx.x;
  int vb = blk & 7;
  int bh = blk >> 3;
  int b = bh / HH, h = bh % HH;
  int tid = threadIdx.x;
  int tx = tid & 7;
  int ty = tid >> 3;
  int t0 = ty * 2, t1 = t0 + 1;
  int v0 = tx * 4;

  for (int i = tid; i < 256 * 36; i += 256) S[i] = 0.f;
  __syncthreads();

  for (int c = 0; c < NC; c++) {
    size_t base = ((size_t)bh * LL + (size_t)c * BT) * DH;
    const float* ap = att + ((size_t)bh * NC + c) * (BT * BT);
    for (int i = tid; i < BT * DH; i += 256) {
      int t = i >> 8, d = i & 255;
      Aq[t * 257 + d] = qt[base + i];
      Bk[t * 257 + d] = kt[base + i];
    }
    for (int i = tid; i < BT * BT; i += 256) Tt[i] = ap[i];
    __syncthreads();

    float4 r0 = make_float4(0, 0, 0, 0), r1 = make_float4(0, 0, 0, 0);
    for (int d = 0; d < DH; d++) {
      float4 sv = *(float4*)&S[d * 36 + v0];
      float q0 = Aq[t0 * 257 + d], q1 = Aq[t1 * 257 + d];
      r0.x += q0 * sv.x; r0.y += q0 * sv.y; r0.z += q0 * sv.z; r0.w += q0 * sv.w;
      r1.x += q1 * sv.x; r1.y += q1 * sv.y; r1.z += q1 * sv.z; r1.w += q1 * sv.w;
    }
    __syncthreads();
    for (int i = tid; i < BT * DH; i += 256) {
      int t = i >> 8, d = i & 255;
      Aq[t * 257 + d] = wt[base + i];
    }
    __syncthreads();
    {
      float4 a0 = make_float4(0, 0, 0, 0), a1 = make_float4(0, 0, 0, 0);
      for (int d = 0; d < DH; d++) {
        float4 sv = *(float4*)&S[d * 36 + v0];
        float w0 = Aq[t0 * 257 + d], w1 = Aq[t1 * 257 + d];
        a0.x += w0 * sv.x; a0.y += w0 * sv.y; a0.z += w0 * sv.z; a0.w += w0 * sv.w;
        a1.x += w1 * sv.x; a1.y += w1 * sv.y; a1.z += w1 * sv.z; a1.w += w1 * sv.w;
      }
      float4 u0 = *(const float4*)&ut[base + (size_t)t0 * DH + vb * 32 + v0];
      float4 u1 = *(const float4*)&ut[base + (size_t)t1 * DH + vb * 32 + v0];
      *(float4*)&Un[t0 * 36 + v0] = make_float4(u0.x - a0.x, u0.y - a0.y, u0.z - a0.z, u0.w - a0.w);
      *(float4*)&Un[t1 * 36 + v0] = make_float4(u1.x - a1.x, u1.y - a1.y, u1.z - a1.z, u1.w - a1.w);
    }
    __syncthreads();
    for (int s = 0; s <= t1; s++) {
      float4 u4 = *(float4*)&Un[s * 36 + v0];
      float av1 = Tt[t1 * 64 + s];
      r1.x += av1 * u4.x; r1.y += av1 * u4.y; r1.z += av1 * u4.z; r1.w += av1 * u4.w;
      if (s <= t0) {
        float av0 = Tt[t0 * 64 + s];
        r0.x += av0 * u4.x; r0.y += av0 * u4.y; r0.z += av0 * u4.z; r0.w += av0 * u4.w;
      }
    }
    {
      size_t o0 = (((size_t)b * LL + c * BT + t0) * HH + h) * DH + vb * 32 + v0;
      size_t o1 = (((size_t)b * LL + c * BT + t1) * HH + h) * DH + vb * 32 + v0;
      *(float4*)&og[o0] = r0;
      *(float4*)&og[o1] = r1;
    }
    {
      int d = tid;
      float4 sa[8];
#pragma unroll
      for (int j = 0; j < 8; j++) sa[j] = *(float4*)&S[d * 36 + j * 4];
      for (int t = 0; t < BT; t++) {
        float kv = Bk[t * 257 + d];
#pragma unroll
        for (int j = 0; j < 8; j++) {
          float4 u4 = *(float4*)&Un[t * 36 + j * 4];
          sa[j].x += kv * u4.x; sa[j].y += kv * u4.y;
          sa[j].z += kv * u4.z; sa[j].w += kv * u4.w;
        }
      }
#pragma unroll
      for (int j = 0; j < 8; j++) *(float4*)&S[d * 36 + j * 4] = sa[j];
    }
    __syncthreads();
  }
}

// -------------------- per-head RMSNorm * g_norm --------------------
__global__ __launch_bounds__(256) void rms_kernel(
    const float* __restrict__ og, const float* __restrict__ gn, float* __restrict__ on)
{
  __shared__ float red[256];
  int idx = blockIdx.x;
  int d = threadIdx.x;
  float v = og[(size_t)idx * DH + d];
  red[d] = v * v;
  __syncthreads();
  for (int s = 128; s; s >>= 1) { if (d < s) red[d] += red[d + s]; __syncthreads(); }
  float scale = rsqrtf(red[0] * (1.f / DH) + 1e-5f);
  on[(size_t)idx * DH + d] = v * scale * gn[d];
}

// -------------------- host launch --------------------
#define SOLVE_SMEM ((3*64*257 + 64*64 + 64) * 4)
#define ATTN_SMEM  ((2*64*257) * 4)
#define SCAN_SMEM  ((256*36 + 2*64*257 + 64*64 + 64*36) * 4)

extern "C" void kernel_launch(void* const* d_in, const int* in_sizes, int n_in,
                              void* d_out, int out_size)
{
  const float* hs = (const float*)d_in[0];
  const float* Wq = (const float*)d_in[1];
  const float* Wk = (const float*)d_in[2];
  const float* Wv = (const float*)d_in[3];
  const float* Wb = (const float*)d_in[4];
  const float* cq = (const float*)d_in[5];
  const float* ck = (const float*)d_in[6];
  const float* cv = (const float*)d_in[7];
  const float* gn = (const float*)d_in[8];
  const float* Wo = (const float*)d_in[9];
  float* out = (float*)d_out;

  float *preq, *prek, *prev, *qt, *kt, *vt, *wt, *ut, *beta, *att, *og, *on;
  __half *ah, *wh;
  cudaGetSymbolAddress((void**)&preq, g_preq);
  cudaGetSymbolAddress((void**)&prek, g_prek);
  cudaGetSymbolAddress((void**)&prev, g_prev);
  cudaGetSymbolAddress((void**)&qt, g_qt);
  cudaGetSymbolAddress((void**)&kt, g_kt);
  cudaGetSymbolAddress((void**)&vt, g_vt);
  cudaGetSymbolAddress((void**)&wt, g_wt);
  cudaGetSymbolAddress((void**)&ut, g_ut);
  cudaGetSymbolAddress((void**)&beta, g_beta);
  cudaGetSymbolAddress((void**)&att, g_att);
  cudaGetSymbolAddress((void**)&og, g_og);
  cudaGetSymbolAddress((void**)&on, g_on);
  cudaGetSymbolAddress((void**)&ah, g_ah);
  cudaGetSymbolAddress((void**)&wh, g_wh);

  cudaFuncSetAttribute(gemm_h_kernel, cudaFuncAttributeMaxDynamicSharedMemorySize, GEMM_SMEM);
  cudaFuncSetAttribute(solve_kernel, cudaFuncAttributeMaxDynamicSharedMemorySize, SOLVE_SMEM);
  cudaFuncSetAttribute(attn_kernel, cudaFuncAttributeMaxDynamicSharedMemorySize, ATTN_SMEM);
  cudaFuncSetAttribute(scan_kernel, cudaFuncAttributeMaxDynamicSharedMemorySize, SCAN_SMEM);

  dim3 gg(DDIM / 128, (BB * LL) / 128);   // (16, 64)
  const int actN4 = BLD / 4, wN4 = DD2 / 4;

  // fp16 conversions
  cvt_kernel<<<(actN4 + 255) / 256, 256>>>(hs, ah, actN4);
  cvt_kernel<<<(wN4 + 255) / 256, 256>>>(Wq, wh + 0 * (size_t)DD2, wN4);
  cvt_kernel<<<(wN4 + 255) / 256, 256>>>(Wk, wh + 1 * (size_t)DD2, wN4);
  cvt_kernel<<<(wN4 + 255) / 256, 256>>>(Wv, wh + 2 * (size_t)DD2, wN4);
  cvt_kernel<<<(wN4 + 255) / 256, 256>>>(Wo, wh + 3 * (size_t)DD2, wN4);

  gemm_h_kernel<<<gg, 256, GEMM_SMEM>>>(ah, wh + 0 * (size_t)DD2, preq, BB * LL, DDIM, DDIM);
  gemm_h_kernel<<<gg, 256, GEMM_SMEM>>>(ah, wh + 1 * (size_t)DD2, prek, BB * LL, DDIM, DDIM);
  gemm_h_kernel<<<gg, 256, GEMM_SMEM>>>(ah, wh + 2 * (size_t)DD2, prev, BB * LL, DDIM, DDIM);
  beta_kernel<<<BB * LL, 256>>>(hs, Wb, beta);

  conv_kernel<<<BB * LL * HH, 256>>>(preq, cq, qt, 0);
  conv_kernel<<<BB * LL * HH, 256>>>(prek, ck, kt, 1);
  conv_kernel<<<BB * LL * HH, 256>>>(prev, cv, vt, 2);

  solve_kernel<<<BB * HH * NC, 512, SOLVE_SMEM>>>(kt, vt, beta, wt, ut);
  attn_kernel<<<BB * HH * NC, 256, ATTN_SMEM>>>(qt, kt, att);
  scan_kernel<<<BB * HH * 8, 256, SCAN_SMEM>>>(qt, kt, wt, ut, att, og);

  rms_kernel<<<BB * LL * HH, 256>>>(og, gn, on);
  cvt_kernel<<<(actN4 + 255) / 256, 256>>>(on, ah, actN4);
  gemm_h_kernel<<<gg, 256, GEMM_SMEM>>>(ah, wh + 3 * (size_t)DD2, out, BB * LL, DDIM, DDIM);
}

// round 6
// speedup vs baseline: 2.1460x; 1.0480x over previous
#include <cuda_runtime.h>
#include <cuda_fp16.h>
#include <math.h>
#include <stdint.h>

#define BB 2
#define LL 4096
#define DDIM 2048
#define HH 8
#define DH 256
#define BT 64
#define NC 64          // LL / BT
#define BLD (BB*LL*DDIM)
#define DD2 (DDIM*DDIM)

// -------------------- scratch (device globals; no allocation) --------------------
__device__ float g_preq[BLD];
__device__ float g_prek[BLD];
__device__ float g_prev[BLD];
__device__ float g_qt[BLD];
__device__ float g_kt[BLD];
__device__ float g_vt[BLD];
__device__ float g_wt[BLD];
__device__ float g_ut[BLD];
__device__ float g_beta[BB*HH*LL];
__device__ float g_att[(size_t)BB*HH*NC*BT*BT];
__device__ float g_og[BLD];
__device__ float g_on[BLD];
// fp16 scratch (16B aligned for cp.async)
__device__ __align__(128) __half g_ah[BLD];     // activation fp16
__device__ __align__(128) __half g_wh[4*DD2];   // Wq,Wk,Wv,Wo fp16

// ==================== convert fp32 -> fp16 ====================
__global__ __launch_bounds__(256) void cvt_kernel(
    const float* __restrict__ x, __half* __restrict__ h, int n4)
{
  int i = blockIdx.x * blockDim.x + threadIdx.x;
  if (i >= n4) return;
  float4 v = *(const float4*)(x + (size_t)i * 4);
  __half2* hp = (__half2*)(h + (size_t)i * 4);
  hp[0] = __floats2half2_rn(v.x, v.y);
  hp[1] = __floats2half2_rn(v.z, v.w);
}

// ==================== fp16 HMMA GEMM, 4-stage cp.async ====================
// C[M,N] = A[M,K]@B[N,K]^T, fp32 accumulate.
// 128x128x32 CTA tile, 8 warps (2x4), warp tile 64x32, mma.m16n8k16.

#define GSTRIDE 40                     // padded fp16 row stride (80B)
#define GTILE (128*GSTRIDE)            // elems per tile matrix (5120)
#define ABYTES (GTILE*2)               // 10240 B per array
#define STAGEB (2*ABYTES)              // A,B  (20480 B)
#define NSTAGE 4
#define GEMM_SMEM (NSTAGE*STAGEB)      // 81920 B

__device__ __forceinline__ void cpa16(uint32_t dst, const void* src) {
  asm volatile("cp.async.ca.shared.global [%0], [%1], 16;" :: "r"(dst), "l"(src));
}
#define CP_COMMIT() asm volatile("cp.async.commit_group;" ::: "memory")
#define CP_WAIT(n)  asm volatile("cp.async.wait_group %0;" :: "n"(n) : "memory")

__device__ __forceinline__ void ldsm4(uint32_t* r, uint32_t addr) {
  asm volatile("ldmatrix.sync.aligned.m8n8.x4.shared.b16 {%0,%1,%2,%3}, [%4];"
    : "=r"(r[0]), "=r"(r[1]), "=r"(r[2]), "=r"(r[3]) : "r"(addr));
}
__device__ __forceinline__ void mma16816(float* d, const uint32_t* a, uint32_t b0, uint32_t b1) {
  asm volatile("mma.sync.aligned.m16n8k16.row.col.f32.f16.f16.f32 "
    "{%0,%1,%2,%3}, {%4,%5,%6,%7}, {%8,%9}, {%0,%1,%2,%3};"
    : "+f"(d[0]), "+f"(d[1]), "+f"(d[2]), "+f"(d[3])
    : "r"(a[0]), "r"(a[1]), "r"(a[2]), "r"(a[3]), "r"(b0), "r"(b1));
}

__device__ __forceinline__ void load_stage_async(
    const __half* __restrict__ A, const __half* __restrict__ B,
    int bm, int bn, int K, int k0, uint32_t sb, int tid)
{
  const __half* srcs[2] = {A, B};
  const int rb[2] = {bm, bn};
#pragma unroll
  for (int a = 0; a < 2; a++) {
#pragma unroll
    for (int i = 0; i < 2; i++) {
      int idx = tid + i * 256;          // 0..511
      int r = idx >> 2, ch = idx & 3;   // row, 16B chunk
      const __half* g = srcs[a] + (size_t)(rb[a] + r) * K + k0 + ch * 8;
      uint32_t dst = sb + a * ABYTES + (uint32_t)(r * 80 + ch * 16);
      cpa16(dst, g);
    }
  }
}

__global__ __launch_bounds__(256, 2) void gemm_h_kernel(
    const __half* __restrict__ A, const __half* __restrict__ B,
    float* __restrict__ C, int M, int N, int K)
{
  extern __shared__ char sm[];
  const int tid = threadIdx.x, lane = tid & 31, wid = tid >> 5;
  const int warp_m = wid >> 2, warp_n = wid & 3;
  const int bm = blockIdx.y * 128, bn = blockIdx.x * 128;
  const uint32_t sbase = (uint32_t)__cvta_generic_to_shared(sm);

  float acc[4][4][4];
#pragma unroll
  for (int i = 0; i < 4; i++)
#pragma unroll
    for (int j = 0; j < 4; j++)
#pragma unroll
      for (int e = 0; e < 4; e++) acc[i][j][e] = 0.f;

  const int NT = K / 32;                // 64
  // prologue: stages 0..2
#pragma unroll
  for (int p = 0; p < NSTAGE - 1; p++) {
    load_stage_async(A, B, bm, bn, K, p * 32, sbase + p * STAGEB, tid);
    CP_COMMIT();
  }

  const int arow  = warp_m * 64 + (lane & 15);
  const int acol0 = (lane >> 4) * 8;
  const int brow  = warp_n * 32 + (lane >> 4) * 8 + (lane & 7);
  const int bcol0 = ((lane >> 3) & 1) * 8;

  for (int kt = 0; kt < NT; kt++) {
    CP_WAIT(NSTAGE - 2);
    __syncthreads();
    // issue kt+3 (clamped at the tail so group accounting stays uniform)
    {
      int knext = kt + NSTAGE - 1;
      int kc = knext < NT ? knext : NT - 1;
      load_stage_async(A, B, bm, bn, K, kc * 32, sbase + (knext & (NSTAGE - 1)) * STAGEB, tid);
      CP_COMMIT();
    }
    const uint32_t stb = sbase + (kt & (NSTAGE - 1)) * STAGEB;
    const uint32_t aoff = stb;
    const uint32_t boff = stb + ABYTES;
#pragma unroll
    for (int kk = 0; kk < 32; kk += 16) {
      uint32_t af[4][4], bf[2][4];
#pragma unroll
      for (int mt = 0; mt < 4; mt++) {
        uint32_t ab = (uint32_t)(((arow + mt * 16) * GSTRIDE + kk + acol0) * 2);
        ldsm4(af[mt], aoff + ab);
      }
#pragma unroll
      for (int p = 0; p < 2; p++) {
        uint32_t bb = (uint32_t)(((brow + p * 16) * GSTRIDE + kk + bcol0) * 2);
        ldsm4(bf[p], boff + bb);
      }
#pragma unroll
      for (int mt = 0; mt < 4; mt++)
#pragma unroll
        for (int nt = 0; nt < 4; nt++) {
          const uint32_t* bp = bf[nt >> 1];
          int bi = (nt & 1) * 2;
          mma16816(acc[mt][nt], af[mt], bp[bi], bp[bi + 1]);
        }
    }
  }
  __syncthreads();
  // epilogue
  const int row0 = bm + warp_m * 64 + (lane >> 2);
  const int col0 = bn + warp_n * 32 + (lane & 3) * 2;
#pragma unroll
  for (int mt = 0; mt < 4; mt++)
#pragma unroll
    for (int nt = 0; nt < 4; nt++) {
      int r = row0 + mt * 16;
      int c = col0 + nt * 8;
      *(float2*)(C + (size_t)r * N + c)       = make_float2(acc[mt][nt][0], acc[mt][nt][1]);
      *(float2*)(C + (size_t)(r + 8) * N + c) = make_float2(acc[mt][nt][2], acc[mt][nt][3]);
    }
}

// -------------------- beta = sigmoid(hs @ Wb^T), [B,H,L] --------------------
__global__ __launch_bounds__(256) void beta_kernel(
    const float* __restrict__ hs, const float* __restrict__ Wb, float* __restrict__ beta)
{
  int bl = blockIdx.x;
  int b = bl / LL, l = bl % LL;
  int w = threadIdx.x >> 5, lane = threadIdx.x & 31;
  const float* x = hs + (size_t)bl * DDIM;
  const float* wb = Wb + (size_t)w * DDIM;
  float s = 0.f;
  for (int d = lane; d < DDIM; d += 32) s += x[d] * wb[d];
#pragma unroll
  for (int o = 16; o; o >>= 1) s += __shfl_xor_sync(0xffffffffu, s, o);
  if (lane == 0)
    beta[((size_t)b * HH + w) * LL + l] = 1.f / (1.f + expf(-s));
}

// -------------------- conv + SiLU (+l2norm), warp-per-token --------------------
// grid = BB*HH*(LL/8), 256 threads (8 warps), warp w handles l = lt*8 + w.
__global__ __launch_bounds__(256) void conv_kernel(
    const float* __restrict__ pre, const float* __restrict__ cw,
    float* __restrict__ out, int mode)
{
  int blk = blockIdx.x;
  int lt = blk & (LL / 8 - 1);
  int bh = blk >> 9;                 // LL/8 = 512
  int h = bh % HH, b = bh / HH;
  int w = threadIdx.x >> 5, lane = threadIdx.x & 31;
  int l = lt * 8 + w;
  const float* base = pre + ((size_t)b * LL) * DDIM + h * DH;
  float y[8];
  float ss = 0.f;
#pragma unroll
  for (int j = 0; j < 8; j++) {
    int dd = lane + j * 32;
    int c = h * DH + dd;
    float4 cv = *(const float4*)(cw + (size_t)c * 4);
    float acc = base[(size_t)l * DDIM + dd] * cv.w;
    if (l >= 1) acc += base[(size_t)(l - 1) * DDIM + dd] * cv.z;
    if (l >= 2) acc += base[(size_t)(l - 2) * DDIM + dd] * cv.y;
    if (l >= 3) acc += base[(size_t)(l - 3) * DDIM + dd] * cv.x;
    float yy = acc / (1.f + expf(-acc));
    y[j] = yy;
    ss += yy * yy;
  }
  float scale = 1.f;
  if (mode < 2) {
#pragma unroll
    for (int o = 16; o; o >>= 1) ss += __shfl_xor_sync(0xffffffffu, ss, o);
    scale = rsqrtf(ss + 1e-6f);
    if (mode == 0) scale *= 0.0625f;
  }
  float* op = out + (((size_t)b * HH + h) * LL + l) * DH;
#pragma unroll
  for (int j = 0; j < 8; j++) op[lane + j * 32] = y[j] * scale;
}

// -------------------- per-chunk triangular solve --------------------
__global__ __launch_bounds__(512) void solve_kernel(
    const float* __restrict__ kt, const float* __restrict__ vt,
    const float* __restrict__ beta, float* __restrict__ Wt, float* __restrict__ Ut)
{
  extern __shared__ float sh[];
  float* sk = sh;
  float* sw = sk + 64 * 257;
  float* su = sw + 64 * 257;
  float* sM = su + 64 * 257;
  float* sb = sM + 64 * 64;
  int blk = blockIdx.x;
  int c = blk % NC, bh = blk / NC;
  size_t base = ((size_t)bh * LL + (size_t)c * BT) * DH;
  int tid = threadIdx.x;

  if (tid < 64) sb[tid] = beta[(size_t)bh * LL + c * BT + tid];
  __syncthreads();
  for (int i = tid; i < BT * DH; i += 512) {
    int t = i >> 8, d = i & 255;
    float kv = kt[base + i];
    float bt = sb[t];
    sk[t * 257 + d] = kv;
    sw[t * 257 + d] = kv * bt;
    su[t * 257 + d] = vt[base + i] * bt;
  }
  __syncthreads();
  for (int e = tid; e < BT * BT; e += 512) {
    int t = e >> 6, s = e & 63;
    float acc = 0.f;
    if (s < t) {
      const float* kb = &sw[t * 257];
      const float* kk = &sk[s * 257];
#pragma unroll 8
      for (int d = 0; d < DH; d++) acc += kb[d] * kk[d];
    }
    sM[e] = acc;
  }
  __syncthreads();
  if (tid < 256) {
    int d = tid;
    for (int t = 1; t < BT; t++) {
      float aw = 0.f;
      const float* Mr = &sM[t * 64];
      for (int s = 0; s < t; s++) aw += Mr[s] * sw[s * 257 + d];
      sw[t * 257 + d] -= aw;
    }
  } else {
    int d = tid - 256;
    for (int t = 1; t < BT; t++) {
      float au = 0.f;
      const float* Mr = &sM[t * 64];
      for (int s = 0; s < t; s++) au += Mr[s] * su[s * 257 + d];
      su[t * 257 + d] -= au;
    }
  }
  __syncthreads();
  for (int i = tid; i < BT * DH; i += 512) {
    int t = i >> 8, d = i & 255;
    Wt[base + i] = sw[t * 257 + d];
    Ut[base + i] = su[t * 257 + d];
  }
}

// -------------------- attn = tril(q k^T) --------------------
__global__ __launch_bounds__(256) void attn_kernel(
    const float* __restrict__ qt, const float* __restrict__ kt, float* __restrict__ att)
{
  extern __shared__ float sh[];
  float* sq = sh;
  float* sk = sq + 64 * 257;
  int blk = blockIdx.x;
  int c = blk % NC, bh = blk / NC;
  size_t base = ((size_t)bh * LL + (size_t)c * BT) * DH;
  int tid = threadIdx.x;
  for (int i = tid; i < BT * DH; i += 256) {
    int t = i >> 8, d = i & 255;
    sq[t * 257 + d] = qt[base + i];
    sk[t * 257 + d] = kt[base + i];
  }
  __syncthreads();
  float* ap = att + (size_t)blk * (BT * BT);
  for (int e = tid; e < BT * BT; e += 256) {
    int t = e >> 6, s = e & 63;
    float acc = 0.f;
    if (s <= t) {
      const float* q = &sq[t * 257];
      const float* k = &sk[s * 257];
#pragma unroll 8
      for (int d = 0; d < DH; d++) acc += q[d] * k[d];
    }
    ap[e] = acc;
  }
}

// -------------------- sequential chunk scan, dv split 8 ways --------------------
__global__ __launch_bounds__(256) void scan_kernel(
    const float* __restrict__ qt, const float* __restrict__ kt,
    const float* __restrict__ wt, const float* __restrict__ ut,
    const float* __restrict__ att, float* __restrict__ og)
{
  extern __shared__ float sh[];
  float* S  = sh;
  float* Aq = S + 256 * 36;
  float* Bk = Aq + 64 * 257;
  float* Tt = Bk + 64 * 257;
  float* Un = Tt + 64 * 64;
  int blk = blockIdx.x;
  int vb = blk & 7;
  int bh = blk >> 3;
  int b = bh / HH, h = bh % HH;
  int tid = threadIdx.x;
  int tx = tid & 7;
  int ty = tid >> 3;
  int t0 = ty * 2, t1 = t0 + 1;
  int v0 = tx * 4;

  for (int i = tid; i < 256 * 36; i += 256) S[i] = 0.f;
  __syncthreads();

  for (int c = 0; c < NC; c++) {
    size_t base = ((size_t)bh * LL + (size_t)c * BT) * DH;
    const float* ap = att + ((size_t)bh * NC + c) * (BT * BT);
    for (int i = tid; i < BT * DH; i += 256) {
      int t = i >> 8, d = i & 255;
      Aq[t * 257 + d] = qt[base + i];
      Bk[t * 257 + d] = kt[base + i];
    }
    for (int i = tid; i < BT * BT; i += 256) Tt[i] = ap[i];
    __syncthreads();

    float4 r0 = make_float4(0, 0, 0, 0), r1 = make_float4(0, 0, 0, 0);
    for (int d = 0; d < DH; d++) {
      float4 sv = *(float4*)&S[d * 36 + v0];
      float q0 = Aq[t0 * 257 + d], q1 = Aq[t1 * 257 + d];
      r0.x += q0 * sv.x; r0.y += q0 * sv.y; r0.z += q0 * sv.z; r0.w += q0 * sv.w;
      r1.x += q1 * sv.x; r1.y += q1 * sv.y; r1.z += q1 * sv.z; r1.w += q1 * sv.w;
    }
    __syncthreads();
    for (int i = tid; i < BT * DH; i += 256) {
      int t = i >> 8, d = i & 255;
      Aq[t * 257 + d] = wt[base + i];
    }
    __syncthreads();
    {
      float4 a0 = make_float4(0, 0, 0, 0), a1 = make_float4(0, 0, 0, 0);
      for (int d = 0; d < DH; d++) {
        float4 sv = *(float4*)&S[d * 36 + v0];
        float w0 = Aq[t0 * 257 + d], w1 = Aq[t1 * 257 + d];
        a0.x += w0 * sv.x; a0.y += w0 * sv.y; a0.z += w0 * sv.z; a0.w += w0 * sv.w;
        a1.x += w1 * sv.x; a1.y += w1 * sv.y; a1.z += w1 * sv.z; a1.w += w1 * sv.w;
      }
      float4 u0 = *(const float4*)&ut[base + (size_t)t0 * DH + vb * 32 + v0];
      float4 u1 = *(const float4*)&ut[base + (size_t)t1 * DH + vb * 32 + v0];
      *(float4*)&Un[t0 * 36 + v0] = make_float4(u0.x - a0.x, u0.y - a0.y, u0.z - a0.z, u0.w - a0.w);
      *(float4*)&Un[t1 * 36 + v0] = make_float4(u1.x - a1.x, u1.y - a1.y, u1.z - a1.z, u1.w - a1.w);
    }
    __syncthreads();
    for (int s = 0; s <= t1; s++) {
      float4 u4 = *(float4*)&Un[s * 36 + v0];
      float av1 = Tt[t1 * 64 + s];
      r1.x += av1 * u4.x; r1.y += av1 * u4.y; r1.z += av1 * u4.z; r1.w += av1 * u4.w;
      if (s <= t0) {
        float av0 = Tt[t0 * 64 + s];
        r0.x += av0 * u4.x; r0.y += av0 * u4.y; r0.z += av0 * u4.z; r0.w += av0 * u4.w;
      }
    }
    {
      size_t o0 = (((size_t)b * LL + c * BT + t0) * HH + h) * DH + vb * 32 + v0;
      size_t o1 = (((size_t)b * LL + c * BT + t1) * HH + h) * DH + vb * 32 + v0;
      *(float4*)&og[o0] = r0;
      *(float4*)&og[o1] = r1;
    }
    {
      int d = tid;
      float4 sa[8];
#pragma unroll
      for (int j = 0; j < 8; j++) sa[j] = *(float4*)&S[d * 36 + j * 4];
      for (int t = 0; t < BT; t++) {
        float kv = Bk[t * 257 + d];
#pragma unroll
        for (int j = 0; j < 8; j++) {
          float4 u4 = *(float4*)&Un[t * 36 + j * 4];
          sa[j].x += kv * u4.x; sa[j].y += kv * u4.y;
          sa[j].z += kv * u4.z; sa[j].w += kv * u4.w;
        }
      }
#pragma unroll
      for (int j = 0; j < 8; j++) *(float4*)&S[d * 36 + j * 4] = sa[j];
    }
    __syncthreads();
  }
}

// -------------------- per-head RMSNorm * g_norm, warp-per-row --------------------
__global__ __launch_bounds__(256) void rms_kernel(
    const float* __restrict__ og, const float* __restrict__ gn, float* __restrict__ on)
{
  int w = threadIdx.x >> 5, lane = threadIdx.x & 31;
  size_t idx = (size_t)blockIdx.x * 8 + w;       // (b*LL + l)*HH + h
  const float* ip = og + idx * DH;
  float v[8];
  float ss = 0.f;
#pragma unroll
  for (int j = 0; j < 8; j++) {
    v[j] = ip[lane + j * 32];
    ss += v[j] * v[j];
  }
#pragma unroll
  for (int o = 16; o; o >>= 1) ss += __shfl_xor_sync(0xffffffffu, ss, o);
  float scale = rsqrtf(ss * (1.f / DH) + 1e-5f);
  float* op = on + idx * DH;
#pragma unroll
  for (int j = 0; j < 8; j++) op[lane + j * 32] = v[j] * scale * gn[lane + j * 32];
}

// -------------------- host launch --------------------
#define SOLVE_SMEM ((3*64*257 + 64*64 + 64) * 4)
#define ATTN_SMEM  ((2*64*257) * 4)
#define SCAN_SMEM  ((256*36 + 2*64*257 + 64*64 + 64*36) * 4)

extern "C" void kernel_launch(void* const* d_in, const int* in_sizes, int n_in,
                              void* d_out, int out_size)
{
  const float* hs = (const float*)d_in[0];
  const float* Wq = (const float*)d_in[1];
  const float* Wk = (const float*)d_in[2];
  const float* Wv = (const float*)d_in[3];
  const float* Wb = (const float*)d_in[4];
  const float* cq = (const float*)d_in[5];
  const float* ck = (const float*)d_in[6];
  const float* cv = (const float*)d_in[7];
  const float* gn = (const float*)d_in[8];
  const float* Wo = (const float*)d_in[9];
  float* out = (float*)d_out;

  float *preq, *prek, *prev, *qt, *kt, *vt, *wt, *ut, *beta, *att, *og, *on;
  __half *ah, *wh;
  cudaGetSymbolAddress((void**)&preq, g_preq);
  cudaGetSymbolAddress((void**)&prek, g_prek);
  cudaGetSymbolAddress((void**)&prev, g_prev);
  cudaGetSymbolAddress((void**)&qt, g_qt);
  cudaGetSymbolAddress((void**)&kt, g_kt);
  cudaGetSymbolAddress((void**)&vt, g_vt);
  cudaGetSymbolAddress((void**)&wt, g_wt);
  cudaGetSymbolAddress((void**)&ut, g_ut);
  cudaGetSymbolAddress((void**)&beta, g_beta);
  cudaGetSymbolAddress((void**)&att, g_att);
  cudaGetSymbolAddress((void**)&og, g_og);
  cudaGetSymbolAddress((void**)&on, g_on);
  cudaGetSymbolAddress((void**)&ah, g_ah);
  cudaGetSymbolAddress((void**)&wh, g_wh);

  cudaFuncSetAttribute(gemm_h_kernel, cudaFuncAttributeMaxDynamicSharedMemorySize, GEMM_SMEM);
  cudaFuncSetAttribute(solve_kernel, cudaFuncAttributeMaxDynamicSharedMemorySize, SOLVE_SMEM);
  cudaFuncSetAttribute(attn_kernel, cudaFuncAttributeMaxDynamicSharedMemorySize, ATTN_SMEM);
  cudaFuncSetAttribute(scan_kernel, cudaFuncAttributeMaxDynamicSharedMemorySize, SCAN_SMEM);

  dim3 gg(DDIM / 128, (BB * LL) / 128);   // (16, 64)
  const int actN4 = BLD / 4, wN4 = DD2 / 4;

  // order chosen so launch #4 (the profiled slot) is gemm_h_kernel
  cvt_kernel<<<(actN4 + 255) / 256, 256>>>(hs, ah, actN4);
  cvt_kernel<<<(wN4 + 255) / 256, 256>>>(Wq, wh + 0 * (size_t)DD2, wN4);
  cvt_kernel<<<(wN4 + 255) / 256, 256>>>(Wk, wh + 1 * (size_t)DD2, wN4);
  gemm_h_kernel<<<gg, 256, GEMM_SMEM>>>(ah, wh + 0 * (size_t)DD2, preq, BB * LL, DDIM, DDIM);   // #4
  cvt_kernel<<<(wN4 + 255) / 256, 256>>>(Wv, wh + 2 * (size_t)DD2, wN4);
  cvt_kernel<<<(wN4 + 255) / 256, 256>>>(Wo, wh + 3 * (size_t)DD2, wN4);
  gemm_h_kernel<<<gg, 256, GEMM_SMEM>>>(ah, wh + 1 * (size_t)DD2, prek, BB * LL, DDIM, DDIM);
  gemm_h_kernel<<<gg, 256, GEMM_SMEM>>>(ah, wh + 2 * (size_t)DD2, prev, BB * LL, DDIM, DDIM);
  beta_kernel<<<BB * LL, 256>>>(hs, Wb, beta);

  conv_kernel<<<BB * HH * (LL / 8), 256>>>(preq, cq, qt, 0);
  conv_kernel<<<BB * HH * (LL / 8), 256>>>(prek, ck, kt, 1);
  conv_kernel<<<BB * HH * (LL / 8), 256>>>(prev, cv, vt, 2);

  solve_kernel<<<BB * HH * NC, 512, SOLVE_SMEM>>>(kt, vt, beta, wt, ut);
  attn_kernel<<<BB * HH * NC, 256, ATTN_SMEM>>>(qt, kt, att);
  scan_kernel<<<BB * HH * 8, 256, SCAN_SMEM>>>(qt, kt, wt, ut, att, og);

  rms_kernel<<<BB * LL * HH / 8, 256>>>(og, gn, on);
  cvt_kernel<<<(actN4 + 255) / 256, 256>>>(on, ah, actN4);
  gemm_h_kernel<<<gg, 256, GEMM_SMEM>>>(ah, wh + 3 * (size_t)DD2, out, BB * LL, DDIM, DDIM);
}

// round 7
// speedup vs baseline: 2.9040x; 1.3532x over previous
#include <cuda_runtime.h>
#include <cuda_fp16.h>
#include <math.h>
#include <stdint.h>

#define BB 2
#define LL 4096
#define DDIM 2048
#define HH 8
#define DH 256
#define BT 64
#define NC 64          // LL / BT
#define BLD (BB*LL*DDIM)
#define DD2 (DDIM*DDIM)
#define QS 260         // padded fp32 tile stride (16B aligned)
#define SCS 36         // S / Un row stride

// -------------------- scratch (device globals; no allocation) --------------------
__device__ float g_preq[BLD];
__device__ float g_prek[BLD];
__device__ float g_prev[BLD];
__device__ float g_qt[BLD];
__device__ float g_kt[BLD];
__device__ float g_vt[BLD];
__device__ float g_wt[BLD];
__device__ float g_ut[BLD];
__device__ float g_beta[BB*HH*LL];
__device__ float g_att[(size_t)BB*HH*NC*BT*BT];
__device__ float g_og[BLD];
__device__ float g_on[BLD];
__device__ __align__(128) __half g_ah[BLD];
__device__ __align__(128) __half g_wh[4*DD2];

// -------------------- f32x2 packed helpers --------------------
__device__ __forceinline__ unsigned long long pack2dup(float x) {
  unsigned long long r;
  asm("mov.b64 %0, {%1,%1};" : "=l"(r) : "f"(x));
  return r;
}
__device__ __forceinline__ void unpack2(unsigned long long v, float& x, float& y) {
  asm("mov.b64 {%0,%1}, %2;" : "=f"(x), "=f"(y) : "l"(v));
}
__device__ __forceinline__ void fma2(unsigned long long& d,
                                     unsigned long long a, unsigned long long b) {
  asm("fma.rn.f32x2 %0, %1, %2, %0;" : "+l"(d) : "l"(a), "l"(b));
}

// ==================== convert fp32 -> fp16 ====================
__global__ __launch_bounds__(256) void cvt_kernel(
    const float* __restrict__ x, __half* __restrict__ h, int n4)
{
  int i = blockIdx.x * blockDim.x + threadIdx.x;
  if (i >= n4) return;
  float4 v = *(const float4*)(x + (size_t)i * 4);
  __half2* hp = (__half2*)(h + (size_t)i * 4);
  hp[0] = __floats2half2_rn(v.x, v.y);
  hp[1] = __floats2half2_rn(v.z, v.w);
}

// ==================== fp16 HMMA GEMM, 4-stage cp.async ====================
#define GSTRIDE 40
#define GTILE (128*GSTRIDE)
#define ABYTES (GTILE*2)
#define STAGEB (2*ABYTES)
#define NSTAGE 4
#define GEMM_SMEM (NSTAGE*STAGEB)

__device__ __forceinline__ void cpa16(uint32_t dst, const void* src) {
  asm volatile("cp.async.ca.shared.global [%0], [%1], 16;" :: "r"(dst), "l"(src));
}
#define CP_COMMIT() asm volatile("cp.async.commit_group;" ::: "memory")
#define CP_WAIT(n)  asm volatile("cp.async.wait_group %0;" :: "n"(n) : "memory")

__device__ __forceinline__ void ldsm4(uint32_t* r, uint32_t addr) {
  asm volatile("ldmatrix.sync.aligned.m8n8.x4.shared.b16 {%0,%1,%2,%3}, [%4];"
    : "=r"(r[0]), "=r"(r[1]), "=r"(r[2]), "=r"(r[3]) : "r"(addr));
}
__device__ __forceinline__ void mma16816(float* d, const uint32_t* a, uint32_t b0, uint32_t b1) {
  asm volatile("mma.sync.aligned.m16n8k16.row.col.f32.f16.f16.f32 "
    "{%0,%1,%2,%3}, {%4,%5,%6,%7}, {%8,%9}, {%0,%1,%2,%3};"
    : "+f"(d[0]), "+f"(d[1]), "+f"(d[2]), "+f"(d[3])
    : "r"(a[0]), "r"(a[1]), "r"(a[2]), "r"(a[3]), "r"(b0), "r"(b1));
}

__device__ __forceinline__ void load_stage_async(
    const __half* __restrict__ A, const __half* __restrict__ B,
    int bm, int bn, int K, int k0, uint32_t sb, int tid)
{
  const __half* srcs[2] = {A, B};
  const int rb[2] = {bm, bn};
#pragma unroll
  for (int a = 0; a < 2; a++) {
#pragma unroll
    for (int i = 0; i < 2; i++) {
      int idx = tid + i * 256;
      int r = idx >> 2, ch = idx & 3;
      const __half* g = srcs[a] + (size_t)(rb[a] + r) * K + k0 + ch * 8;
      uint32_t dst = sb + a * ABYTES + (uint32_t)(r * 80 + ch * 16);
      cpa16(dst, g);
    }
  }
}

__global__ __launch_bounds__(256, 2) void gemm_h_kernel(
    const __half* __restrict__ A, const __half* __restrict__ B,
    float* __restrict__ C, int M, int N, int K)
{
  extern __shared__ char sm[];
  const int tid = threadIdx.x, lane = tid & 31, wid = tid >> 5;
  const int warp_m = wid >> 2, warp_n = wid & 3;
  const int bm = blockIdx.y * 128, bn = blockIdx.x * 128;
  const uint32_t sbase = (uint32_t)__cvta_generic_to_shared(sm);

  float acc[4][4][4];
#pragma unroll
  for (int i = 0; i < 4; i++)
#pragma unroll
    for (int j = 0; j < 4; j++)
#pragma unroll
      for (int e = 0; e < 4; e++) acc[i][j][e] = 0.f;

  const int NT = K / 32;
#pragma unroll
  for (int p = 0; p < NSTAGE - 1; p++) {
    load_stage_async(A, B, bm, bn, K, p * 32, sbase + p * STAGEB, tid);
    CP_COMMIT();
  }

  const int arow  = warp_m * 64 + (lane & 15);
  const int acol0 = (lane >> 4) * 8;
  const int brow  = warp_n * 32 + (lane >> 4) * 8 + (lane & 7);
  const int bcol0 = ((lane >> 3) & 1) * 8;

  for (int kt = 0; kt < NT; kt++) {
    CP_WAIT(NSTAGE - 2);
    __syncthreads();
    {
      int knext = kt + NSTAGE - 1;
      int kc = knext < NT ? knext : NT - 1;
      load_stage_async(A, B, bm, bn, K, kc * 32, sbase + (knext & (NSTAGE - 1)) * STAGEB, tid);
      CP_COMMIT();
    }
    const uint32_t stb = sbase + (kt & (NSTAGE - 1)) * STAGEB;
    const uint32_t aoff = stb;
    const uint32_t boff = stb + ABYTES;
#pragma unroll
    for (int kk = 0; kk < 32; kk += 16) {
      uint32_t af[4][4], bf[2][4];
#pragma unroll
      for (int mt = 0; mt < 4; mt++) {
        uint32_t ab = (uint32_t)(((arow + mt * 16) * GSTRIDE + kk + acol0) * 2);
        ldsm4(af[mt], aoff + ab);
      }
#pragma unroll
      for (int p = 0; p < 2; p++) {
        uint32_t bb = (uint32_t)(((brow + p * 16) * GSTRIDE + kk + bcol0) * 2);
        ldsm4(bf[p], boff + bb);
      }
#pragma unroll
      for (int mt = 0; mt < 4; mt++)
#pragma unroll
        for (int nt = 0; nt < 4; nt++) {
          const uint32_t* bp = bf[nt >> 1];
          int bi = (nt & 1) * 2;
          mma16816(acc[mt][nt], af[mt], bp[bi], bp[bi + 1]);
        }
    }
  }
  __syncthreads();
  const int row0 = bm + warp_m * 64 + (lane >> 2);
  const int col0 = bn + warp_n * 32 + (lane & 3) * 2;
#pragma unroll
  for (int mt = 0; mt < 4; mt++)
#pragma unroll
    for (int nt = 0; nt < 4; nt++) {
      int r = row0 + mt * 16;
      int c = col0 + nt * 8;
      *(float2*)(C + (size_t)r * N + c)       = make_float2(acc[mt][nt][0], acc[mt][nt][1]);
      *(float2*)(C + (size_t)(r + 8) * N + c) = make_float2(acc[mt][nt][2], acc[mt][nt][3]);
    }
}

// -------------------- beta = sigmoid(hs @ Wb^T), [B,H,L] --------------------
__global__ __launch_bounds__(256) void beta_kernel(
    const float* __restrict__ hs, const float* __restrict__ Wb, float* __restrict__ beta)
{
  int bl = blockIdx.x;
  int b = bl / LL, l = bl % LL;
  int w = threadIdx.x >> 5, lane = threadIdx.x & 31;
  const float* x = hs + (size_t)bl * DDIM;
  const float* wb = Wb + (size_t)w * DDIM;
  float s = 0.f;
  for (int d = lane; d < DDIM; d += 32) s += x[d] * wb[d];
#pragma unroll
  for (int o = 16; o; o >>= 1) s += __shfl_xor_sync(0xffffffffu, s, o);
  if (lane == 0)
    beta[((size_t)b * HH + w) * LL + l] = 1.f / (1.f + expf(-s));
}

// -------------------- conv + SiLU (+l2norm), warp-per-token --------------------
__global__ __launch_bounds__(256) void conv_kernel(
    const float* __restrict__ pre, const float* __restrict__ cw,
    float* __restrict__ out, int mode)
{
  int blk = blockIdx.x;
  int lt = blk & (LL / 8 - 1);
  int bh = blk >> 9;
  int h = bh % HH, b = bh / HH;
  int w = threadIdx.x >> 5, lane = threadIdx.x & 31;
  int l = lt * 8 + w;
  const float* base = pre + ((size_t)b * LL) * DDIM + h * DH;
  float y[8];
  float ss = 0.f;
#pragma unroll
  for (int j = 0; j < 8; j++) {
    int dd = lane + j * 32;
    int c = h * DH + dd;
    float4 cv = *(const float4*)(cw + (size_t)c * 4);
    float acc = base[(size_t)l * DDIM + dd] * cv.w;
    if (l >= 1) acc += base[(size_t)(l - 1) * DDIM + dd] * cv.z;
    if (l >= 2) acc += base[(size_t)(l - 2) * DDIM + dd] * cv.y;
    if (l >= 3) acc += base[(size_t)(l - 3) * DDIM + dd] * cv.x;
    float yy = acc / (1.f + expf(-acc));
    y[j] = yy;
    ss += yy * yy;
  }
  float scale = 1.f;
  if (mode < 2) {
#pragma unroll
    for (int o = 16; o; o >>= 1) ss += __shfl_xor_sync(0xffffffffu, ss, o);
    scale = rsqrtf(ss + 1e-6f);
    if (mode == 0) scale *= 0.0625f;
  }
  float* op = out + (((size_t)b * HH + h) * LL + l) * DH;
#pragma unroll
  for (int j = 0; j < 8; j++) op[lane + j * 32] = y[j] * scale;
}

// -------------------- per-chunk triangular solve (512 thr, f32x2) ----------------
#define SOLVE_SMEM ((3*64*QS + 64*64 + 64) * 4)
__global__ __launch_bounds__(512) void solve_kernel(
    const float* __restrict__ kt, const float* __restrict__ vt,
    const float* __restrict__ beta, float* __restrict__ Wt, float* __restrict__ Ut)
{
  extern __shared__ float sh[];
  float* sk = sh;                 // [64][260]
  float* sw = sk + 64 * QS;
  float* su = sw + 64 * QS;
  float* sM = su + 64 * QS;       // [64][64]
  float* sb = sM + 64 * 64;
  int blk = blockIdx.x;
  int c = blk % NC, bh = blk / NC;
  size_t base = ((size_t)bh * LL + (size_t)c * BT) * DH;
  int tid = threadIdx.x;

  if (tid < 64) sb[tid] = beta[(size_t)bh * LL + c * BT + tid];
  __syncthreads();
  for (int i = tid; i < 4096; i += 512) {
    int t = i >> 6, dd = (i & 63) * 4;
    float bt = sb[t];
    float4 kv = *(const float4*)(kt + base + (size_t)t * DH + dd);
    float4 vv = *(const float4*)(vt + base + (size_t)t * DH + dd);
    *(float4*)&sk[t * QS + dd] = kv;
    *(float4*)&sw[t * QS + dd] = make_float4(kv.x * bt, kv.y * bt, kv.z * bt, kv.w * bt);
    *(float4*)&su[t * QS + dd] = make_float4(vv.x * bt, vv.y * bt, vv.z * bt, vv.w * bt);
  }
  __syncthreads();
  // M = strict_lower(kb @ k^T)
  for (int e = tid; e < BT * BT; e += 512) {
    int t = e >> 6, s = e & 63;
    float acc = 0.f;
    if (s < t) {
      unsigned long long a0 = 0, a1 = 0;
      const float* kb = &sw[t * QS];
      const float* kk = &sk[s * QS];
#pragma unroll 4
      for (int d = 0; d < DH; d += 4) {
        ulonglong2 q2 = *(const ulonglong2*)(kb + d);
        ulonglong2 k2 = *(const ulonglong2*)(kk + d);
        fma2(a0, q2.x, k2.x);
        fma2(a1, q2.y, k2.y);
      }
      float x0, x1, x2, x3;
      unpack2(a0, x0, x1); unpack2(a1, x2, x3);
      acc = (x0 + x1) + (x2 + x3);
    }
    sM[e] = acc;
  }
  __syncthreads();
  // unit-lower forward substitution
  if (tid < 256) {
    int d = tid;
    for (int t = 1; t < BT; t++) {
      float aw = 0.f;
      const float* Mr = &sM[t * 64];
      for (int s = 0; s < t; s++) aw += Mr[s] * sw[s * QS + d];
      sw[t * QS + d] -= aw;
    }
  } else {
    int d = tid - 256;
    for (int t = 1; t < BT; t++) {
      float au = 0.f;
      const float* Mr = &sM[t * 64];
      for (int s = 0; s < t; s++) au += Mr[s] * su[s * QS + d];
      su[t * QS + d] -= au;
    }
  }
  __syncthreads();
  for (int i = tid; i < 4096; i += 512) {
    int t = i >> 6, dd = (i & 63) * 4;
    *(float4*)(Wt + base + (size_t)t * DH + dd) = *(float4*)&sw[t * QS + dd];
    *(float4*)(Ut + base + (size_t)t * DH + dd) = *(float4*)&su[t * QS + dd];
  }
}

// -------------------- attn = tril(q k^T) (512 thr, f32x2) --------------------
#define ATTN_SMEM (2*64*QS*4)
__global__ __launch_bounds__(512) void attn_kernel(
    const float* __restrict__ qt, const float* __restrict__ kt, float* __restrict__ att)
{
  extern __shared__ float sh[];
  float* sq = sh;                // [64][260]
  float* sk = sq + 64 * QS;
  int blk = blockIdx.x;
  int c = blk % NC, bh = blk / NC;
  size_t base = ((size_t)bh * LL + (size_t)c * BT) * DH;
  int tid = threadIdx.x;
  for (int i = tid; i < 4096; i += 512) {
    int t = i >> 6, dd = (i & 63) * 4;
    *(float4*)&sq[t * QS + dd] = *(const float4*)(qt + base + (size_t)t * DH + dd);
    *(float4*)&sk[t * QS + dd] = *(const float4*)(kt + base + (size_t)t * DH + dd);
  }
  __syncthreads();
  float* ap = att + (size_t)blk * (BT * BT);
  for (int e = tid; e < BT * BT; e += 512) {
    int t = e >> 6, s = e & 63;
    float acc = 0.f;
    if (s <= t) {
      unsigned long long a0 = 0, a1 = 0;
      const float* q = &sq[t * QS];
      const float* k = &sk[s * QS];
#pragma unroll 4
      for (int d = 0; d < DH; d += 4) {
        ulonglong2 q2 = *(const ulonglong2*)(q + d);
        ulonglong2 k2 = *(const ulonglong2*)(k + d);
        fma2(a0, q2.x, k2.x);
        fma2(a1, q2.y, k2.y);
      }
      float x0, x1, x2, x3;
      unpack2(a0, x0, x1); unpack2(a1, x2, x3);
      acc = (x0 + x1) + (x2 + x3);
    }
    ap[e] = acc;
  }
}

// -------------------- sequential chunk scan (512 thr, f32x2, merged passes) ------
#define SCAN_SMEM ((256*SCS + 2*64*QS + 64*64 + 64*SCS) * 4)
__global__ __launch_bounds__(512) void scan_kernel(
    const float* __restrict__ qt, const float* __restrict__ kt,
    const float* __restrict__ wt, const float* __restrict__ ut,
    const float* __restrict__ att, float* __restrict__ og)
{
  extern __shared__ float sh[];
  float* S  = sh;                 // [256][36]
  float* Q  = S + 256 * SCS;      // [64][260]  q, then k
  float* W  = Q + 64 * QS;        // [64][260]
  float* T  = W + 64 * QS;        // [64][64]
  float* Un = T + 64 * 64;        // [64][36]
  int blk = blockIdx.x;
  int vb = blk & 7;
  int bh = blk >> 3;
  int b = bh / HH, h = bh % HH;
  int tid = threadIdx.x;
  int tx = tid & 7, t = tid >> 3;          // t = row 0..63, v0 = tx*4
  int v0 = tx * 4;
  int du = tid & 255, uh = tid >> 8;       // S-update: row du, v-half uh

  for (int i = tid; i < 256 * SCS; i += 512) S[i] = 0.f;
  __syncthreads();

  for (int c = 0; c < NC; c++) {
    size_t base = ((size_t)bh * LL + (size_t)c * BT) * DH;
    const float* ap = att + ((size_t)bh * NC + c) * (BT * BT);
    // stage q, w, att tiles (float4)
    for (int i = tid; i < 4096; i += 512) {
      int tt = i >> 6, dd = (i & 63) * 4;
      *(float4*)&Q[tt * QS + dd] = *(const float4*)(qt + base + (size_t)tt * DH + dd);
      *(float4*)&W[tt * QS + dd] = *(const float4*)(wt + base + (size_t)tt * DH + dd);
    }
    for (int i = tid; i < 1024; i += 512)
      *(float4*)&T[i * 4] = *(const float4*)(ap + i * 4);
    float4 u4 = *(const float4*)(ut + base + (size_t)t * DH + vb * 32 + v0);
    __syncthreads();

    // merged: ro = q@S, ao = w@S  (4 v per thread as 2 f32x2 pairs)
    unsigned long long ro0 = 0, ro1 = 0, ao0 = 0, ao1 = 0;
    {
      const float* qr = &Q[t * QS];
      const float* wr = &W[t * QS];
#pragma unroll 4
      for (int d = 0; d < DH; d++) {
        ulonglong2 s2 = *(const ulonglong2*)&S[d * SCS + v0];
        unsigned long long qq = pack2dup(qr[d]);
        unsigned long long ww = pack2dup(wr[d]);
        fma2(ro0, qq, s2.x); fma2(ro1, qq, s2.y);
        fma2(ao0, ww, s2.x); fma2(ao1, ww, s2.y);
      }
    }
    // u_new = u - w@S
    {
      float a0, a1, a2, a3;
      unpack2(ao0, a0, a1); unpack2(ao1, a2, a3);
      *(float4*)&Un[t * SCS + v0] = make_float4(u4.x - a0, u4.y - a1, u4.z - a2, u4.w - a3);
    }
    __syncthreads();

    // prefetch k into Q buffer (independent of attn pass below)
    for (int i = tid; i < 4096; i += 512) {
      int tt = i >> 6, dd = (i & 63) * 4;
      *(float4*)&Q[tt * QS + dd] = *(const float4*)(kt + base + (size_t)tt * DH + dd);
    }
    // o += attn @ u_new
    for (int s = 0; s <= t; s++) {
      unsigned long long aa = pack2dup(T[t * 64 + s]);
      ulonglong2 u2 = *(const ulonglong2*)&Un[s * SCS + v0];
      fma2(ro0, aa, u2.x); fma2(ro1, aa, u2.y);
    }
    {
      float o0, o1, o2, o3;
      unpack2(ro0, o0, o1); unpack2(ro1, o2, o3);
      size_t op = (((size_t)b * LL + (size_t)c * BT + t) * HH + h) * DH + vb * 32 + v0;
      *(float4*)&og[op] = make_float4(o0, o1, o2, o3);
    }
    __syncthreads();

    // S update: S[du][uh*16 .. +15] += sum_t k[t][du] * Un[t][uh*16 ..]
    {
      float* Sp = &S[du * SCS + uh * 16];
      ulonglong2 a0 = *(ulonglong2*)(Sp + 0);
      ulonglong2 a1 = *(ulonglong2*)(Sp + 4);
      ulonglong2 a2 = *(ulonglong2*)(Sp + 8);
      ulonglong2 a3 = *(ulonglong2*)(Sp + 12);
#pragma unroll 4
      for (int t2 = 0; t2 < BT; t2++) {
        unsigned long long kk = pack2dup(Q[t2 * QS + du]);
        const float* up = &Un[t2 * SCS + uh * 16];
        ulonglong2 u0 = *(const ulonglong2*)(up + 0);
        ulonglong2 u1 = *(const ulonglong2*)(up + 4);
        ulonglong2 u2 = *(const ulonglong2*)(up + 8);
        ulonglong2 u3 = *(const ulonglong2*)(up + 12);
        fma2(a0.x, kk, u0.x); fma2(a0.y, kk, u0.y);
        fma2(a1.x, kk, u1.x); fma2(a1.y, kk, u1.y);
        fma2(a2.x, kk, u2.x); fma2(a2.y, kk, u2.y);
        fma2(a3.x, kk, u3.x); fma2(a3.y, kk, u3.y);
      }
      *(ulonglong2*)(Sp + 0)  = a0;
      *(ulonglong2*)(Sp + 4)  = a1;
      *(ulonglong2*)(Sp + 8)  = a2;
      *(ulonglong2*)(Sp + 12) = a3;
    }
    __syncthreads();
  }
}

// -------------------- per-head RMSNorm * g_norm, warp-per-row --------------------
__global__ __launch_bounds__(256) void rms_kernel(
    const float* __restrict__ og, const float* __restrict__ gn, float* __restrict__ on)
{
  int w = threadIdx.x >> 5, lane = threadIdx.x & 31;
  size_t idx = (size_t)blockIdx.x * 8 + w;
  const float* ip = og + idx * DH;
  float v[8];
  float ss = 0.f;
#pragma unroll
  for (int j = 0; j < 8; j++) {
    v[j] = ip[lane + j * 32];
    ss += v[j] * v[j];
  }
#pragma unroll
  for (int o = 16; o; o >>= 1) ss += __shfl_xor_sync(0xffffffffu, ss, o);
  float scale = rsqrtf(ss * (1.f / DH) + 1e-5f);
  float* op = on + idx * DH;
#pragma unroll
  for (int j = 0; j < 8; j++) op[lane + j * 32] = v[j] * scale * gn[lane + j * 32];
}

// -------------------- host launch --------------------
extern "C" void kernel_launch(void* const* d_in, const int* in_sizes, int n_in,
                              void* d_out, int out_size)
{
  const float* hs = (const float*)d_in[0];
  const float* Wq = (const float*)d_in[1];
  const float* Wk = (const float*)d_in[2];
  const float* Wv = (const float*)d_in[3];
  const float* Wb = (const float*)d_in[4];
  const float* cq = (const float*)d_in[5];
  const float* ck = (const float*)d_in[6];
  const float* cv = (const float*)d_in[7];
  const float* gn = (const float*)d_in[8];
  const float* Wo = (const float*)d_in[9];
  float* out = (float*)d_out;

  float *preq, *prek, *prev, *qt, *kt, *vt, *wt, *ut, *beta, *att, *og, *on;
  __half *ah, *wh;
  cudaGetSymbolAddress((void**)&preq, g_preq);
  cudaGetSymbolAddress((void**)&prek, g_prek);
  cudaGetSymbolAddress((void**)&prev, g_prev);
  cudaGetSymbolAddress((void**)&qt, g_qt);
  cudaGetSymbolAddress((void**)&kt, g_kt);
  cudaGetSymbolAddress((void**)&vt, g_vt);
  cudaGetSymbolAddress((void**)&wt, g_wt);
  cudaGetSymbolAddress((void**)&ut, g_ut);
  cudaGetSymbolAddress((void**)&beta, g_beta);
  cudaGetSymbolAddress((void**)&att, g_att);
  cudaGetSymbolAddress((void**)&og, g_og);
  cudaGetSymbolAddress((void**)&on, g_on);
  cudaGetSymbolAddress((void**)&ah, g_ah);
  cudaGetSymbolAddress((void**)&wh, g_wh);

  cudaFuncSetAttribute(gemm_h_kernel, cudaFuncAttributeMaxDynamicSharedMemorySize, GEMM_SMEM);
  cudaFuncSetAttribute(solve_kernel, cudaFuncAttributeMaxDynamicSharedMemorySize, SOLVE_SMEM);
  cudaFuncSetAttribute(attn_kernel, cudaFuncAttributeMaxDynamicSharedMemorySize, ATTN_SMEM);
  cudaFuncSetAttribute(scan_kernel, cudaFuncAttributeMaxDynamicSharedMemorySize, SCAN_SMEM);

  dim3 gg(DDIM / 128, (BB * LL) / 128);
  const int actN4 = BLD / 4, wN4 = DD2 / 4;

  cvt_kernel<<<(actN4 + 255) / 256, 256>>>(hs, ah, actN4);
  cvt_kernel<<<(wN4 + 255) / 256, 256>>>(Wq, wh + 0 * (size_t)DD2, wN4);
  cvt_kernel<<<(wN4 + 255) / 256, 256>>>(Wk, wh + 1 * (size_t)DD2, wN4);
  gemm_h_kernel<<<gg, 256, GEMM_SMEM>>>(ah, wh + 0 * (size_t)DD2, preq, BB * LL, DDIM, DDIM);
  cvt_kernel<<<(wN4 + 255) / 256, 256>>>(Wv, wh + 2 * (size_t)DD2, wN4);
  cvt_kernel<<<(wN4 + 255) / 256, 256>>>(Wo, wh + 3 * (size_t)DD2, wN4);
  gemm_h_kernel<<<gg, 256, GEMM_SMEM>>>(ah, wh + 1 * (size_t)DD2, prek, BB * LL, DDIM, DDIM);
  gemm_h_kernel<<<gg, 256, GEMM_SMEM>>>(ah, wh + 2 * (size_t)DD2, prev, BB * LL, DDIM, DDIM);
  beta_kernel<<<BB * LL, 256>>>(hs, Wb, beta);

  conv_kernel<<<BB * HH * (LL / 8), 256>>>(preq, cq, qt, 0);
  conv_kernel<<<BB * HH * (LL / 8), 256>>>(prek, ck, kt, 1);
  conv_kernel<<<BB * HH * (LL / 8), 256>>>(prev, cv, vt, 2);

  solve_kernel<<<BB * HH * NC, 512, SOLVE_SMEM>>>(kt, vt, beta, wt, ut);
  attn_kernel<<<BB * HH * NC, 512, ATTN_SMEM>>>(qt, kt, att);
  scan_kernel<<<BB * HH * 8, 512, SCAN_SMEM>>>(qt, kt, wt, ut, att, og);

  rms_kernel<<<BB * LL * HH / 8, 256>>>(og, gn, on);
  cvt_kernel<<<(actN4 + 255) / 256, 256>>>(on, ah, actN4);
  gemm_h_kernel<<<gg, 256, GEMM_SMEM>>>(ah, wh + 3 * (size_t)DD2, out, BB * LL, DDIM, DDIM);
}

// round 8
// speedup vs baseline: 3.0014x; 1.0336x over previous
#include <cuda_runtime.h>
#include <cuda_fp16.h>
#include <math.h>
#include <stdint.h>

#define BB 2
#define LL 4096
#define DDIM 2048
#define HH 8
#define DH 256
#define BT 64
#define NC 64          // LL / BT
#define BLD (BB*LL*DDIM)
#define DD2 (DDIM*DDIM)
#define QS 260         // padded fp32 tile stride
#define SCS 36         // S / Un row stride

// -------------------- scratch (device globals; no allocation) --------------------
__device__ float g_preq[BLD];
__device__ float g_prek[BLD];
__device__ float g_prev[BLD];
__device__ float g_qt[BLD];
__device__ float g_kt[BLD];
__device__ float g_vt[BLD];
__device__ float g_wt[BLD];
__device__ float g_ut[BLD];
__device__ float g_beta[BB*HH*LL];
__device__ float g_att[(size_t)BB*HH*NC*BT*BT];
__device__ float g_og[BLD];
__device__ float g_on[BLD];
__device__ __align__(128) __half g_ah[BLD];
__device__ __align__(128) __half g_wh[4*DD2];

// -------------------- f32x2 packed helpers --------------------
__device__ __forceinline__ unsigned long long pack2dup(float x) {
  unsigned long long r;
  asm("mov.b64 %0, {%1,%1};" : "=l"(r) : "f"(x));
  return r;
}
__device__ __forceinline__ void unpack2(unsigned long long v, float& x, float& y) {
  asm("mov.b64 {%0,%1}, %2;" : "=f"(x), "=f"(y) : "l"(v));
}
__device__ __forceinline__ void fma2(unsigned long long& d,
                                     unsigned long long a, unsigned long long b) {
  asm("fma.rn.f32x2 %0, %1, %2, %0;" : "+l"(d) : "l"(a), "l"(b));
}

// ==================== convert fp32 -> fp16 ====================
__global__ __launch_bounds__(256) void cvt_kernel(
    const float* __restrict__ x, __half* __restrict__ h, int n4)
{
  int i = blockIdx.x * blockDim.x + threadIdx.x;
  if (i >= n4) return;
  float4 v = *(const float4*)(x + (size_t)i * 4);
  __half2* hp = (__half2*)(h + (size_t)i * 4);
  hp[0] = __floats2half2_rn(v.x, v.y);
  hp[1] = __floats2half2_rn(v.z, v.w);
}

// ==================== fp16 HMMA GEMM, BK=64, 3-stage cp.async ====================
#define GSTRIDE 72                      // halfs per row (64 data + 8 pad = 144B)
#define GTILE (128*GSTRIDE)             // 9216 halfs
#define ABYTES (GTILE*2)                // 18432 B
#define STAGEB (2*ABYTES)               // 36864 B (A+B)
#define NSTAGE 3
#define GEMM_SMEM (NSTAGE*STAGEB)       // 110592 B
#define BK 64

__device__ __forceinline__ void cpa16(uint32_t dst, const void* src) {
  asm volatile("cp.async.ca.shared.global [%0], [%1], 16;" :: "r"(dst), "l"(src));
}
#define CP_COMMIT() asm volatile("cp.async.commit_group;" ::: "memory")
#define CP_WAIT(n)  asm volatile("cp.async.wait_group %0;" :: "n"(n) : "memory")

__device__ __forceinline__ void ldsm4(uint32_t* r, uint32_t addr) {
  asm volatile("ldmatrix.sync.aligned.m8n8.x4.shared.b16 {%0,%1,%2,%3}, [%4];"
    : "=r"(r[0]), "=r"(r[1]), "=r"(r[2]), "=r"(r[3]) : "r"(addr));
}
__device__ __forceinline__ void mma16816(float* d, const uint32_t* a, uint32_t b0, uint32_t b1) {
  asm volatile("mma.sync.aligned.m16n8k16.row.col.f32.f16.f16.f32 "
    "{%0,%1,%2,%3}, {%4,%5,%6,%7}, {%8,%9}, {%0,%1,%2,%3};"
    : "+f"(d[0]), "+f"(d[1]), "+f"(d[2]), "+f"(d[3])
    : "r"(a[0]), "r"(a[1]), "r"(a[2]), "r"(a[3]), "r"(b0), "r"(b1));
}

__device__ __forceinline__ void load_stage_async(
    const __half* __restrict__ A, const __half* __restrict__ B,
    int bm, int bn, int K, int k0, uint32_t sb, int tid)
{
  const __half* srcs[2] = {A, B};
  const int rb[2] = {bm, bn};
#pragma unroll
  for (int a = 0; a < 2; a++) {
#pragma unroll
    for (int i = 0; i < 4; i++) {
      int idx = tid + i * 256;          // 0..1023
      int r = idx >> 3, ch = idx & 7;   // row, 16B chunk (8 per row)
      const __half* g = srcs[a] + (size_t)(rb[a] + r) * K + k0 + ch * 8;
      uint32_t dst = sb + a * ABYTES + (uint32_t)(r * 144 + ch * 16);
      cpa16(dst, g);
    }
  }
}

__global__ __launch_bounds__(256, 2) void gemm_h_kernel(
    const __half* __restrict__ A, const __half* __restrict__ B,
    float* __restrict__ C, int M, int N, int K)
{
  extern __shared__ char sm[];
  const int tid = threadIdx.x, lane = tid & 31, wid = tid >> 5;
  const int warp_m = wid >> 2, warp_n = wid & 3;
  const int bm = blockIdx.y * 128, bn = blockIdx.x * 128;
  const uint32_t sbase = (uint32_t)__cvta_generic_to_shared(sm);

  float acc[4][4][4];
#pragma unroll
  for (int i = 0; i < 4; i++)
#pragma unroll
    for (int j = 0; j < 4; j++)
#pragma unroll
      for (int e = 0; e < 4; e++) acc[i][j][e] = 0.f;

  const int NT = K / BK;                // 32
  load_stage_async(A, B, bm, bn, K, 0, sbase, tid);
  CP_COMMIT();
  load_stage_async(A, B, bm, bn, K, BK, sbase + STAGEB, tid);
  CP_COMMIT();

  const int arow  = warp_m * 64 + (lane & 15);
  const int acol0 = (lane >> 4) * 8;
  const int brow  = warp_n * 32 + (lane >> 4) * 8 + (lane & 7);
  const int bcol0 = ((lane >> 3) & 1) * 8;

  int s_cur = 0, s_nxt = 2;
  for (int kt = 0; kt < NT; kt++) {
    CP_WAIT(1);
    __syncthreads();
    {
      int knext = kt + 2;
      int kc = knext < NT ? knext : NT - 1;
      load_stage_async(A, B, bm, bn, K, kc * BK, sbase + s_nxt * STAGEB, tid);
      CP_COMMIT();
    }
    const uint32_t stb = sbase + s_cur * STAGEB;
    const uint32_t aoff = stb;
    const uint32_t boff = stb + ABYTES;
#pragma unroll
    for (int kk = 0; kk < BK; kk += 16) {
      uint32_t af[4][4], bf[2][4];
#pragma unroll
      for (int mt = 0; mt < 4; mt++) {
        uint32_t ab = (uint32_t)(((arow + mt * 16) * GSTRIDE + kk + acol0) * 2);
        ldsm4(af[mt], aoff + ab);
      }
#pragma unroll
      for (int p = 0; p < 2; p++) {
        uint32_t bb = (uint32_t)(((brow + p * 16) * GSTRIDE + kk + bcol0) * 2);
        ldsm4(bf[p], boff + bb);
      }
#pragma unroll
      for (int mt = 0; mt < 4; mt++)
#pragma unroll
        for (int nt = 0; nt < 4; nt++) {
          const uint32_t* bp = bf[nt >> 1];
          int bi = (nt & 1) * 2;
          mma16816(acc[mt][nt], af[mt], bp[bi], bp[bi + 1]);
        }
    }
    s_cur = s_cur == 2 ? 0 : s_cur + 1;
    s_nxt = s_nxt == 2 ? 0 : s_nxt + 1;
  }
  __syncthreads();
  const int row0 = bm + warp_m * 64 + (lane >> 2);
  const int col0 = bn + warp_n * 32 + (lane & 3) * 2;
#pragma unroll
  for (int mt = 0; mt < 4; mt++)
#pragma unroll
    for (int nt = 0; nt < 4; nt++) {
      int r = row0 + mt * 16;
      int c = col0 + nt * 8;
      *(float2*)(C + (size_t)r * N + c)       = make_float2(acc[mt][nt][0], acc[mt][nt][1]);
      *(float2*)(C + (size_t)(r + 8) * N + c) = make_float2(acc[mt][nt][2], acc[mt][nt][3]);
    }
}

// -------------------- beta = sigmoid(hs @ Wb^T), [B,H,L] --------------------
__global__ __launch_bounds__(256) void beta_kernel(
    const float* __restrict__ hs, const float* __restrict__ Wb, float* __restrict__ beta)
{
  int bl = blockIdx.x;
  int b = bl / LL, l = bl % LL;
  int w = threadIdx.x >> 5, lane = threadIdx.x & 31;
  const float* x = hs + (size_t)bl * DDIM;
  const float* wb = Wb + (size_t)w * DDIM;
  float s = 0.f;
  for (int d = lane; d < DDIM; d += 32) s += x[d] * wb[d];
#pragma unroll
  for (int o = 16; o; o >>= 1) s += __shfl_xor_sync(0xffffffffu, s, o);
  if (lane == 0)
    beta[((size_t)b * HH + w) * LL + l] = 1.f / (1.f + expf(-s));
}

// -------------------- conv + SiLU (+l2norm), warp-per-token, float4 --------------------
__global__ __launch_bounds__(256) void conv_kernel(
    const float* __restrict__ pre, const float* __restrict__ cw,
    float* __restrict__ out, int mode)
{
  int blk = blockIdx.x;
  int lt = blk & (LL / 8 - 1);
  int bh = blk >> 9;
  int h = bh % HH, b = bh / HH;
  int w = threadIdx.x >> 5, lane = threadIdx.x & 31;
  int l = lt * 8 + w;
  const float* base = pre + ((size_t)b * LL) * DDIM + h * DH;
  float y[2][4];
  float ss = 0.f;
  const float4 zero4 = make_float4(0, 0, 0, 0);
#pragma unroll
  for (int j = 0; j < 2; j++) {
    int dd = lane * 4 + j * 128;
    int c = h * DH + dd;
    float4 x0 = *(const float4*)(base + (size_t)l * DDIM + dd);
    float4 x1 = (l >= 1) ? *(const float4*)(base + (size_t)(l - 1) * DDIM + dd) : zero4;
    float4 x2 = (l >= 2) ? *(const float4*)(base + (size_t)(l - 2) * DDIM + dd) : zero4;
    float4 x3 = (l >= 3) ? *(const float4*)(base + (size_t)(l - 3) * DDIM + dd) : zero4;
    const float xs[4][4] = {{x0.x, x1.x, x2.x, x3.x}, {x0.y, x1.y, x2.y, x3.y},
                            {x0.z, x1.z, x2.z, x3.z}, {x0.w, x1.w, x2.w, x3.w}};
#pragma unroll
    for (int ci = 0; ci < 4; ci++) {
      float4 cv = *(const float4*)(cw + (size_t)(c + ci) * 4);
      float acc = xs[ci][0] * cv.w + xs[ci][1] * cv.z + xs[ci][2] * cv.y + xs[ci][3] * cv.x;
      float yy = acc / (1.f + expf(-acc));
      y[j][ci] = yy;
      ss += yy * yy;
    }
  }
  float scale = 1.f;
  if (mode < 2) {
#pragma unroll
    for (int o = 16; o; o >>= 1) ss += __shfl_xor_sync(0xffffffffu, ss, o);
    scale = rsqrtf(ss + 1e-6f);
    if (mode == 0) scale *= 0.0625f;
  }
  float* op = out + (((size_t)b * HH + h) * LL + l) * DH;
#pragma unroll
  for (int j = 0; j < 2; j++) {
    int dd = lane * 4 + j * 128;
    *(float4*)(op + dd) = make_float4(y[j][0] * scale, y[j][1] * scale,
                                      y[j][2] * scale, y[j][3] * scale);
  }
}

// -------------------- per-chunk triangular solve (tiled M pass) ----------------
#define SOLVE_SMEM ((3*64*QS + 64*64 + 64) * 4)
__global__ __launch_bounds__(512) void solve_kernel(
    const float* __restrict__ kt, const float* __restrict__ vt,
    const float* __restrict__ beta, float* __restrict__ Wt, float* __restrict__ Ut)
{
  extern __shared__ float sh[];
  float* sk = sh;                 // [64][260]
  float* sw = sk + 64 * QS;
  float* su = sw + 64 * QS;
  float* sM = su + 64 * QS;       // [64][64]
  float* sbeta = sM + 64 * 64;
  int blk = blockIdx.x;
  int c = blk % NC, bh = blk / NC;
  size_t base = ((size_t)bh * LL + (size_t)c * BT) * DH;
  int tid = threadIdx.x;

  if (tid < 64) sbeta[tid] = beta[(size_t)bh * LL + c * BT + tid];
  __syncthreads();
  for (int i = tid; i < 4096; i += 512) {
    int t = i >> 6, dd = (i & 63) * 4;
    float bt = sbeta[t];
    float4 kv = *(const float4*)(kt + base + (size_t)t * DH + dd);
    float4 vv = *(const float4*)(vt + base + (size_t)t * DH + dd);
    *(float4*)&sk[t * QS + dd] = kv;
    *(float4*)&sw[t * QS + dd] = make_float4(kv.x * bt, kv.y * bt, kv.z * bt, kv.w * bt);
    *(float4*)&su[t * QS + dd] = make_float4(vv.x * bt, vv.y * bt, vv.z * bt, vv.w * bt);
  }
  __syncthreads();
  // M = strict_lower(kb @ k^T), 2t x 4s register tile, strided s
  {
    int tp = tid >> 4, sb = tid & 15;
    int t0 = tp * 2, t1 = t0 + 1;
    unsigned long long acc[2][4];
#pragma unroll
    for (int ti = 0; ti < 2; ti++)
#pragma unroll
      for (int si = 0; si < 4; si++) acc[ti][si] = 0;
    if (sb < t1) {
      const float* q0 = &sw[t0 * QS];
      const float* q1 = &sw[t1 * QS];
#pragma unroll 2
      for (int d = 0; d < DH; d += 4) {
        ulonglong2 a0 = *(const ulonglong2*)(q0 + d);
        ulonglong2 a1 = *(const ulonglong2*)(q1 + d);
#pragma unroll
        for (int si = 0; si < 4; si++) {
          ulonglong2 kv = *(const ulonglong2*)(&sk[(sb + si * 16) * QS + d]);
          fma2(acc[0][si], a0.x, kv.x); fma2(acc[0][si], a0.y, kv.y);
          fma2(acc[1][si], a1.x, kv.x); fma2(acc[1][si], a1.y, kv.y);
        }
      }
    }
#pragma unroll
    for (int ti = 0; ti < 2; ti++)
#pragma unroll
      for (int si = 0; si < 4; si++) {
        int t = t0 + ti, s = sb + si * 16;
        float x0, x1;
        unpack2(acc[ti][si], x0, x1);
        sM[t * 64 + s] = (s < t) ? (x0 + x1) : 0.f;
      }
  }
  __syncthreads();
  // unit-lower forward substitution
  if (tid < 256) {
    int d = tid;
    for (int t = 1; t < BT; t++) {
      float aw = 0.f;
      const float* Mr = &sM[t * 64];
      for (int s = 0; s < t; s++) aw += Mr[s] * sw[s * QS + d];
      sw[t * QS + d] -= aw;
    }
  } else {
    int d = tid - 256;
    for (int t = 1; t < BT; t++) {
      float au = 0.f;
      const float* Mr = &sM[t * 64];
      for (int s = 0; s < t; s++) au += Mr[s] * su[s * QS + d];
      su[t * QS + d] -= au;
    }
  }
  __syncthreads();
  for (int i = tid; i < 4096; i += 512) {
    int t = i >> 6, dd = (i & 63) * 4;
    *(float4*)(Wt + base + (size_t)t * DH + dd) = *(float4*)&sw[t * QS + dd];
    *(float4*)(Ut + base + (size_t)t * DH + dd) = *(float4*)&su[t * QS + dd];
  }
}

// -------------------- attn = tril(q k^T), 2t x 4s register tile --------------------
#define ATTN_SMEM (2*64*QS*4)
__global__ __launch_bounds__(512) void attn_kernel(
    const float* __restrict__ qt, const float* __restrict__ kt, float* __restrict__ att)
{
  extern __shared__ float sh[];
  float* sq = sh;                // [64][260]
  float* sk = sq + 64 * QS;
  int blk = blockIdx.x;
  int c = blk % NC, bh = blk / NC;
  size_t base = ((size_t)bh * LL + (size_t)c * BT) * DH;
  int tid = threadIdx.x;
  for (int i = tid; i < 4096; i += 512) {
    int t = i >> 6, dd = (i & 63) * 4;
    *(float4*)&sq[t * QS + dd] = *(const float4*)(qt + base + (size_t)t * DH + dd);
    *(float4*)&sk[t * QS + dd] = *(const float4*)(kt + base + (size_t)t * DH + dd);
  }
  __syncthreads();
  float* ap = att + (size_t)blk * (BT * BT);
  int tp = tid >> 4, sb = tid & 15;
  int t0 = tp * 2, t1 = t0 + 1;
  unsigned long long acc[2][4];
#pragma unroll
  for (int ti = 0; ti < 2; ti++)
#pragma unroll
    for (int si = 0; si < 4; si++) acc[ti][si] = 0;
  if (sb <= t1) {
    const float* q0 = &sq[t0 * QS];
    const float* q1 = &sq[t1 * QS];
#pragma unroll 2
    for (int d = 0; d < DH; d += 4) {
      ulonglong2 a0 = *(const ulonglong2*)(q0 + d);
      ulonglong2 a1 = *(const ulonglong2*)(q1 + d);
#pragma unroll
      for (int si = 0; si < 4; si++) {
        ulonglong2 kv = *(const ulonglong2*)(&sk[(sb + si * 16) * QS + d]);
        fma2(acc[0][si], a0.x, kv.x); fma2(acc[0][si], a0.y, kv.y);
        fma2(acc[1][si], a1.x, kv.x); fma2(acc[1][si], a1.y, kv.y);
      }
    }
  }
#pragma unroll
  for (int ti = 0; ti < 2; ti++)
#pragma unroll
    for (int si = 0; si < 4; si++) {
      int t = t0 + ti, s = sb + si * 16;
      float x0, x1;
      unpack2(acc[ti][si], x0, x1);
      ap[t * 64 + s] = (s <= t) ? (x0 + x1) : 0.f;
    }
}

// -------------------- sequential chunk scan (512 thr, f32x2, merged passes) ------
#define SCAN_SMEM ((256*SCS + 2*64*QS + 64*64 + 64*SCS) * 4)
__global__ __launch_bounds__(512) void scan_kernel(
    const float* __restrict__ qt, const float* __restrict__ kt,
    const float* __restrict__ wt, const float* __restrict__ ut,
    const float* __restrict__ att, float* __restrict__ og)
{
  extern __shared__ float sh[];
  float* S  = sh;                 // [256][36]
  float* Q  = S + 256 * SCS;      // [64][260]  q, then k
  float* W  = Q + 64 * QS;        // [64][260]
  float* T  = W + 64 * QS;        // [64][64]
  float* Un = T + 64 * 64;        // [64][36]
  int blk = blockIdx.x;
  int vb = blk & 7;
  int bh = blk >> 3;
  int b = bh / HH, h = bh % HH;
  int tid = threadIdx.x;
  int tx = tid & 7, t = tid >> 3;
  int v0 = tx * 4;
  int du = tid & 255, uh = tid >> 8;

  for (int i = tid; i < 256 * SCS; i += 512) S[i] = 0.f;
  __syncthreads();

  for (int c = 0; c < NC; c++) {
    size_t base = ((size_t)bh * LL + (size_t)c * BT) * DH;
    const float* ap = att + ((size_t)bh * NC + c) * (BT * BT);
    for (int i = tid; i < 4096; i += 512) {
      int tt = i >> 6, dd = (i & 63) * 4;
      *(float4*)&Q[tt * QS + dd] = *(const float4*)(qt + base + (size_t)tt * DH + dd);
      *(float4*)&W[tt * QS + dd] = *(const float4*)(wt + base + (size_t)tt * DH + dd);
    }
    for (int i = tid; i < 1024; i += 512)
      *(float4*)&T[i * 4] = *(const float4*)(ap + i * 4);
    float4 u4 = *(const float4*)(ut + base + (size_t)t * DH + vb * 32 + v0);
    __syncthreads();

    // merged: ro = q@S, ao = w@S
    unsigned long long ro0 = 0, ro1 = 0, ao0 = 0, ao1 = 0;
    {
      const float* qr = &Q[t * QS];
      const float* wr = &W[t * QS];
#pragma unroll 2
      for (int d = 0; d < DH; d += 4) {
        float4 qv = *(const float4*)(qr + d);
        float4 wv = *(const float4*)(wr + d);
        {
          ulonglong2 s2 = *(const ulonglong2*)&S[(d + 0) * SCS + v0];
          unsigned long long qq = pack2dup(qv.x), ww = pack2dup(wv.x);
          fma2(ro0, qq, s2.x); fma2(ro1, qq, s2.y);
          fma2(ao0, ww, s2.x); fma2(ao1, ww, s2.y);
        }
        {
          ulonglong2 s2 = *(const ulonglong2*)&S[(d + 1) * SCS + v0];
          unsigned long long qq = pack2dup(qv.y), ww = pack2dup(wv.y);
          fma2(ro0, qq, s2.x); fma2(ro1, qq, s2.y);
          fma2(ao0, ww, s2.x); fma2(ao1, ww, s2.y);
        }
        {
          ulonglong2 s2 = *(const ulonglong2*)&S[(d + 2) * SCS + v0];
          unsigned long long qq = pack2dup(qv.z), ww = pack2dup(wv.z);
          fma2(ro0, qq, s2.x); fma2(ro1, qq, s2.y);
          fma2(ao0, ww, s2.x); fma2(ao1, ww, s2.y);
        }
        {
          ulonglong2 s2 = *(const ulonglong2*)&S[(d + 3) * SCS + v0];
          unsigned long long qq = pack2dup(qv.w), ww = pack2dup(wv.w);
          fma2(ro0, qq, s2.x); fma2(ro1, qq, s2.y);
          fma2(ao0, ww, s2.x); fma2(ao1, ww, s2.y);
        }
      }
    }
    {
      float a0, a1, a2, a3;
      unpack2(ao0, a0, a1); unpack2(ao1, a2, a3);
      *(float4*)&Un[t * SCS + v0] = make_float4(u4.x - a0, u4.y - a1, u4.z - a2, u4.w - a3);
    }
    __syncthreads();

    // prefetch k into Q buffer
    for (int i = tid; i < 4096; i += 512) {
      int tt = i >> 6, dd = (i & 63) * 4;
      *(float4*)&Q[tt * QS + dd] = *(const float4*)(kt + base + (size_t)tt * DH + dd);
    }
    // o += attn @ u_new
    for (int s = 0; s <= t; s++) {
      unsigned long long aa = pack2dup(T[t * 64 + s]);
      ulonglong2 u2 = *(const ulonglong2*)&Un[s * SCS + v0];
      fma2(ro0, aa, u2.x); fma2(ro1, aa, u2.y);
    }
    {
      float o0, o1, o2, o3;
      unpack2(ro0, o0, o1); unpack2(ro1, o2, o3);
      size_t op = (((size_t)b * LL + (size_t)c * BT + t) * HH + h) * DH + vb * 32 + v0;
      *(float4*)&og[op] = make_float4(o0, o1, o2, o3);
    }
    __syncthreads();

    // S update
    {
      float* Sp = &S[du * SCS + uh * 16];
      ulonglong2 a0 = *(ulonglong2*)(Sp + 0);
      ulonglong2 a1 = *(ulonglong2*)(Sp + 4);
      ulonglong2 a2 = *(ulonglong2*)(Sp + 8);
      ulonglong2 a3 = *(ulonglong2*)(Sp + 12);
#pragma unroll 4
      for (int t2 = 0; t2 < BT; t2++) {
        unsigned long long kk = pack2dup(Q[t2 * QS + du]);
        const float* up = &Un[t2 * SCS + uh * 16];
        ulonglong2 u0 = *(const ulonglong2*)(up + 0);
        ulonglong2 u1 = *(const ulonglong2*)(up + 4);
        ulonglong2 u2 = *(const ulonglong2*)(up + 8);
        ulonglong2 u3 = *(const ulonglong2*)(up + 12);
        fma2(a0.x, kk, u0.x); fma2(a0.y, kk, u0.y);
        fma2(a1.x, kk, u1.x); fma2(a1.y, kk, u1.y);
        fma2(a2.x, kk, u2.x); fma2(a2.y, kk, u2.y);
        fma2(a3.x, kk, u3.x); fma2(a3.y, kk, u3.y);
      }
      *(ulonglong2*)(Sp + 0)  = a0;
      *(ulonglong2*)(Sp + 4)  = a1;
      *(ulonglong2*)(Sp + 8)  = a2;
      *(ulonglong2*)(Sp + 12) = a3;
    }
    __syncthreads();
  }
}

// -------------------- per-head RMSNorm * g_norm, warp-per-row --------------------
__global__ __launch_bounds__(256) void rms_kernel(
    const float* __restrict__ og, const float* __restrict__ gn, float* __restrict__ on)
{
  int w = threadIdx.x >> 5, lane = threadIdx.x & 31;
  size_t idx = (size_t)blockIdx.x * 8 + w;
  const float* ip = og + idx * DH;
  float v[8];
  float ss = 0.f;
#pragma unroll
  for (int j = 0; j < 8; j++) {
    v[j] = ip[lane + j * 32];
    ss += v[j] * v[j];
  }
#pragma unroll
  for (int o = 16; o; o >>= 1) ss += __shfl_xor_sync(0xffffffffu, ss, o);
  float scale = rsqrtf(ss * (1.f / DH) + 1e-5f);
  float* op = on + idx * DH;
#pragma unroll
  for (int j = 0; j < 8; j++) op[lane + j * 32] = v[j] * scale * gn[lane + j * 32];
}

// -------------------- host launch --------------------
extern "C" void kernel_launch(void* const* d_in, const int* in_sizes, int n_in,
                              void* d_out, int out_size)
{
  const float* hs = (const float*)d_in[0];
  const float* Wq = (const float*)d_in[1];
  const float* Wk = (const float*)d_in[2];
  const float* Wv = (const float*)d_in[3];
  const float* Wb = (const float*)d_in[4];
  const float* cq = (const float*)d_in[5];
  const float* ck = (const float*)d_in[6];
  const float* cv = (const float*)d_in[7];
  const float* gn = (const float*)d_in[8];
  const float* Wo = (const float*)d_in[9];
  float* out = (float*)d_out;

  float *preq, *prek, *prev, *qt, *kt, *vt, *wt, *ut, *beta, *att, *og, *on;
  __half *ah, *wh;
  cudaGetSymbolAddress((void**)&preq, g_preq);
  cudaGetSymbolAddress((void**)&prek, g_prek);
  cudaGetSymbolAddress((void**)&prev, g_prev);
  cudaGetSymbolAddress((void**)&qt, g_qt);
  cudaGetSymbolAddress((void**)&kt, g_kt);
  cudaGetSymbolAddress((void**)&vt, g_vt);
  cudaGetSymbolAddress((void**)&wt, g_wt);
  cudaGetSymbolAddress((void**)&ut, g_ut);
  cudaGetSymbolAddress((void**)&beta, g_beta);
  cudaGetSymbolAddress((void**)&att, g_att);
  cudaGetSymbolAddress((void**)&og, g_og);
  cudaGetSymbolAddress((void**)&on, g_on);
  cudaGetSymbolAddress((void**)&ah, g_ah);
  cudaGetSymbolAddress((void**)&wh, g_wh);

  cudaFuncSetAttribute(gemm_h_kernel, cudaFuncAttributeMaxDynamicSharedMemorySize, GEMM_SMEM);
  cudaFuncSetAttribute(solve_kernel, cudaFuncAttributeMaxDynamicSharedMemorySize, SOLVE_SMEM);
  cudaFuncSetAttribute(attn_kernel, cudaFuncAttributeMaxDynamicSharedMemorySize, ATTN_SMEM);
  cudaFuncSetAttribute(scan_kernel, cudaFuncAttributeMaxDynamicSharedMemorySize, SCAN_SMEM);

  dim3 gg(DDIM / 128, (BB * LL) / 128);
  const int actN4 = BLD / 4, wN4 = DD2 / 4;

  cvt_kernel<<<(actN4 + 255) / 256, 256>>>(hs, ah, actN4);
  cvt_kernel<<<(wN4 + 255) / 256, 256>>>(Wq, wh + 0 * (size_t)DD2, wN4);
  cvt_kernel<<<(wN4 + 255) / 256, 256>>>(Wk, wh + 1 * (size_t)DD2, wN4);
  gemm_h_kernel<<<gg, 256, GEMM_SMEM>>>(ah, wh + 0 * (size_t)DD2, preq, BB * LL, DDIM, DDIM);
  cvt_kernel<<<(wN4 + 255) / 256, 256>>>(Wv, wh + 2 * (size_t)DD2, wN4);
  cvt_kernel<<<(wN4 + 255) / 256, 256>>>(Wo, wh + 3 * (size_t)DD2, wN4);
  gemm_h_kernel<<<gg, 256, GEMM_SMEM>>>(ah, wh + 1 * (size_t)DD2, prek, BB * LL, DDIM, DDIM);
  gemm_h_kernel<<<gg, 256, GEMM_SMEM>>>(ah, wh + 2 * (size_t)DD2, prev, BB * LL, DDIM, DDIM);
  beta_kernel<<<BB * LL, 256>>>(hs, Wb, beta);

  conv_kernel<<<BB * HH * (LL / 8), 256>>>(preq, cq, qt, 0);
  conv_kernel<<<BB * HH * (LL / 8), 256>>>(prek, ck, kt, 1);
  conv_kernel<<<BB * HH * (LL / 8), 256>>>(prev, cv, vt, 2);

  solve_kernel<<<BB * HH * NC, 512, SOLVE_SMEM>>>(kt, vt, beta, wt, ut);
  attn_kernel<<<BB * HH * NC, 512, ATTN_SMEM>>>(qt, kt, att);
  scan_kernel<<<BB * HH * 8, 512, SCAN_SMEM>>>(qt, kt, wt, ut, att, og);

  rms_kernel<<<BB * LL * HH / 8, 256>>>(og, gn, on);
  cvt_kernel<<<(actN4 + 255) / 256, 256>>>(on, ah, actN4);
  gemm_h_kernel<<<gg, 256, GEMM_SMEM>>>(ah, wh + 3 * (size_t)DD2, out, BB * LL, DDIM, DDIM);
}

// round 9
// speedup vs baseline: 3.3360x; 1.1115x over previous
#include <cuda_runtime.h>
#include <cuda_fp16.h>
#include <math.h>
#include <stdint.h>

#define BB 2
#define LL 4096
#define DDIM 2048
#define HH 8
#define DH 256
#define BT 64
#define NC 64          // LL / BT
#define BLD (BB*LL*DDIM)
#define DD2 (DDIM*DDIM)
#define QS 260         // padded fp32 tile stride
#define SCS 36         // S / Un row stride

// -------------------- scratch (device globals; no allocation) --------------------
__device__ float g_preq[BLD];
__device__ float g_prek[BLD];
__device__ float g_prev[BLD];
__device__ float g_qt[BLD];
__device__ float g_kt[BLD];
__device__ float g_vt[BLD];
__device__ float g_wt[BLD];
__device__ float g_ut[BLD];
__device__ float g_beta[BB*HH*LL];
__device__ float g_att[(size_t)BB*HH*NC*BT*BT];
__device__ float g_og[BLD];
__device__ float g_on[BLD];
__device__ __align__(128) __half g_ah[BLD];
__device__ __align__(128) __half g_wh[4*DD2];

// -------------------- f32x2 packed helpers --------------------
__device__ __forceinline__ unsigned long long pack2dup(float x) {
  unsigned long long r;
  asm("mov.b64 %0, {%1,%1};" : "=l"(r) : "f"(x));
  return r;
}
__device__ __forceinline__ void unpack2(unsigned long long v, float& x, float& y) {
  asm("mov.b64 {%0,%1}, %2;" : "=f"(x), "=f"(y) : "l"(v));
}
__device__ __forceinline__ void fma2(unsigned long long& d,
                                     unsigned long long a, unsigned long long b) {
  asm("fma.rn.f32x2 %0, %1, %2, %0;" : "+l"(d) : "l"(a), "l"(b));
}
__device__ __forceinline__ uint32_t h2(float x, float y) {
  __half2 h = __floats2half2_rn(x, y);
  return *(uint32_t*)&h;
}

// ==================== convert fp32 -> fp16 ====================
__global__ __launch_bounds__(256) void cvt_kernel(
    const float* __restrict__ x, __half* __restrict__ h, int n4)
{
  int i = blockIdx.x * blockDim.x + threadIdx.x;
  if (i >= n4) return;
  float4 v = *(const float4*)(x + (size_t)i * 4);
  __half2* hp = (__half2*)(h + (size_t)i * 4);
  hp[0] = __floats2half2_rn(v.x, v.y);
  hp[1] = __floats2half2_rn(v.z, v.w);
}

// ==================== fp16 HMMA GEMM, BK=32, 4-stage cp.async (R7 config) ====================
#define GSTRIDE 40
#define GTILE (128*GSTRIDE)
#define ABYTES (GTILE*2)
#define STAGEB (2*ABYTES)
#define NSTAGE 4
#define GEMM_SMEM (NSTAGE*STAGEB)

__device__ __forceinline__ void cpa16(uint32_t dst, const void* src) {
  asm volatile("cp.async.ca.shared.global [%0], [%1], 16;" :: "r"(dst), "l"(src));
}
#define CP_COMMIT() asm volatile("cp.async.commit_group;" ::: "memory")
#define CP_WAIT(n)  asm volatile("cp.async.wait_group %0;" :: "n"(n) : "memory")

__device__ __forceinline__ void ldsm4(uint32_t* r, uint32_t addr) {
  asm volatile("ldmatrix.sync.aligned.m8n8.x4.shared.b16 {%0,%1,%2,%3}, [%4];"
    : "=r"(r[0]), "=r"(r[1]), "=r"(r[2]), "=r"(r[3]) : "r"(addr));
}
__device__ __forceinline__ void mma16816(float* d, const uint32_t* a, uint32_t b0, uint32_t b1) {
  asm volatile("mma.sync.aligned.m16n8k16.row.col.f32.f16.f16.f32 "
    "{%0,%1,%2,%3}, {%4,%5,%6,%7}, {%8,%9}, {%0,%1,%2,%3};"
    : "+f"(d[0]), "+f"(d[1]), "+f"(d[2]), "+f"(d[3])
    : "r"(a[0]), "r"(a[1]), "r"(a[2]), "r"(a[3]), "r"(b0), "r"(b1));
}

__device__ __forceinline__ void load_stage_async(
    const __half* __restrict__ A, const __half* __restrict__ B,
    int bm, int bn, int K, int k0, uint32_t sb, int tid)
{
  const __half* srcs[2] = {A, B};
  const int rb[2] = {bm, bn};
#pragma unroll
  for (int a = 0; a < 2; a++) {
#pragma unroll
    for (int i = 0; i < 2; i++) {
      int idx = tid + i * 256;
      int r = idx >> 2, ch = idx & 3;
      const __half* g = srcs[a] + (size_t)(rb[a] + r) * K + k0 + ch * 8;
      uint32_t dst = sb + a * ABYTES + (uint32_t)(r * 80 + ch * 16);
      cpa16(dst, g);
    }
  }
}

__global__ __launch_bounds__(256, 2) void gemm_h_kernel(
    const __half* __restrict__ A, const __half* __restrict__ B,
    float* __restrict__ C, int M, int N, int K)
{
  extern __shared__ char sm[];
  const int tid = threadIdx.x, lane = tid & 31, wid = tid >> 5;
  const int warp_m = wid >> 2, warp_n = wid & 3;
  const int bm = blockIdx.y * 128, bn = blockIdx.x * 128;
  const uint32_t sbase = (uint32_t)__cvta_generic_to_shared(sm);

  float acc[4][4][4];
#pragma unroll
  for (int i = 0; i < 4; i++)
#pragma unroll
    for (int j = 0; j < 4; j++)
#pragma unroll
      for (int e = 0; e < 4; e++) acc[i][j][e] = 0.f;

  const int NT = K / 32;
#pragma unroll
  for (int p = 0; p < NSTAGE - 1; p++) {
    load_stage_async(A, B, bm, bn, K, p * 32, sbase + p * STAGEB, tid);
    CP_COMMIT();
  }

  const int arow  = warp_m * 64 + (lane & 15);
  const int acol0 = (lane >> 4) * 8;
  const int brow  = warp_n * 32 + (lane >> 4) * 8 + (lane & 7);
  const int bcol0 = ((lane >> 3) & 1) * 8;

  for (int kt = 0; kt < NT; kt++) {
    CP_WAIT(NSTAGE - 2);
    __syncthreads();
    {
      int knext = kt + NSTAGE - 1;
      int kc = knext < NT ? knext : NT - 1;
      load_stage_async(A, B, bm, bn, K, kc * 32, sbase + (knext & (NSTAGE - 1)) * STAGEB, tid);
      CP_COMMIT();
    }
    const uint32_t stb = sbase + (kt & (NSTAGE - 1)) * STAGEB;
    const uint32_t aoff = stb;
    const uint32_t boff = stb + ABYTES;
#pragma unroll
    for (int kk = 0; kk < 32; kk += 16) {
      uint32_t af[4][4], bf[2][4];
#pragma unroll
      for (int mt = 0; mt < 4; mt++) {
        uint32_t ab = (uint32_t)(((arow + mt * 16) * GSTRIDE + kk + acol0) * 2);
        ldsm4(af[mt], aoff + ab);
      }
#pragma unroll
      for (int p = 0; p < 2; p++) {
        uint32_t bb = (uint32_t)(((brow + p * 16) * GSTRIDE + kk + bcol0) * 2);
        ldsm4(bf[p], boff + bb);
      }
#pragma unroll
      for (int mt = 0; mt < 4; mt++)
#pragma unroll
        for (int nt = 0; nt < 4; nt++) {
          const uint32_t* bp = bf[nt >> 1];
          int bi = (nt & 1) * 2;
          mma16816(acc[mt][nt], af[mt], bp[bi], bp[bi + 1]);
        }
    }
  }
  __syncthreads();
  const int row0 = bm + warp_m * 64 + (lane >> 2);
  const int col0 = bn + warp_n * 32 + (lane & 3) * 2;
#pragma unroll
  for (int mt = 0; mt < 4; mt++)
#pragma unroll
    for (int nt = 0; nt < 4; nt++) {
      int r = row0 + mt * 16;
      int c = col0 + nt * 8;
      *(float2*)(C + (size_t)r * N + c)       = make_float2(acc[mt][nt][0], acc[mt][nt][1]);
      *(float2*)(C + (size_t)(r + 8) * N + c) = make_float2(acc[mt][nt][2], acc[mt][nt][3]);
    }
}

// -------------------- beta = sigmoid(hs @ Wb^T), [B,H,L] --------------------
__global__ __launch_bounds__(256) void beta_kernel(
    const float* __restrict__ hs, const float* __restrict__ Wb, float* __restrict__ beta)
{
  int bl = blockIdx.x;
  int b = bl / LL, l = bl % LL;
  int w = threadIdx.x >> 5, lane = threadIdx.x & 31;
  const float* x = hs + (size_t)bl * DDIM;
  const float* wb = Wb + (size_t)w * DDIM;
  float s = 0.f;
  for (int d = lane; d < DDIM; d += 32) s += x[d] * wb[d];
#pragma unroll
  for (int o = 16; o; o >>= 1) s += __shfl_xor_sync(0xffffffffu, s, o);
  if (lane == 0)
    beta[((size_t)b * HH + w) * LL + l] = 1.f / (1.f + expf(-s));
}

// -------------------- conv + SiLU (+l2norm), warp-per-token, float4 --------------------
__global__ __launch_bounds__(256) void conv_kernel(
    const float* __restrict__ pre, const float* __restrict__ cw,
    float* __restrict__ out, int mode)
{
  int blk = blockIdx.x;
  int lt = blk & (LL / 8 - 1);
  int bh = blk >> 9;
  int h = bh % HH, b = bh / HH;
  int w = threadIdx.x >> 5, lane = threadIdx.x & 31;
  int l = lt * 8 + w;
  const float* base = pre + ((size_t)b * LL) * DDIM + h * DH;
  float y[2][4];
  float ss = 0.f;
  const float4 zero4 = make_float4(0, 0, 0, 0);
#pragma unroll
  for (int j = 0; j < 2; j++) {
    int dd = lane * 4 + j * 128;
    int c = h * DH + dd;
    float4 x0 = *(const float4*)(base + (size_t)l * DDIM + dd);
    float4 x1 = (l >= 1) ? *(const float4*)(base + (size_t)(l - 1) * DDIM + dd) : zero4;
    float4 x2 = (l >= 2) ? *(const float4*)(base + (size_t)(l - 2) * DDIM + dd) : zero4;
    float4 x3 = (l >= 3) ? *(const float4*)(base + (size_t)(l - 3) * DDIM + dd) : zero4;
    const float xs[4][4] = {{x0.x, x1.x, x2.x, x3.x}, {x0.y, x1.y, x2.y, x3.y},
                            {x0.z, x1.z, x2.z, x3.z}, {x0.w, x1.w, x2.w, x3.w}};
#pragma unroll
    for (int ci = 0; ci < 4; ci++) {
      float4 cv = *(const float4*)(cw + (size_t)(c + ci) * 4);
      float acc = xs[ci][0] * cv.w + xs[ci][1] * cv.z + xs[ci][2] * cv.y + xs[ci][3] * cv.x;
      float yy = acc / (1.f + expf(-acc));
      y[j][ci] = yy;
      ss += yy * yy;
    }
  }
  float scale = 1.f;
  if (mode < 2) {
#pragma unroll
    for (int o = 16; o; o >>= 1) ss += __shfl_xor_sync(0xffffffffu, ss, o);
    scale = rsqrtf(ss + 1e-6f);
    if (mode == 0) scale *= 0.0625f;
  }
  float* op = out + (((size_t)b * HH + h) * LL + l) * DH;
#pragma unroll
  for (int j = 0; j < 2; j++) {
    int dd = lane * 4 + j * 128;
    *(float4*)(op + dd) = make_float4(y[j][0] * scale, y[j][1] * scale,
                                      y[j][2] * scale, y[j][3] * scale);
  }
}

// -------------------- per-chunk triangular solve (tiled M, f32x2 substitution) ------
#define SOLVE_SMEM ((3*64*QS + 64*64 + 64) * 4)
__global__ __launch_bounds__(512) void solve_kernel(
    const float* __restrict__ kt, const float* __restrict__ vt,
    const float* __restrict__ beta, float* __restrict__ Wt, float* __restrict__ Ut)
{
  extern __shared__ float sh[];
  float* sk = sh;                 // [64][260]
  float* sw = sk + 64 * QS;
  float* su = sw + 64 * QS;
  float* sM = su + 64 * QS;       // [64][64]
  float* sbeta = sM + 64 * 64;
  int blk = blockIdx.x;
  int c = blk % NC, bh = blk / NC;
  size_t base = ((size_t)bh * LL + (size_t)c * BT) * DH;
  int tid = threadIdx.x;

  if (tid < 64) sbeta[tid] = beta[(size_t)bh * LL + c * BT + tid];
  __syncthreads();
  for (int i = tid; i < 4096; i += 512) {
    int t = i >> 6, dd = (i & 63) * 4;
    float bt = sbeta[t];
    float4 kv = *(const float4*)(kt + base + (size_t)t * DH + dd);
    float4 vv = *(const float4*)(vt + base + (size_t)t * DH + dd);
    *(float4*)&sk[t * QS + dd] = kv;
    *(float4*)&sw[t * QS + dd] = make_float4(kv.x * bt, kv.y * bt, kv.z * bt, kv.w * bt);
    *(float4*)&su[t * QS + dd] = make_float4(vv.x * bt, vv.y * bt, vv.z * bt, vv.w * bt);
  }
  __syncthreads();
  // M = strict_lower(kb @ k^T), 2t x 4s register tile, strided s
  {
    int tp = tid >> 4, sb = tid & 15;
    int t0 = tp * 2, t1 = t0 + 1;
    unsigned long long acc[2][4];
#pragma unroll
    for (int ti = 0; ti < 2; ti++)
#pragma unroll
      for (int si = 0; si < 4; si++) acc[ti][si] = 0;
    if (sb < t1) {
      const float* q0 = &sw[t0 * QS];
      const float* q1 = &sw[t1 * QS];
#pragma unroll 2
      for (int d = 0; d < DH; d += 4) {
        ulonglong2 a0 = *(const ulonglong2*)(q0 + d);
        ulonglong2 a1 = *(const ulonglong2*)(q1 + d);
#pragma unroll
        for (int si = 0; si < 4; si++) {
          ulonglong2 kv = *(const ulonglong2*)(&sk[(sb + si * 16) * QS + d]);
          fma2(acc[0][si], a0.x, kv.x); fma2(acc[0][si], a0.y, kv.y);
          fma2(acc[1][si], a1.x, kv.x); fma2(acc[1][si], a1.y, kv.y);
        }
      }
    }
#pragma unroll
    for (int ti = 0; ti < 2; ti++)
#pragma unroll
      for (int si = 0; si < 4; si++) {
        int t = t0 + ti, s = sb + si * 16;
        float x0, x1;
        unpack2(acc[ti][si], x0, x1);
        sM[t * 64 + s] = (s < t) ? (x0 + x1) : 0.f;
      }
  }
  __syncthreads();
  // unit-lower forward substitution, f32x2 column pairs
  if (tid < 128) {
    int d = tid * 2;
    for (int t = 1; t < BT; t++) {
      unsigned long long acc = 0;
      const float* Mr = &sM[t * 64];
      for (int s = 0; s < t; s++)
        fma2(acc, pack2dup(Mr[s]), *(const unsigned long long*)&sw[s * QS + d]);
      float a0, a1;
      unpack2(acc, a0, a1);
      sw[t * QS + d]     -= a0;
      sw[t * QS + d + 1] -= a1;
    }
  } else if (tid < 256) {
    int d = (tid - 128) * 2;
    for (int t = 1; t < BT; t++) {
      unsigned long long acc = 0;
      const float* Mr = &sM[t * 64];
      for (int s = 0; s < t; s++)
        fma2(acc, pack2dup(Mr[s]), *(const unsigned long long*)&su[s * QS + d]);
      float a0, a1;
      unpack2(acc, a0, a1);
      su[t * QS + d]     -= a0;
      su[t * QS + d + 1] -= a1;
    }
  }
  __syncthreads();
  for (int i = tid; i < 4096; i += 512) {
    int t = i >> 6, dd = (i & 63) * 4;
    *(float4*)(Wt + base + (size_t)t * DH + dd) = *(float4*)&sw[t * QS + dd];
    *(float4*)(Ut + base + (size_t)t * DH + dd) = *(float4*)&su[t * QS + dd];
  }
}

// -------------------- attn = tril(q k^T), 2t x 4s register tile --------------------
#define ATTN_SMEM (2*64*QS*4)
__global__ __launch_bounds__(512) void attn_kernel(
    const float* __restrict__ qt, const float* __restrict__ kt, float* __restrict__ att)
{
  extern __shared__ float sh[];
  float* sq = sh;                // [64][260]
  float* sk = sq + 64 * QS;
  int blk = blockIdx.x;
  int c = blk % NC, bh = blk / NC;
  size_t base = ((size_t)bh * LL + (size_t)c * BT) * DH;
  int tid = threadIdx.x;
  for (int i = tid; i < 4096; i += 512) {
    int t = i >> 6, dd = (i & 63) * 4;
    *(float4*)&sq[t * QS + dd] = *(const float4*)(qt + base + (size_t)t * DH + dd);
    *(float4*)&sk[t * QS + dd] = *(const float4*)(kt + base + (size_t)t * DH + dd);
  }
  __syncthreads();
  float* ap = att + (size_t)blk * (BT * BT);
  int tp = tid >> 4, sb = tid & 15;
  int t0 = tp * 2, t1 = t0 + 1;
  unsigned long long acc[2][4];
#pragma unroll
  for (int ti = 0; ti < 2; ti++)
#pragma unroll
    for (int si = 0; si < 4; si++) acc[ti][si] = 0;
  if (sb <= t1) {
    const float* q0 = &sq[t0 * QS];
    const float* q1 = &sq[t1 * QS];
#pragma unroll 2
    for (int d = 0; d < DH; d += 4) {
      ulonglong2 a0 = *(const ulonglong2*)(q0 + d);
      ulonglong2 a1 = *(const ulonglong2*)(q1 + d);
#pragma unroll
      for (int si = 0; si < 4; si++) {
        ulonglong2 kv = *(const ulonglong2*)(&sk[(sb + si * 16) * QS + d]);
        fma2(acc[0][si], a0.x, kv.x); fma2(acc[0][si], a0.y, kv.y);
        fma2(acc[1][si], a1.x, kv.x); fma2(acc[1][si], a1.y, kv.y);
      }
    }
  }
#pragma unroll
  for (int ti = 0; ti < 2; ti++)
#pragma unroll
    for (int si = 0; si < 4; si++) {
      int t = t0 + ti, s = sb + si * 16;
      float x0, x1;
      unpack2(acc[ti][si], x0, x1);
      ap[t * 64 + s] = (s <= t) ? (x0 + x1) : 0.f;
    }
}

// -------------------- sequential chunk scan: f32x2 merged pass + MMA S-update ------
#define SCAN_SMEM ((256*SCS + 2*64*QS + 64*64 + 64*SCS) * 4)
__global__ __launch_bounds__(512) void scan_kernel(
    const float* __restrict__ qt, const float* __restrict__ kt,
    const float* __restrict__ wt, const float* __restrict__ ut,
    const float* __restrict__ att, float* __restrict__ og)
{
  extern __shared__ float sh[];
  float* S  = sh;                 // [256][36]
  float* Q  = S + 256 * SCS;      // [64][260]  q, then k
  float* W  = Q + 64 * QS;        // [64][260]
  float* T  = W + 64 * QS;        // [64][64]
  float* Un = T + 64 * 64;        // [64][36]
  int blk = blockIdx.x;
  int vb = blk & 7;
  int bh = blk >> 3;
  int b = bh / HH, h = bh % HH;
  int tid = threadIdx.x;
  int lane = tid & 31, wrp = tid >> 5;
  int tx = tid & 7, t = tid >> 3;
  int v0 = tx * 4;
  // MMA S-update mapping
  int fr = lane >> 2;             // fragment row 0..7
  int fc = (lane & 3) * 2;        // fragment col (even)
  int dw = wrp * 16;              // this warp's d-row base

  for (int i = tid; i < 256 * SCS; i += 512) S[i] = 0.f;
  __syncthreads();

  for (int c = 0; c < NC; c++) {
    size_t base = ((size_t)bh * LL + (size_t)c * BT) * DH;
    const float* ap = att + ((size_t)bh * NC + c) * (BT * BT);
    for (int i = tid; i < 4096; i += 512) {
      int tt = i >> 6, dd = (i & 63) * 4;
      *(float4*)&Q[tt * QS + dd] = *(const float4*)(qt + base + (size_t)tt * DH + dd);
      *(float4*)&W[tt * QS + dd] = *(const float4*)(wt + base + (size_t)tt * DH + dd);
    }
    for (int i = tid; i < 1024; i += 512)
      *(float4*)&T[i * 4] = *(const float4*)(ap + i * 4);
    float4 u4 = *(const float4*)(ut + base + (size_t)t * DH + vb * 32 + v0);
    __syncthreads();

    // merged: ro = q@S, ao = w@S (fp32 f32x2)
    unsigned long long ro0 = 0, ro1 = 0, ao0 = 0, ao1 = 0;
    {
      const float* qr = &Q[t * QS];
      const float* wr = &W[t * QS];
#pragma unroll 2
      for (int d = 0; d < DH; d += 4) {
        float4 qv = *(const float4*)(qr + d);
        float4 wv = *(const float4*)(wr + d);
        {
          ulonglong2 s2 = *(const ulonglong2*)&S[(d + 0) * SCS + v0];
          unsigned long long qq = pack2dup(qv.x), ww = pack2dup(wv.x);
          fma2(ro0, qq, s2.x); fma2(ro1, qq, s2.y);
          fma2(ao0, ww, s2.x); fma2(ao1, ww, s2.y);
        }
        {
          ulonglong2 s2 = *(const ulonglong2*)&S[(d + 1) * SCS + v0];
          unsigned long long qq = pack2dup(qv.y), ww = pack2dup(wv.y);
          fma2(ro0, qq, s2.x); fma2(ro1, qq, s2.y);
          fma2(ao0, ww, s2.x); fma2(ao1, ww, s2.y);
        }
        {
          ulonglong2 s2 = *(const ulonglong2*)&S[(d + 2) * SCS + v0];
          unsigned long long qq = pack2dup(qv.z), ww = pack2dup(wv.z);
          fma2(ro0, qq, s2.x); fma2(ro1, qq, s2.y);
          fma2(ao0, ww, s2.x); fma2(ao1, ww, s2.y);
        }
        {
          ulonglong2 s2 = *(const ulonglong2*)&S[(d + 3) * SCS + v0];
          unsigned long long qq = pack2dup(qv.w), ww = pack2dup(wv.w);
          fma2(ro0, qq, s2.x); fma2(ro1, qq, s2.y);
          fma2(ao0, ww, s2.x); fma2(ao1, ww, s2.y);
        }
      }
    }
    {
      float a0, a1, a2, a3;
      unpack2(ao0, a0, a1); unpack2(ao1, a2, a3);
      *(float4*)&Un[t * SCS + v0] = make_float4(u4.x - a0, u4.y - a1, u4.z - a2, u4.w - a3);
    }
    __syncthreads();

    // prefetch k into Q buffer
    for (int i = tid; i < 4096; i += 512) {
      int tt = i >> 6, dd = (i & 63) * 4;
      *(float4*)&Q[tt * QS + dd] = *(const float4*)(kt + base + (size_t)tt * DH + dd);
    }
    // o += attn @ u_new (fp32)
    for (int s = 0; s <= t; s++) {
      unsigned long long aa = pack2dup(T[t * 64 + s]);
      ulonglong2 u2 = *(const ulonglong2*)&Un[s * SCS + v0];
      fma2(ro0, aa, u2.x); fma2(ro1, aa, u2.y);
    }
    {
      float o0, o1, o2, o3;
      unpack2(ro0, o0, o1); unpack2(ro1, o2, o3);
      size_t op = (((size_t)b * LL + (size_t)c * BT + t) * HH + h) * DH + vb * 32 + v0;
      *(float4*)&og[op] = make_float4(o0, o1, o2, o3);
    }
    __syncthreads();

    // S update via fp16 MMA (fp32 accumulate): dS = k^T @ u_new
    // warp owns d-rows [dw, dw+16), v cols 0..31 (4 n-tiles of 8)
    {
      float sacc[4][4];
#pragma unroll
      for (int vt = 0; vt < 4; vt++)
#pragma unroll
        for (int e = 0; e < 4; e++) sacc[vt][e] = 0.f;
#pragma unroll
      for (int kk = 0; kk < BT; kk += 16) {
        // A = k^T tile [16 d x 16 t]; A[r][c] = k[kk+c][dw+r] from Q (fp32)
        const float* k0 = &Q[(kk + fc) * QS + dw];
        const float* k1 = &Q[(kk + fc + 1) * QS + dw];
        const float* k8 = &Q[(kk + fc + 8) * QS + dw];
        const float* k9 = &Q[(kk + fc + 9) * QS + dw];
        uint32_t a[4];
        a[0] = h2(k0[fr],     k1[fr]);
        a[1] = h2(k0[fr + 8], k1[fr + 8]);
        a[2] = h2(k8[fr],     k9[fr]);
        a[3] = h2(k8[fr + 8], k9[fr + 8]);
        const float* un0 = &Un[(kk + fc) * SCS];
        const float* un1 = &Un[(kk + fc + 1) * SCS];
        const float* un8 = &Un[(kk + fc + 8) * SCS];
        const float* un9 = &Un[(kk + fc + 9) * SCS];
#pragma unroll
        for (int vt = 0; vt < 4; vt++) {
          uint32_t b0 = h2(un0[vt * 8 + fr], un1[vt * 8 + fr]);
          uint32_t b1 = h2(un8[vt * 8 + fr], un9[vt * 8 + fr]);
          mma16816(sacc[vt], a, b0, b1);
        }
      }
#pragma unroll
      for (int vt = 0; vt < 4; vt++) {
        float2* sp0 = (float2*)&S[(dw + fr) * SCS + vt * 8 + fc];
        float2 v0r = *sp0;
        v0r.x += sacc[vt][0]; v0r.y += sacc[vt][1];
        *sp0 = v0r;
        float2* sp1 = (float2*)&S[(dw + fr + 8) * SCS + vt * 8 + fc];
        float2 v1r = *sp1;
        v1r.x += sacc[vt][2]; v1r.y += sacc[vt][3];
        *sp1 = v1r;
      }
    }
    __syncthreads();
  }
}

// -------------------- per-head RMSNorm * g_norm, warp-per-row --------------------
__global__ __launch_bounds__(256) void rms_kernel(
    const float* __restrict__ og, const float* __restrict__ gn, float* __restrict__ on)
{
  int w = threadIdx.x >> 5, lane = threadIdx.x & 31;
  size_t idx = (size_t)blockIdx.x * 8 + w;
  const float* ip = og + idx * DH;
  float v[8];
  float ss = 0.f;
#pragma unroll
  for (int j = 0; j < 8; j++) {
    v[j] = ip[lane + j * 32];
    ss += v[j] * v[j];
  }
#pragma unroll
  for (int o = 16; o; o >>= 1) ss += __shfl_xor_sync(0xffffffffu, ss, o);
  float scale = rsqrtf(ss * (1.f / DH) + 1e-5f);
  float* op = on + idx * DH;
#pragma unroll
  for (int j = 0; j < 8; j++) op[lane + j * 32] = v[j] * scale * gn[lane + j * 32];
}

// -------------------- host launch --------------------
extern "C" void kernel_launch(void* const* d_in, const int* in_sizes, int n_in,
                              void* d_out, int out_size)
{
  const float* hs = (const float*)d_in[0];
  const float* Wq = (const float*)d_in[1];
  const float* Wk = (const float*)d_in[2];
  const float* Wv = (const float*)d_in[3];
  const float* Wb = (const float*)d_in[4];
  const float* cq = (const float*)d_in[5];
  const float* ck = (const float*)d_in[6];
  const float* cv = (const float*)d_in[7];
  const float* gn = (const float*)d_in[8];
  const float* Wo = (const float*)d_in[9];
  float* out = (float*)d_out;

  float *preq, *prek, *prev, *qt, *kt, *vt, *wt, *ut, *beta, *att, *og, *on;
  __half *ah, *wh;
  cudaGetSymbolAddress((void**)&preq, g_preq);
  cudaGetSymbolAddress((void**)&prek, g_prek);
  cudaGetSymbolAddress((void**)&prev, g_prev);
  cudaGetSymbolAddress((void**)&qt, g_qt);
  cudaGetSymbolAddress((void**)&kt, g_kt);
  cudaGetSymbolAddress((void**)&vt, g_vt);
  cudaGetSymbolAddress((void**)&wt, g_wt);
  cudaGetSymbolAddress((void**)&ut, g_ut);
  cudaGetSymbolAddress((void**)&beta, g_beta);
  cudaGetSymbolAddress((void**)&att, g_att);
  cudaGetSymbolAddress((void**)&og, g_og);
  cudaGetSymbolAddress((void**)&on, g_on);
  cudaGetSymbolAddress((void**)&ah, g_ah);
  cudaGetSymbolAddress((void**)&wh, g_wh);

  cudaFuncSetAttribute(gemm_h_kernel, cudaFuncAttributeMaxDynamicSharedMemorySize, GEMM_SMEM);
  cudaFuncSetAttribute(solve_kernel, cudaFuncAttributeMaxDynamicSharedMemorySize, SOLVE_SMEM);
  cudaFuncSetAttribute(attn_kernel, cudaFuncAttributeMaxDynamicSharedMemorySize, ATTN_SMEM);
  cudaFuncSetAttribute(scan_kernel, cudaFuncAttributeMaxDynamicSharedMemorySize, SCAN_SMEM);

  dim3 gg(DDIM / 128, (BB * LL) / 128);
  const int actN4 = BLD / 4, wN4 = DD2 / 4;

  cvt_kernel<<<(actN4 + 255) / 256, 256>>>(hs, ah, actN4);
  cvt_kernel<<<(wN4 + 255) / 256, 256>>>(Wq, wh + 0 * (size_t)DD2, wN4);
  cvt_kernel<<<(wN4 + 255) / 256, 256>>>(Wk, wh + 1 * (size_t)DD2, wN4);
  gemm_h_kernel<<<gg, 256, GEMM_SMEM>>>(ah, wh + 0 * (size_t)DD2, preq, BB * LL, DDIM, DDIM);
  cvt_kernel<<<(wN4 + 255) / 256, 256>>>(Wv, wh + 2 * (size_t)DD2, wN4);
  cvt_kernel<<<(wN4 + 255) / 256, 256>>>(Wo, wh + 3 * (size_t)DD2, wN4);
  gemm_h_kernel<<<gg, 256, GEMM_SMEM>>>(ah, wh + 1 * (size_t)DD2, prek, BB * LL, DDIM, DDIM);
  gemm_h_kernel<<<gg, 256, GEMM_SMEM>>>(ah, wh + 2 * (size_t)DD2, prev, BB * LL, DDIM, DDIM);
  beta_kernel<<<BB * LL, 256>>>(hs, Wb, beta);

  conv_kernel<<<BB * HH * (LL / 8), 256>>>(preq, cq, qt, 0);
  conv_kernel<<<BB * HH * (LL / 8), 256>>>(prek, ck, kt, 1);
  conv_kernel<<<BB * HH * (LL / 8), 256>>>(prev, cv, vt, 2);

  solve_kernel<<<BB * HH * NC, 512, SOLVE_SMEM>>>(kt, vt, beta, wt, ut);
  attn_kernel<<<BB * HH * NC, 512, ATTN_SMEM>>>(qt, kt, att);
  scan_kernel<<<BB * HH * 8, 512, SCAN_SMEM>>>(qt, kt, wt, ut, att, og);

  rms_kernel<<<BB * LL * HH / 8, 256>>>(og, gn, on);
  cvt_kernel<<<(actN4 + 255) / 256, 256>>>(on, ah, actN4);
  gemm_h_kernel<<<gg, 256, GEMM_SMEM>>>(ah, wh + 3 * (size_t)DD2, out, BB * LL, DDIM, DDIM);
}

// round 10
// speedup vs baseline: 3.9060x; 1.1709x over previous
#include <cuda_runtime.h>
#include <cuda_fp16.h>
#include <math.h>
#include <stdint.h>

#define BB 2
#define LL 4096
#define DDIM 2048
#define HH 8
#define DH 256
#define BT 64
#define NC 64          // LL / BT
#define BLD (BB*LL*DDIM)
#define DD2 (DDIM*DDIM)
#define QS 260         // padded fp32 tile stride
#define SCS 36         // S / Un / P row stride

// -------------------- scratch (device globals; no allocation) --------------------
__device__ float g_preq[BLD];
__device__ float g_prek[BLD];
__device__ float g_prev[BLD];
__device__ float g_qt[BLD];
__device__ float g_kt[BLD];
__device__ float g_vt[BLD];
__device__ float g_wt[BLD];
__device__ float g_ut[BLD];
__device__ float g_beta[BB*HH*LL];
__device__ float g_att[(size_t)BB*HH*NC*BT*BT];
__device__ float g_og[BLD];
__device__ float g_on[BLD];
__device__ __align__(128) __half g_ah[BLD];
__device__ __align__(128) __half g_wh[4*DD2];

// -------------------- f32x2 packed helpers --------------------
__device__ __forceinline__ unsigned long long pack2dup(float x) {
  unsigned long long r;
  asm("mov.b64 %0, {%1,%1};" : "=l"(r) : "f"(x));
  return r;
}
__device__ __forceinline__ void unpack2(unsigned long long v, float& x, float& y) {
  asm("mov.b64 {%0,%1}, %2;" : "=f"(x), "=f"(y) : "l"(v));
}
__device__ __forceinline__ void fma2(unsigned long long& d,
                                     unsigned long long a, unsigned long long b) {
  asm("fma.rn.f32x2 %0, %1, %2, %0;" : "+l"(d) : "l"(a), "l"(b));
}
__device__ __forceinline__ uint32_t h2(float x, float y) {
  __half2 h = __floats2half2_rn(x, y);
  return *(uint32_t*)&h;
}

// ==================== convert fp32 -> fp16 ====================
__global__ __launch_bounds__(256) void cvt_kernel(
    const float* __restrict__ x, __half* __restrict__ h, int n4)
{
  int i = blockIdx.x * blockDim.x + threadIdx.x;
  if (i >= n4) return;
  float4 v = *(const float4*)(x + (size_t)i * 4);
  __half2* hp = (__half2*)(h + (size_t)i * 4);
  hp[0] = __floats2half2_rn(v.x, v.y);
  hp[1] = __floats2half2_rn(v.z, v.w);
}

// ==================== fp16 HMMA GEMM, BK=32, 4-stage cp.async ====================
#define GSTRIDE 40
#define GTILE (128*GSTRIDE)
#define ABYTES (GTILE*2)
#define STAGEB (2*ABYTES)
#define NSTAGE 4
#define GEMM_SMEM (NSTAGE*STAGEB)

__device__ __forceinline__ void cpa16(uint32_t dst, const void* src) {
  asm volatile("cp.async.ca.shared.global [%0], [%1], 16;" :: "r"(dst), "l"(src));
}
#define CP_COMMIT() asm volatile("cp.async.commit_group;" ::: "memory")
#define CP_WAIT(n)  asm volatile("cp.async.wait_group %0;" :: "n"(n) : "memory")

__device__ __forceinline__ void ldsm4(uint32_t* r, uint32_t addr) {
  asm volatile("ldmatrix.sync.aligned.m8n8.x4.shared.b16 {%0,%1,%2,%3}, [%4];"
    : "=r"(r[0]), "=r"(r[1]), "=r"(r[2]), "=r"(r[3]) : "r"(addr));
}
__device__ __forceinline__ void mma16816(float* d, const uint32_t* a, uint32_t b0, uint32_t b1) {
  asm volatile("mma.sync.aligned.m16n8k16.row.col.f32.f16.f16.f32 "
    "{%0,%1,%2,%3}, {%4,%5,%6,%7}, {%8,%9}, {%0,%1,%2,%3};"
    : "+f"(d[0]), "+f"(d[1]), "+f"(d[2]), "+f"(d[3])
    : "r"(a[0]), "r"(a[1]), "r"(a[2]), "r"(a[3]), "r"(b0), "r"(b1));
}

__device__ __forceinline__ void load_stage_async(
    const __half* __restrict__ A, const __half* __restrict__ B,
    int bm, int bn, int K, int k0, uint32_t sb, int tid)
{
  const __half* srcs[2] = {A, B};
  const int rb[2] = {bm, bn};
#pragma unroll
  for (int a = 0; a < 2; a++) {
#pragma unroll
    for (int i = 0; i < 2; i++) {
      int idx = tid + i * 256;
      int r = idx >> 2, ch = idx & 3;
      const __half* g = srcs[a] + (size_t)(rb[a] + r) * K + k0 + ch * 8;
      uint32_t dst = sb + a * ABYTES + (uint32_t)(r * 80 + ch * 16);
      cpa16(dst, g);
    }
  }
}

__global__ __launch_bounds__(256, 2) void gemm_h_kernel(
    const __half* __restrict__ A, const __half* __restrict__ B,
    float* __restrict__ C, int M, int N, int K)
{
  extern __shared__ char sm[];
  const int tid = threadIdx.x, lane = tid & 31, wid = tid >> 5;
  const int warp_m = wid >> 2, warp_n = wid & 3;
  const int bm = blockIdx.y * 128, bn = blockIdx.x * 128;
  const uint32_t sbase = (uint32_t)__cvta_generic_to_shared(sm);

  float acc[4][4][4];
#pragma unroll
  for (int i = 0; i < 4; i++)
#pragma unroll
    for (int j = 0; j < 4; j++)
#pragma unroll
      for (int e = 0; e < 4; e++) acc[i][j][e] = 0.f;

  const int NT = K / 32;
#pragma unroll
  for (int p = 0; p < NSTAGE - 1; p++) {
    load_stage_async(A, B, bm, bn, K, p * 32, sbase + p * STAGEB, tid);
    CP_COMMIT();
  }

  const int arow  = warp_m * 64 + (lane & 15);
  const int acol0 = (lane >> 4) * 8;
  const int brow  = warp_n * 32 + (lane >> 4) * 8 + (lane & 7);
  const int bcol0 = ((lane >> 3) & 1) * 8;

  for (int kt = 0; kt < NT; kt++) {
    CP_WAIT(NSTAGE - 2);
    __syncthreads();
    {
      int knext = kt + NSTAGE - 1;
      int kc = knext < NT ? knext : NT - 1;
      load_stage_async(A, B, bm, bn, K, kc * 32, sbase + (knext & (NSTAGE - 1)) * STAGEB, tid);
      CP_COMMIT();
    }
    const uint32_t stb = sbase + (kt & (NSTAGE - 1)) * STAGEB;
    const uint32_t aoff = stb;
    const uint32_t boff = stb + ABYTES;
#pragma unroll
    for (int kk = 0; kk < 32; kk += 16) {
      uint32_t af[4][4], bf[2][4];
#pragma unroll
      for (int mt = 0; mt < 4; mt++) {
        uint32_t ab = (uint32_t)(((arow + mt * 16) * GSTRIDE + kk + acol0) * 2);
        ldsm4(af[mt], aoff + ab);
      }
#pragma unroll
      for (int p = 0; p < 2; p++) {
        uint32_t bb = (uint32_t)(((brow + p * 16) * GSTRIDE + kk + bcol0) * 2);
        ldsm4(bf[p], boff + bb);
      }
#pragma unroll
      for (int mt = 0; mt < 4; mt++)
#pragma unroll
        for (int nt = 0; nt < 4; nt++) {
          const uint32_t* bp = bf[nt >> 1];
          int bi = (nt & 1) * 2;
          mma16816(acc[mt][nt], af[mt], bp[bi], bp[bi + 1]);
        }
    }
  }
  __syncthreads();
  const int row0 = bm + warp_m * 64 + (lane >> 2);
  const int col0 = bn + warp_n * 32 + (lane & 3) * 2;
#pragma unroll
  for (int mt = 0; mt < 4; mt++)
#pragma unroll
    for (int nt = 0; nt < 4; nt++) {
      int r = row0 + mt * 16;
      int c = col0 + nt * 8;
      *(float2*)(C + (size_t)r * N + c)       = make_float2(acc[mt][nt][0], acc[mt][nt][1]);
      *(float2*)(C + (size_t)(r + 8) * N + c) = make_float2(acc[mt][nt][2], acc[mt][nt][3]);
    }
}

// -------------------- beta = sigmoid(hs @ Wb^T), [B,H,L] --------------------
__global__ __launch_bounds__(256) void beta_kernel(
    const float* __restrict__ hs, const float* __restrict__ Wb, float* __restrict__ beta)
{
  int bl = blockIdx.x;
  int b = bl / LL, l = bl % LL;
  int w = threadIdx.x >> 5, lane = threadIdx.x & 31;
  const float* x = hs + (size_t)bl * DDIM;
  const float* wb = Wb + (size_t)w * DDIM;
  float s = 0.f;
  for (int d = lane; d < DDIM; d += 32) s += x[d] * wb[d];
#pragma unroll
  for (int o = 16; o; o >>= 1) s += __shfl_xor_sync(0xffffffffu, s, o);
  if (lane == 0)
    beta[((size_t)b * HH + w) * LL + l] = 1.f / (1.f + expf(-s));
}

// -------------------- conv + SiLU (+l2norm), warp-per-token, float4 --------------------
__global__ __launch_bounds__(256) void conv_kernel(
    const float* __restrict__ pre, const float* __restrict__ cw,
    float* __restrict__ out, int mode)
{
  int blk = blockIdx.x;
  int lt = blk & (LL / 8 - 1);
  int bh = blk >> 9;
  int h = bh % HH, b = bh / HH;
  int w = threadIdx.x >> 5, lane = threadIdx.x & 31;
  int l = lt * 8 + w;
  const float* base = pre + ((size_t)b * LL) * DDIM + h * DH;
  float y[2][4];
  float ss = 0.f;
  const float4 zero4 = make_float4(0, 0, 0, 0);
#pragma unroll
  for (int j = 0; j < 2; j++) {
    int dd = lane * 4 + j * 128;
    int c = h * DH + dd;
    float4 x0 = *(const float4*)(base + (size_t)l * DDIM + dd);
    float4 x1 = (l >= 1) ? *(const float4*)(base + (size_t)(l - 1) * DDIM + dd) : zero4;
    float4 x2 = (l >= 2) ? *(const float4*)(base + (size_t)(l - 2) * DDIM + dd) : zero4;
    float4 x3 = (l >= 3) ? *(const float4*)(base + (size_t)(l - 3) * DDIM + dd) : zero4;
    const float xs[4][4] = {{x0.x, x1.x, x2.x, x3.x}, {x0.y, x1.y, x2.y, x3.y},
                            {x0.z, x1.z, x2.z, x3.z}, {x0.w, x1.w, x2.w, x3.w}};
#pragma unroll
    for (int ci = 0; ci < 4; ci++) {
      float4 cv = *(const float4*)(cw + (size_t)(c + ci) * 4);
      float acc = xs[ci][0] * cv.w + xs[ci][1] * cv.z + xs[ci][2] * cv.y + xs[ci][3] * cv.x;
      float yy = acc / (1.f + expf(-acc));
      y[j][ci] = yy;
      ss += yy * yy;
    }
  }
  float scale = 1.f;
  if (mode < 2) {
#pragma unroll
    for (int o = 16; o; o >>= 1) ss += __shfl_xor_sync(0xffffffffu, ss, o);
    scale = rsqrtf(ss + 1e-6f);
    if (mode == 0) scale *= 0.0625f;
  }
  float* op = out + (((size_t)b * HH + h) * LL + l) * DH;
#pragma unroll
  for (int j = 0; j < 2; j++) {
    int dd = lane * 4 + j * 128;
    *(float4*)(op + dd) = make_float4(y[j][0] * scale, y[j][1] * scale,
                                      y[j][2] * scale, y[j][3] * scale);
  }
}

// -------------------- per-chunk triangular solve (tiled M, f32x2 substitution) ------
#define SOLVE_SMEM ((3*64*QS + 64*64 + 64) * 4)
__global__ __launch_bounds__(512) void solve_kernel(
    const float* __restrict__ kt, const float* __restrict__ vt,
    const float* __restrict__ beta, float* __restrict__ Wt, float* __restrict__ Ut)
{
  extern __shared__ float sh[];
  float* sk = sh;                 // [64][260]
  float* sw = sk + 64 * QS;
  float* su = sw + 64 * QS;
  float* sM = su + 64 * QS;       // [64][64]
  float* sbeta = sM + 64 * 64;
  int blk = blockIdx.x;
  int c = blk % NC, bh = blk / NC;
  size_t base = ((size_t)bh * LL + (size_t)c * BT) * DH;
  int tid = threadIdx.x;

  if (tid < 64) sbeta[tid] = beta[(size_t)bh * LL + c * BT + tid];
  __syncthreads();
  for (int i = tid; i < 4096; i += 512) {
    int t = i >> 6, dd = (i & 63) * 4;
    float bt = sbeta[t];
    float4 kv = *(const float4*)(kt + base + (size_t)t * DH + dd);
    float4 vv = *(const float4*)(vt + base + (size_t)t * DH + dd);
    *(float4*)&sk[t * QS + dd] = kv;
    *(float4*)&sw[t * QS + dd] = make_float4(kv.x * bt, kv.y * bt, kv.z * bt, kv.w * bt);
    *(float4*)&su[t * QS + dd] = make_float4(vv.x * bt, vv.y * bt, vv.z * bt, vv.w * bt);
  }
  __syncthreads();
  {
    int tp = tid >> 4, sb = tid & 15;
    int t0 = tp * 2, t1 = t0 + 1;
    unsigned long long acc[2][4];
#pragma unroll
    for (int ti = 0; ti < 2; ti++)
#pragma unroll
      for (int si = 0; si < 4; si++) acc[ti][si] = 0;
    if (sb < t1) {
      const float* q0 = &sw[t0 * QS];
      const float* q1 = &sw[t1 * QS];
#pragma unroll 2
      for (int d = 0; d < DH; d += 4) {
        ulonglong2 a0 = *(const ulonglong2*)(q0 + d);
        ulonglong2 a1 = *(const ulonglong2*)(q1 + d);
#pragma unroll
        for (int si = 0; si < 4; si++) {
          ulonglong2 kv = *(const ulonglong2*)(&sk[(sb + si * 16) * QS + d]);
          fma2(acc[0][si], a0.x, kv.x); fma2(acc[0][si], a0.y, kv.y);
          fma2(acc[1][si], a1.x, kv.x); fma2(acc[1][si], a1.y, kv.y);
        }
      }
    }
#pragma unroll
    for (int ti = 0; ti < 2; ti++)
#pragma unroll
      for (int si = 0; si < 4; si++) {
        int t = t0 + ti, s = sb + si * 16;
        float x0, x1;
        unpack2(acc[ti][si], x0, x1);
        sM[t * 64 + s] = (s < t) ? (x0 + x1) : 0.f;
      }
  }
  __syncthreads();
  if (tid < 128) {
    int d = tid * 2;
    for (int t = 1; t < BT; t++) {
      unsigned long long acc = 0;
      const float* Mr = &sM[t * 64];
      for (int s = 0; s < t; s++)
        fma2(acc, pack2dup(Mr[s]), *(const unsigned long long*)&sw[s * QS + d]);
      float a0, a1;
      unpack2(acc, a0, a1);
      sw[t * QS + d]     -= a0;
      sw[t * QS + d + 1] -= a1;
    }
  } else if (tid < 256) {
    int d = (tid - 128) * 2;
    for (int t = 1; t < BT; t++) {
      unsigned long long acc = 0;
      const float* Mr = &sM[t * 64];
      for (int s = 0; s < t; s++)
        fma2(acc, pack2dup(Mr[s]), *(const unsigned long long*)&su[s * QS + d]);
      float a0, a1;
      unpack2(acc, a0, a1);
      su[t * QS + d]     -= a0;
      su[t * QS + d + 1] -= a1;
    }
  }
  __syncthreads();
  for (int i = tid; i < 4096; i += 512) {
    int t = i >> 6, dd = (i & 63) * 4;
    *(float4*)(Wt + base + (size_t)t * DH + dd) = *(float4*)&sw[t * QS + dd];
    *(float4*)(Ut + base + (size_t)t * DH + dd) = *(float4*)&su[t * QS + dd];
  }
}

// -------------------- attn = tril(q k^T), 2t x 4s register tile --------------------
#define ATTN_SMEM (2*64*QS*4)
__global__ __launch_bounds__(512) void attn_kernel(
    const float* __restrict__ qt, const float* __restrict__ kt, float* __restrict__ att)
{
  extern __shared__ float sh[];
  float* sq = sh;
  float* sk = sq + 64 * QS;
  int blk = blockIdx.x;
  int c = blk % NC, bh = blk / NC;
  size_t base = ((size_t)bh * LL + (size_t)c * BT) * DH;
  int tid = threadIdx.x;
  for (int i = tid; i < 4096; i += 512) {
    int t = i >> 6, dd = (i & 63) * 4;
    *(float4*)&sq[t * QS + dd] = *(const float4*)(qt + base + (size_t)t * DH + dd);
    *(float4*)&sk[t * QS + dd] = *(const float4*)(kt + base + (size_t)t * DH + dd);
  }
  __syncthreads();
  float* ap = att + (size_t)blk * (BT * BT);
  int tp = tid >> 4, sb = tid & 15;
  int t0 = tp * 2, t1 = t0 + 1;
  unsigned long long acc[2][4];
#pragma unroll
  for (int ti = 0; ti < 2; ti++)
#pragma unroll
    for (int si = 0; si < 4; si++) acc[ti][si] = 0;
  if (sb <= t1) {
    const float* q0 = &sq[t0 * QS];
    const float* q1 = &sq[t1 * QS];
#pragma unroll 2
    for (int d = 0; d < DH; d += 4) {
      ulonglong2 a0 = *(const ulonglong2*)(q0 + d);
      ulonglong2 a1 = *(const ulonglong2*)(q1 + d);
#pragma unroll
      for (int si = 0; si < 4; si++) {
        ulonglong2 kv = *(const ulonglong2*)(&sk[(sb + si * 16) * QS + d]);
        fma2(acc[0][si], a0.x, kv.x); fma2(acc[0][si], a0.y, kv.y);
        fma2(acc[1][si], a1.x, kv.x); fma2(acc[1][si], a1.y, kv.y);
      }
    }
  }
#pragma unroll
  for (int ti = 0; ti < 2; ti++)
#pragma unroll
    for (int si = 0; si < 4; si++) {
      int t = t0 + ti, s = sb + si * 16;
      float x0, x1;
      unpack2(acc[ti][si], x0, x1);
      ap[t * 64 + s] = (s <= t) ? (x0 + x1) : 0.f;
    }
}

// -------------------- scan: MMA merged q@S/w@S + MMA S-update --------------------
// smem: S[256][36], Q[64][260], W[64][260], T[64][64], Un[64][36], P[2][64][36]
#define SCAN_SMEM ((256*SCS + 2*64*QS + 64*64 + 64*SCS + 2*64*SCS) * 4)
__global__ __launch_bounds__(512) void scan_kernel(
    const float* __restrict__ qt, const float* __restrict__ kt,
    const float* __restrict__ wt, const float* __restrict__ ut,
    const float* __restrict__ att, float* __restrict__ og)
{
  extern __shared__ float sh[];
  float* S  = sh;                 // [256][36]
  float* Q  = S + 256 * SCS;      // [64][260]  q, then k
  float* W  = Q + 64 * QS;        // [64][260]
  float* T  = W + 64 * QS;        // [64][64]
  float* Un = T + 64 * 64;        // [64][36]
  float* P  = Un + 64 * SCS;      // [2][64][36] partials/finals
  int blk = blockIdx.x;
  int vb = blk & 7;
  int bh = blk >> 3;
  int b = bh / HH, h = bh % HH;
  int tid = threadIdx.x;
  int lane = tid & 31, wrp = tid >> 5;
  int tx = tid & 7, t = tid >> 3;
  int v0 = tx * 4;
  int fr = lane >> 2;             // fragment row
  int fc = (lane & 3) * 2;        // fragment col (even)
  int dw = wrp * 16;              // S-update d-row base
  // merged-pass warp mapping
  int which = wrp >> 3;           // 0: q@S, 1: w@S
  int sub = wrp & 7;
  int ttile = sub & 3;            // t base = ttile*16
  int khalf = sub >> 2;           // K half (128 d each)
  int tb = ttile * 16;
  // prefetch thread index for khalf==1 warps (8 warps -> 0..255)
  int pidx = (((wrp >> 3) << 2) | (wrp & 3)) * 32 + lane;

  for (int i = tid; i < 256 * SCS; i += 512) S[i] = 0.f;
  __syncthreads();

  for (int c = 0; c < NC; c++) {
    size_t base = ((size_t)bh * LL + (size_t)c * BT) * DH;
    const float* ap = att + ((size_t)bh * NC + c) * (BT * BT);
    // stage q, w, att tiles
    for (int i = tid; i < 4096; i += 512) {
      int tt = i >> 6, dd = (i & 63) * 4;
      *(float4*)&Q[tt * QS + dd] = *(const float4*)(qt + base + (size_t)tt * DH + dd);
      *(float4*)&W[tt * QS + dd] = *(const float4*)(wt + base + (size_t)tt * DH + dd);
    }
    for (int i = tid; i < 1024; i += 512)
      *(float4*)&T[i * 4] = *(const float4*)(ap + i * 4);
    __syncthreads();

    // ---- Phase A: fp16 MMA partials of q@S (which=0) and w@S (which=1) ----
    float acc[4][4];
#pragma unroll
    for (int vt = 0; vt < 4; vt++)
#pragma unroll
      for (int e = 0; e < 4; e++) acc[vt][e] = 0.f;
    {
      const float* Ab = which ? W : Q;
      const float* ar0 = Ab + (tb + fr) * QS;
      const float* ar1 = Ab + (tb + fr + 8) * QS;
      int k0 = khalf * 128;
#pragma unroll
      for (int kk = k0; kk < k0 + 128; kk += 16) {
        float2 f00 = *(const float2*)(ar0 + kk + fc);
        float2 f01 = *(const float2*)(ar0 + kk + fc + 8);
        float2 f10 = *(const float2*)(ar1 + kk + fc);
        float2 f11 = *(const float2*)(ar1 + kk + fc + 8);
        uint32_t a[4];
        a[0] = h2(f00.x, f00.y);
        a[1] = h2(f10.x, f10.y);
        a[2] = h2(f01.x, f01.y);
        a[3] = h2(f11.x, f11.y);
        const float* s0 = &S[(kk + fc) * SCS];
        const float* s1 = &S[(kk + fc + 1) * SCS];
        const float* s8 = &S[(kk + fc + 8) * SCS];
        const float* s9 = &S[(kk + fc + 9) * SCS];
#pragma unroll
        for (int vt = 0; vt < 4; vt++) {
          int vn = vt * 8 + fr;
          uint32_t b0 = h2(s0[vn], s1[vn]);
          uint32_t b1 = h2(s8[vn], s9[vn]);
          mma16816(acc[vt], a, b0, b1);
        }
      }
    }
    float* Pp = &P[which * 64 * SCS + tb * SCS];
    if (khalf == 1) {
#pragma unroll
      for (int vt = 0; vt < 4; vt++) {
        *(float2*)&Pp[fr * SCS + vt * 8 + fc]       = make_float2(acc[vt][0], acc[vt][1]);
        *(float2*)&Pp[(fr + 8) * SCS + vt * 8 + fc] = make_float2(acc[vt][2], acc[vt][3]);
      }
    }
    __syncthreads();

    // ---- Phase B: khalf0 combine; khalf1 prefetch k into Q ----
    if (khalf == 0) {
      if (which == 0) {
        // final q@S -> P[0] as [64][36]
#pragma unroll
        for (int vt = 0; vt < 4; vt++) {
          float2 p0 = *(float2*)&Pp[fr * SCS + vt * 8 + fc];
          float2 p1 = *(float2*)&Pp[(fr + 8) * SCS + vt * 8 + fc];
          *(float2*)&Pp[fr * SCS + vt * 8 + fc] =
              make_float2(acc[vt][0] + p0.x, acc[vt][1] + p0.y);
          *(float2*)&Pp[(fr + 8) * SCS + vt * 8 + fc] =
              make_float2(acc[vt][2] + p1.x, acc[vt][3] + p1.y);
        }
      } else {
        // Un = u - w@S
        size_t ub0 = base + (size_t)(tb + fr) * DH + vb * 32;
        size_t ub1 = base + (size_t)(tb + fr + 8) * DH + vb * 32;
#pragma unroll
        for (int vt = 0; vt < 4; vt++) {
          float2 p0 = *(float2*)&Pp[fr * SCS + vt * 8 + fc];
          float2 p1 = *(float2*)&Pp[(fr + 8) * SCS + vt * 8 + fc];
          float2 u0 = *(const float2*)(ut + ub0 + vt * 8 + fc);
          float2 u1 = *(const float2*)(ut + ub1 + vt * 8 + fc);
          *(float2*)&Un[(tb + fr) * SCS + vt * 8 + fc] =
              make_float2(u0.x - (acc[vt][0] + p0.x), u0.y - (acc[vt][1] + p0.y));
          *(float2*)&Un[(tb + fr + 8) * SCS + vt * 8 + fc] =
              make_float2(u1.x - (acc[vt][2] + p1.x), u1.y - (acc[vt][3] + p1.y));
        }
      }
    } else {
      // prefetch k into Q (8 warps, 256 threads)
      for (int i = pidx; i < 1024; i += 256) {
        int tt = i >> 4, dd = (i & 15) * 16;
        *(float4*)&Q[tt * QS + dd]      = *(const float4*)(kt + base + (size_t)tt * DH + dd);
        *(float4*)&Q[tt * QS + dd + 4]  = *(const float4*)(kt + base + (size_t)tt * DH + dd + 4);
        *(float4*)&Q[tt * QS + dd + 8]  = *(const float4*)(kt + base + (size_t)tt * DH + dd + 8);
        *(float4*)&Q[tt * QS + dd + 12] = *(const float4*)(kt + base + (size_t)tt * DH + dd + 12);
      }
    }
    __syncthreads();

    // ---- Phase C: o = q@S + attn @ u_new (per-thread t, v0) ----
    {
      ulonglong2 ro2 = *(const ulonglong2*)&P[t * SCS + v0];   // P[0] slice
      unsigned long long ro0 = ro2.x, ro1 = ro2.y;
      for (int s = 0; s <= t; s++) {
        unsigned long long aa = pack2dup(T[t * 64 + s]);
        ulonglong2 u2 = *(const ulonglong2*)&Un[s * SCS + v0];
        fma2(ro0, aa, u2.x); fma2(ro1, aa, u2.y);
      }
      float o0, o1, o2, o3;
      unpack2(ro0, o0, o1); unpack2(ro1, o2, o3);
      size_t op = (((size_t)b * LL + (size_t)c * BT + t) * HH + h) * DH + vb * 32 + v0;
      *(float4*)&og[op] = make_float4(o0, o1, o2, o3);
    }

    // ---- Phase D: S += k^T @ u_new via fp16 MMA ----
    {
      float sacc[4][4];
#pragma unroll
      for (int vt = 0; vt < 4; vt++)
#pragma unroll
        for (int e = 0; e < 4; e++) sacc[vt][e] = 0.f;
#pragma unroll
      for (int kk = 0; kk < BT; kk += 16) {
        const float* k0 = &Q[(kk + fc) * QS + dw];
        const float* k1 = &Q[(kk + fc + 1) * QS + dw];
        const float* k8 = &Q[(kk + fc + 8) * QS + dw];
        const float* k9 = &Q[(kk + fc + 9) * QS + dw];
        uint32_t a[4];
        a[0] = h2(k0[fr],     k1[fr]);
        a[1] = h2(k0[fr + 8], k1[fr + 8]);
        a[2] = h2(k8[fr],     k9[fr]);
        a[3] = h2(k8[fr + 8], k9[fr + 8]);
        const float* un0 = &Un[(kk + fc) * SCS];
        const float* un1 = &Un[(kk + fc + 1) * SCS];
        const float* un8 = &Un[(kk + fc + 8) * SCS];
        const float* un9 = &Un[(kk + fc + 9) * SCS];
#pragma unroll
        for (int vt = 0; vt < 4; vt++) {
          uint32_t b0 = h2(un0[vt * 8 + fr], un1[vt * 8 + fr]);
          uint32_t b1 = h2(un8[vt * 8 + fr], un9[vt * 8 + fr]);
          mma16816(sacc[vt], a, b0, b1);
        }
      }
#pragma unroll
      for (int vt = 0; vt < 4; vt++) {
        float2* sp0 = (float2*)&S[(dw + fr) * SCS + vt * 8 + fc];
        float2 v0r = *sp0;
        v0r.x += sacc[vt][0]; v0r.y += sacc[vt][1];
        *sp0 = v0r;
        float2* sp1 = (float2*)&S[(dw + fr + 8) * SCS + vt * 8 + fc];
        float2 v1r = *sp1;
        v1r.x += sacc[vt][2]; v1r.y += sacc[vt][3];
        *sp1 = v1r;
      }
    }
    __syncthreads();
  }
}

// -------------------- per-head RMSNorm * g_norm, warp-per-row --------------------
__global__ __launch_bounds__(256) void rms_kernel(
    const float* __restrict__ og, const float* __restrict__ gn, float* __restrict__ on)
{
  int w = threadIdx.x >> 5, lane = threadIdx.x & 31;
  size_t idx = (size_t)blockIdx.x * 8 + w;
  const float* ip = og + idx * DH;
  float v[8];
  float ss = 0.f;
#pragma unroll
  for (int j = 0; j < 8; j++) {
    v[j] = ip[lane + j * 32];
    ss += v[j] * v[j];
  }
#pragma unroll
  for (int o = 16; o; o >>= 1) ss += __shfl_xor_sync(0xffffffffu, ss, o);
  float scale = rsqrtf(ss * (1.f / DH) + 1e-5f);
  float* op = on + idx * DH;
#pragma unroll
  for (int j = 0; j < 8; j++) op[lane + j * 32] = v[j] * scale * gn[lane + j * 32];
}

// -------------------- host launch --------------------
extern "C" void kernel_launch(void* const* d_in, const int* in_sizes, int n_in,
                              void* d_out, int out_size)
{
  const float* hs = (const float*)d_in[0];
  const float* Wq = (const float*)d_in[1];
  const float* Wk = (const float*)d_in[2];
  const float* Wv = (const float*)d_in[3];
  const float* Wb = (const float*)d_in[4];
  const float* cq = (const float*)d_in[5];
  const float* ck = (const float*)d_in[6];
  const float* cv = (const float*)d_in[7];
  const float* gn = (const float*)d_in[8];
  const float* Wo = (const float*)d_in[9];
  float* out = (float*)d_out;

  float *preq, *prek, *prev, *qt, *kt, *vt, *wt, *ut, *beta, *att, *og, *on;
  __half *ah, *wh;
  cudaGetSymbolAddress((void**)&preq, g_preq);
  cudaGetSymbolAddress((void**)&prek, g_prek);
  cudaGetSymbolAddress((void**)&prev, g_prev);
  cudaGetSymbolAddress((void**)&qt, g_qt);
  cudaGetSymbolAddress((void**)&kt, g_kt);
  cudaGetSymbolAddress((void**)&vt, g_vt);
  cudaGetSymbolAddress((void**)&wt, g_wt);
  cudaGetSymbolAddress((void**)&ut, g_ut);
  cudaGetSymbolAddress((void**)&beta, g_beta);
  cudaGetSymbolAddress((void**)&att, g_att);
  cudaGetSymbolAddress((void**)&og, g_og);
  cudaGetSymbolAddress((void**)&on, g_on);
  cudaGetSymbolAddress((void**)&ah, g_ah);
  cudaGetSymbolAddress((void**)&wh, g_wh);

  cudaFuncSetAttribute(gemm_h_kernel, cudaFuncAttributeMaxDynamicSharedMemorySize, GEMM_SMEM);
  cudaFuncSetAttribute(solve_kernel, cudaFuncAttributeMaxDynamicSharedMemorySize, SOLVE_SMEM);
  cudaFuncSetAttribute(attn_kernel, cudaFuncAttributeMaxDynamicSharedMemorySize, ATTN_SMEM);
  cudaFuncSetAttribute(scan_kernel, cudaFuncAttributeMaxDynamicSharedMemorySize, SCAN_SMEM);

  dim3 gg(DDIM / 128, (BB * LL) / 128);
  const int actN4 = BLD / 4, wN4 = DD2 / 4;

  cvt_kernel<<<(actN4 + 255) / 256, 256>>>(hs, ah, actN4);
  cvt_kernel<<<(wN4 + 255) / 256, 256>>>(Wq, wh + 0 * (size_t)DD2, wN4);
  cvt_kernel<<<(wN4 + 255) / 256, 256>>>(Wk, wh + 1 * (size_t)DD2, wN4);
  gemm_h_kernel<<<gg, 256, GEMM_SMEM>>>(ah, wh + 0 * (size_t)DD2, preq, BB * LL, DDIM, DDIM);
  cvt_kernel<<<(wN4 + 255) / 256, 256>>>(Wv, wh + 2 * (size_t)DD2, wN4);
  cvt_kernel<<<(wN4 + 255) / 256, 256>>>(Wo, wh + 3 * (size_t)DD2, wN4);
  gemm_h_kernel<<<gg, 256, GEMM_SMEM>>>(ah, wh + 1 * (size_t)DD2, prek, BB * LL, DDIM, DDIM);
  gemm_h_kernel<<<gg, 256, GEMM_SMEM>>>(ah, wh + 2 * (size_t)DD2, prev, BB * LL, DDIM, DDIM);
  beta_kernel<<<BB * LL, 256>>>(hs, Wb, beta);

  conv_kernel<<<BB * HH * (LL / 8), 256>>>(preq, cq, qt, 0);
  conv_kernel<<<BB * HH * (LL / 8), 256>>>(prek, ck, kt, 1);
  conv_kernel<<<BB * HH * (LL / 8), 256>>>(prev, cv, vt, 2);

  solve_kernel<<<BB * HH * NC, 512, SOLVE_SMEM>>>(kt, vt, beta, wt, ut);
  attn_kernel<<<BB * HH * NC, 512, ATTN_SMEM>>>(qt, kt, att);
  scan_kernel<<<BB * HH * 8, 512, SCAN_SMEM>>>(qt, kt, wt, ut, att, og);

  rms_kernel<<<BB * LL * HH / 8, 256>>>(og, gn, on);
  cvt_kernel<<<(actN4 + 255) / 256, 256>>>(on, ah, actN4);
  gemm_h_kernel<<<gg, 256, GEMM_SMEM>>>(ah, wh + 3 * (size_t)DD2, out, BB * LL, DDIM, DDIM);
}

// round 11
// speedup vs baseline: 3.9774x; 1.0183x over previous
#include <cuda_runtime.h>
#include <cuda_fp16.h>
#include <math.h>
#include <stdint.h>

#define BB 2
#define LL 4096
#define DDIM 2048
#define HH 8
#define DH 256
#define BT 64
#define NC 64          // LL / BT
#define BLD (BB*LL*DDIM)
#define DD2 (DDIM*DDIM)
#define QS 260         // padded fp32 tile stride
#define SCS 36         // S / Un / P row stride
#define TS 68          // T row stride (≡4 mod 32: conflict-free fragment loads)

// -------------------- scratch (device globals; no allocation) --------------------
__device__ float g_preq[BLD];
__device__ float g_prek[BLD];
__device__ float g_prev[BLD];
__device__ float g_qt[BLD];
__device__ float g_kt[BLD];
__device__ float g_vt[BLD];
__device__ float g_wt[BLD];
__device__ float g_ut[BLD];
__device__ float g_beta[BB*HH*LL];
__device__ float g_att[(size_t)BB*HH*NC*BT*BT];
__device__ float g_og[BLD];
__device__ float g_on[BLD];
__device__ __align__(128) __half g_ah[BLD];
__device__ __align__(128) __half g_wh[4*DD2];

// -------------------- f32x2 packed helpers --------------------
__device__ __forceinline__ unsigned long long pack2dup(float x) {
  unsigned long long r;
  asm("mov.b64 %0, {%1,%1};" : "=l"(r) : "f"(x));
  return r;
}
__device__ __forceinline__ void unpack2(unsigned long long v, float& x, float& y) {
  asm("mov.b64 {%0,%1}, %2;" : "=f"(x), "=f"(y) : "l"(v));
}
__device__ __forceinline__ void fma2(unsigned long long& d,
                                     unsigned long long a, unsigned long long b) {
  asm("fma.rn.f32x2 %0, %1, %2, %0;" : "+l"(d) : "l"(a), "l"(b));
}
__device__ __forceinline__ uint32_t h2(float x, float y) {
  __half2 h = __floats2half2_rn(x, y);
  return *(uint32_t*)&h;
}

// ==================== convert fp32 -> fp16 ====================
__global__ __launch_bounds__(256) void cvt_kernel(
    const float* __restrict__ x, __half* __restrict__ h, int n4)
{
  int i = blockIdx.x * blockDim.x + threadIdx.x;
  if (i >= n4) return;
  float4 v = *(const float4*)(x + (size_t)i * 4);
  __half2* hp = (__half2*)(h + (size_t)i * 4);
  hp[0] = __floats2half2_rn(v.x, v.y);
  hp[1] = __floats2half2_rn(v.z, v.w);
}

// ==================== fp16 HMMA GEMM, BK=32, 4-stage cp.async ====================
#define GSTRIDE 40
#define GTILE (128*GSTRIDE)
#define ABYTES (GTILE*2)
#define STAGEB (2*ABYTES)
#define NSTAGE 4
#define GEMM_SMEM (NSTAGE*STAGEB)

__device__ __forceinline__ void cpa16(uint32_t dst, const void* src) {
  asm volatile("cp.async.ca.shared.global [%0], [%1], 16;" :: "r"(dst), "l"(src));
}
#define CP_COMMIT() asm volatile("cp.async.commit_group;" ::: "memory")
#define CP_WAIT(n)  asm volatile("cp.async.wait_group %0;" :: "n"(n) : "memory")

__device__ __forceinline__ void ldsm4(uint32_t* r, uint32_t addr) {
  asm volatile("ldmatrix.sync.aligned.m8n8.x4.shared.b16 {%0,%1,%2,%3}, [%4];"
    : "=r"(r[0]), "=r"(r[1]), "=r"(r[2]), "=r"(r[3]) : "r"(addr));
}
__device__ __forceinline__ void mma16816(float* d, const uint32_t* a, uint32_t b0, uint32_t b1) {
  asm volatile("mma.sync.aligned.m16n8k16.row.col.f32.f16.f16.f32 "
    "{%0,%1,%2,%3}, {%4,%5,%6,%7}, {%8,%9}, {%0,%1,%2,%3};"
    : "+f"(d[0]), "+f"(d[1]), "+f"(d[2]), "+f"(d[3])
    : "r"(a[0]), "r"(a[1]), "r"(a[2]), "r"(a[3]), "r"(b0), "r"(b1));
}

__device__ __forceinline__ void load_stage_async(
    const __half* __restrict__ A, const __half* __restrict__ B,
    int bm, int bn, int K, int k0, uint32_t sb, int tid)
{
  const __half* srcs[2] = {A, B};
  const int rb[2] = {bm, bn};
#pragma unroll
  for (int a = 0; a < 2; a++) {
#pragma unroll
    for (int i = 0; i < 2; i++) {
      int idx = tid + i * 256;
      int r = idx >> 2, ch = idx & 3;
      const __half* g = srcs[a] + (size_t)(rb[a] + r) * K + k0 + ch * 8;
      uint32_t dst = sb + a * ABYTES + (uint32_t)(r * 80 + ch * 16);
      cpa16(dst, g);
    }
  }
}

__global__ __launch_bounds__(256, 2) void gemm_h_kernel(
    const __half* __restrict__ A, const __half* __restrict__ B,
    float* __restrict__ C, int M, int N, int K)
{
  extern __shared__ char sm[];
  const int tid = threadIdx.x, lane = tid & 31, wid = tid >> 5;
  const int warp_m = wid >> 2, warp_n = wid & 3;
  const int bm = blockIdx.y * 128, bn = blockIdx.x * 128;
  const uint32_t sbase = (uint32_t)__cvta_generic_to_shared(sm);

  float acc[4][4][4];
#pragma unroll
  for (int i = 0; i < 4; i++)
#pragma unroll
    for (int j = 0; j < 4; j++)
#pragma unroll
      for (int e = 0; e < 4; e++) acc[i][j][e] = 0.f;

  const int NT = K / 32;
#pragma unroll
  for (int p = 0; p < NSTAGE - 1; p++) {
    load_stage_async(A, B, bm, bn, K, p * 32, sbase + p * STAGEB, tid);
    CP_COMMIT();
  }

  const int arow  = warp_m * 64 + (lane & 15);
  const int acol0 = (lane >> 4) * 8;
  const int brow  = warp_n * 32 + (lane >> 4) * 8 + (lane & 7);
  const int bcol0 = ((lane >> 3) & 1) * 8;

  for (int kt = 0; kt < NT; kt++) {
    CP_WAIT(NSTAGE - 2);
    __syncthreads();
    {
      int knext = kt + NSTAGE - 1;
      int kc = knext < NT ? knext : NT - 1;
      load_stage_async(A, B, bm, bn, K, kc * 32, sbase + (knext & (NSTAGE - 1)) * STAGEB, tid);
      CP_COMMIT();
    }
    const uint32_t stb = sbase + (kt & (NSTAGE - 1)) * STAGEB;
    const uint32_t aoff = stb;
    const uint32_t boff = stb + ABYTES;
#pragma unroll
    for (int kk = 0; kk < 32; kk += 16) {
      uint32_t af[4][4], bf[2][4];
#pragma unroll
      for (int mt = 0; mt < 4; mt++) {
        uint32_t ab = (uint32_t)(((arow + mt * 16) * GSTRIDE + kk + acol0) * 2);
        ldsm4(af[mt], aoff + ab);
      }
#pragma unroll
      for (int p = 0; p < 2; p++) {
        uint32_t bb = (uint32_t)(((brow + p * 16) * GSTRIDE + kk + bcol0) * 2);
        ldsm4(bf[p], boff + bb);
      }
#pragma unroll
      for (int mt = 0; mt < 4; mt++)
#pragma unroll
        for (int nt = 0; nt < 4; nt++) {
          const uint32_t* bp = bf[nt >> 1];
          int bi = (nt & 1) * 2;
          mma16816(acc[mt][nt], af[mt], bp[bi], bp[bi + 1]);
        }
    }
  }
  __syncthreads();
  const int row0 = bm + warp_m * 64 + (lane >> 2);
  const int col0 = bn + warp_n * 32 + (lane & 3) * 2;
#pragma unroll
  for (int mt = 0; mt < 4; mt++)
#pragma unroll
    for (int nt = 0; nt < 4; nt++) {
      int r = row0 + mt * 16;
      int c = col0 + nt * 8;
      *(float2*)(C + (size_t)r * N + c)       = make_float2(acc[mt][nt][0], acc[mt][nt][1]);
      *(float2*)(C + (size_t)(r + 8) * N + c) = make_float2(acc[mt][nt][2], acc[mt][nt][3]);
    }
}

// -------------------- beta = sigmoid(hs @ Wb^T), [B,H,L] --------------------
__global__ __launch_bounds__(256) void beta_kernel(
    const float* __restrict__ hs, const float* __restrict__ Wb, float* __restrict__ beta)
{
  int bl = blockIdx.x;
  int b = bl / LL, l = bl % LL;
  int w = threadIdx.x >> 5, lane = threadIdx.x & 31;
  const float* x = hs + (size_t)bl * DDIM;
  const float* wb = Wb + (size_t)w * DDIM;
  float s = 0.f;
  for (int d = lane; d < DDIM; d += 32) s += x[d] * wb[d];
#pragma unroll
  for (int o = 16; o; o >>= 1) s += __shfl_xor_sync(0xffffffffu, s, o);
  if (lane == 0)
    beta[((size_t)b * HH + w) * LL + l] = 1.f / (1.f + expf(-s));
}

// -------------------- conv + SiLU (+l2norm), warp-per-token, float4 --------------------
__global__ __launch_bounds__(256) void conv_kernel(
    const float* __restrict__ pre, const float* __restrict__ cw,
    float* __restrict__ out, int mode)
{
  int blk = blockIdx.x;
  int lt = blk & (LL / 8 - 1);
  int bh = blk >> 9;
  int h = bh % HH, b = bh / HH;
  int w = threadIdx.x >> 5, lane = threadIdx.x & 31;
  int l = lt * 8 + w;
  const float* base = pre + ((size_t)b * LL) * DDIM + h * DH;
  float y[2][4];
  float ss = 0.f;
  const float4 zero4 = make_float4(0, 0, 0, 0);
#pragma unroll
  for (int j = 0; j < 2; j++) {
    int dd = lane * 4 + j * 128;
    int c = h * DH + dd;
    float4 x0 = *(const float4*)(base + (size_t)l * DDIM + dd);
    float4 x1 = (l >= 1) ? *(const float4*)(base + (size_t)(l - 1) * DDIM + dd) : zero4;
    float4 x2 = (l >= 2) ? *(const float4*)(base + (size_t)(l - 2) * DDIM + dd) : zero4;
    float4 x3 = (l >= 3) ? *(const float4*)(base + (size_t)(l - 3) * DDIM + dd) : zero4;
    const float xs[4][4] = {{x0.x, x1.x, x2.x, x3.x}, {x0.y, x1.y, x2.y, x3.y},
                            {x0.z, x1.z, x2.z, x3.z}, {x0.w, x1.w, x2.w, x3.w}};
#pragma unroll
    for (int ci = 0; ci < 4; ci++) {
      float4 cv = *(const float4*)(cw + (size_t)(c + ci) * 4);
      float acc = xs[ci][0] * cv.w + xs[ci][1] * cv.z + xs[ci][2] * cv.y + xs[ci][3] * cv.x;
      float yy = acc / (1.f + expf(-acc));
      y[j][ci] = yy;
      ss += yy * yy;
    }
  }
  float scale = 1.f;
  if (mode < 2) {
#pragma unroll
    for (int o = 16; o; o >>= 1) ss += __shfl_xor_sync(0xffffffffu, ss, o);
    scale = rsqrtf(ss + 1e-6f);
    if (mode == 0) scale *= 0.0625f;
  }
  float* op = out + (((size_t)b * HH + h) * LL + l) * DH;
#pragma unroll
  for (int j = 0; j < 2; j++) {
    int dd = lane * 4 + j * 128;
    *(float4*)(op + dd) = make_float4(y[j][0] * scale, y[j][1] * scale,
                                      y[j][2] * scale, y[j][3] * scale);
  }
}

// -------------------- per-chunk triangular solve (tiled M, f32x2 substitution) ------
#define SOLVE_SMEM ((3*64*QS + 64*64 + 64) * 4)
__global__ __launch_bounds__(512) void solve_kernel(
    const float* __restrict__ kt, const float* __restrict__ vt,
    const float* __restrict__ beta, float* __restrict__ Wt, float* __restrict__ Ut)
{
  extern __shared__ float sh[];
  float* sk = sh;                 // [64][260]
  float* sw = sk + 64 * QS;
  float* su = sw + 64 * QS;
  float* sM = su + 64 * QS;       // [64][64]
  float* sbeta = sM + 64 * 64;
  int blk = blockIdx.x;
  int c = blk % NC, bh = blk / NC;
  size_t base = ((size_t)bh * LL + (size_t)c * BT) * DH;
  int tid = threadIdx.x;

  if (tid < 64) sbeta[tid] = beta[(size_t)bh * LL + c * BT + tid];
  __syncthreads();
  for (int i = tid; i < 4096; i += 512) {
    int t = i >> 6, dd = (i & 63) * 4;
    float bt = sbeta[t];
    float4 kv = *(const float4*)(kt + base + (size_t)t * DH + dd);
    float4 vv = *(const float4*)(vt + base + (size_t)t * DH + dd);
    *(float4*)&sk[t * QS + dd] = kv;
    *(float4*)&sw[t * QS + dd] = make_float4(kv.x * bt, kv.y * bt, kv.z * bt, kv.w * bt);
    *(float4*)&su[t * QS + dd] = make_float4(vv.x * bt, vv.y * bt, vv.z * bt, vv.w * bt);
  }
  __syncthreads();
  {
    int tp = tid >> 4, sb = tid & 15;
    int t0 = tp * 2, t1 = t0 + 1;
    unsigned long long acc[2][4];
#pragma unroll
    for (int ti = 0; ti < 2; ti++)
#pragma unroll
      for (int si = 0; si < 4; si++) acc[ti][si] = 0;
    if (sb < t1) {
      const float* q0 = &sw[t0 * QS];
      const float* q1 = &sw[t1 * QS];
#pragma unroll 2
      for (int d = 0; d < DH; d += 4) {
        ulonglong2 a0 = *(const ulonglong2*)(q0 + d);
        ulonglong2 a1 = *(const ulonglong2*)(q1 + d);
#pragma unroll
        for (int si = 0; si < 4; si++) {
          ulonglong2 kv = *(const ulonglong2*)(&sk[(sb + si * 16) * QS + d]);
          fma2(acc[0][si], a0.x, kv.x); fma2(acc[0][si], a0.y, kv.y);
          fma2(acc[1][si], a1.x, kv.x); fma2(acc[1][si], a1.y, kv.y);
        }
      }
    }
#pragma unroll
    for (int ti = 0; ti < 2; ti++)
#pragma unroll
      for (int si = 0; si < 4; si++) {
        int t = t0 + ti, s = sb + si * 16;
        float x0, x1;
        unpack2(acc[ti][si], x0, x1);
        sM[t * 64 + s] = (s < t) ? (x0 + x1) : 0.f;
      }
  }
  __syncthreads();
  if (tid < 128) {
    int d = tid * 2;
    for (int t = 1; t < BT; t++) {
      unsigned long long acc = 0;
      const float* Mr = &sM[t * 64];
      for (int s = 0; s < t; s++)
        fma2(acc, pack2dup(Mr[s]), *(const unsigned long long*)&sw[s * QS + d]);
      float a0, a1;
      unpack2(acc, a0, a1);
      sw[t * QS + d]     -= a0;
      sw[t * QS + d + 1] -= a1;
    }
  } else if (tid < 256) {
    int d = (tid - 128) * 2;
    for (int t = 1; t < BT; t++) {
      unsigned long long acc = 0;
      const float* Mr = &sM[t * 64];
      for (int s = 0; s < t; s++)
        fma2(acc, pack2dup(Mr[s]), *(const unsigned long long*)&su[s * QS + d]);
      float a0, a1;
      unpack2(acc, a0, a1);
      su[t * QS + d]     -= a0;
      su[t * QS + d + 1] -= a1;
    }
  }
  __syncthreads();
  for (int i = tid; i < 4096; i += 512) {
    int t = i >> 6, dd = (i & 63) * 4;
    *(float4*)(Wt + base + (size_t)t * DH + dd) = *(float4*)&sw[t * QS + dd];
    *(float4*)(Ut + base + (size_t)t * DH + dd) = *(float4*)&su[t * QS + dd];
  }
}

// -------------------- attn = tril(q k^T), 2t x 4s register tile --------------------
#define ATTN_SMEM (2*64*QS*4)
__global__ __launch_bounds__(512) void attn_kernel(
    const float* __restrict__ qt, const float* __restrict__ kt, float* __restrict__ att)
{
  extern __shared__ float sh[];
  float* sq = sh;
  float* sk = sq + 64 * QS;
  int blk = blockIdx.x;
  int c = blk % NC, bh = blk / NC;
  size_t base = ((size_t)bh * LL + (size_t)c * BT) * DH;
  int tid = threadIdx.x;
  for (int i = tid; i < 4096; i += 512) {
    int t = i >> 6, dd = (i & 63) * 4;
    *(float4*)&sq[t * QS + dd] = *(const float4*)(qt + base + (size_t)t * DH + dd);
    *(float4*)&sk[t * QS + dd] = *(const float4*)(kt + base + (size_t)t * DH + dd);
  }
  __syncthreads();
  float* ap = att + (size_t)blk * (BT * BT);
  int tp = tid >> 4, sb = tid & 15;
  int t0 = tp * 2, t1 = t0 + 1;
  unsigned long long acc[2][4];
#pragma unroll
  for (int ti = 0; ti < 2; ti++)
#pragma unroll
    for (int si = 0; si < 4; si++) acc[ti][si] = 0;
  if (sb <= t1) {
    const float* q0 = &sq[t0 * QS];
    const float* q1 = &sq[t1 * QS];
#pragma unroll 2
    for (int d = 0; d < DH; d += 4) {
      ulonglong2 a0 = *(const ulonglong2*)(q0 + d);
      ulonglong2 a1 = *(const ulonglong2*)(q1 + d);
#pragma unroll
      for (int si = 0; si < 4; si++) {
        ulonglong2 kv = *(const ulonglong2*)(&sk[(sb + si * 16) * QS + d]);
        fma2(acc[0][si], a0.x, kv.x); fma2(acc[0][si], a0.y, kv.y);
        fma2(acc[1][si], a1.x, kv.x); fma2(acc[1][si], a1.y, kv.y);
      }
    }
  }
#pragma unroll
  for (int ti = 0; ti < 2; ti++)
#pragma unroll
    for (int si = 0; si < 4; si++) {
      int t = t0 + ti, s = sb + si * 16;
      float x0, x1;
      unpack2(acc[ti][si], x0, x1);
      ap[t * 64 + s] = (s <= t) ? (x0 + x1) : 0.f;
    }
}

// -------------------- scan: all three GEMM phases on fp16 MMA --------------------
// smem: S[256][36], Q[64][260], W[64][260], T[64][68], Un[64][36], P[2][64][36]
#define SCAN_SMEM ((256*SCS + 2*64*QS + 64*TS + 64*SCS + 2*64*SCS) * 4)
__global__ __launch_bounds__(512) void scan_kernel(
    const float* __restrict__ qt, const float* __restrict__ kt,
    const float* __restrict__ wt, const float* __restrict__ ut,
    const float* __restrict__ att, float* __restrict__ og)
{
  extern __shared__ float sh[];
  float* S  = sh;                 // [256][36]
  float* Q  = S + 256 * SCS;      // [64][260]  q, then k
  float* W  = Q + 64 * QS;        // [64][260]
  float* T  = W + 64 * QS;        // [64][68]
  float* Un = T + 64 * TS;        // [64][36]
  float* P  = Un + 64 * SCS;      // [2][64][36] partials/finals
  int blk = blockIdx.x;
  int vb = blk & 7;
  int bh = blk >> 3;
  int b = bh / HH, h = bh % HH;
  int tid = threadIdx.x;
  int lane = tid & 31, wrp = tid >> 5;
  int fr = lane >> 2;             // fragment row
  int fc = (lane & 3) * 2;        // fragment col (even)
  int dw = wrp * 16;              // S-update d-row base
  // merged-pass warp mapping
  int which = wrp >> 3;           // 0: q@S, 1: w@S
  int sub = wrp & 7;
  int ttile = sub & 3;            // t base = ttile*16
  int khalf = sub >> 2;           // K half (128 d each)
  int tb = ttile * 16;
  // phase-C warp mapping (o = T@Un tiles)
  int cmt = wrp >> 2;             // 0..3: t rows cmt*16
  int cnt = wrp & 3;              // 0..3: v cols cnt*8
  int ctb = cmt * 16, cnb = cnt * 8;
  // prefetch thread index for khalf==1 warps
  int pidx = (((wrp >> 3) << 2) | (wrp & 3)) * 32 + lane;

  for (int i = tid; i < 256 * SCS; i += 512) S[i] = 0.f;
  __syncthreads();

  for (int c = 0; c < NC; c++) {
    size_t base = ((size_t)bh * LL + (size_t)c * BT) * DH;
    const float* ap = att + ((size_t)bh * NC + c) * (BT * BT);
    // stage q, w, att tiles
    for (int i = tid; i < 4096; i += 512) {
      int tt = i >> 6, dd = (i & 63) * 4;
      *(float4*)&Q[tt * QS + dd] = *(const float4*)(qt + base + (size_t)tt * DH + dd);
      *(float4*)&W[tt * QS + dd] = *(const float4*)(wt + base + (size_t)tt * DH + dd);
    }
    for (int i = tid; i < 1024; i += 512) {
      int tt = i >> 4, cc = (i & 15) * 4;
      *(float4*)&T[tt * TS + cc] = *(const float4*)(ap + tt * 64 + cc);
    }
    __syncthreads();

    // ---- Phase A: fp16 MMA partials of q@S (which=0) and w@S (which=1) ----
    float acc[4][4];
#pragma unroll
    for (int vt = 0; vt < 4; vt++)
#pragma unroll
      for (int e = 0; e < 4; e++) acc[vt][e] = 0.f;
    {
      const float* Ab = which ? W : Q;
      const float* ar0 = Ab + (tb + fr) * QS;
      const float* ar1 = Ab + (tb + fr + 8) * QS;
      int k0 = khalf * 128;
#pragma unroll
      for (int kk = k0; kk < k0 + 128; kk += 16) {
        float2 f00 = *(const float2*)(ar0 + kk + fc);
        float2 f01 = *(const float2*)(ar0 + kk + fc + 8);
        float2 f10 = *(const float2*)(ar1 + kk + fc);
        float2 f11 = *(const float2*)(ar1 + kk + fc + 8);
        uint32_t a[4];
        a[0] = h2(f00.x, f00.y);
        a[1] = h2(f10.x, f10.y);
        a[2] = h2(f01.x, f01.y);
        a[3] = h2(f11.x, f11.y);
        const float* s0 = &S[(kk + fc) * SCS];
        const float* s1 = &S[(kk + fc + 1) * SCS];
        const float* s8 = &S[(kk + fc + 8) * SCS];
        const float* s9 = &S[(kk + fc + 9) * SCS];
#pragma unroll
        for (int vt = 0; vt < 4; vt++) {
          int vn = vt * 8 + fr;
          uint32_t b0 = h2(s0[vn], s1[vn]);
          uint32_t b1 = h2(s8[vn], s9[vn]);
          mma16816(acc[vt], a, b0, b1);
        }
      }
    }
    float* Pp = &P[which * 64 * SCS + tb * SCS];
    if (khalf == 1) {
#pragma unroll
      for (int vt = 0; vt < 4; vt++) {
        *(float2*)&Pp[fr * SCS + vt * 8 + fc]       = make_float2(acc[vt][0], acc[vt][1]);
        *(float2*)&Pp[(fr + 8) * SCS + vt * 8 + fc] = make_float2(acc[vt][2], acc[vt][3]);
      }
    }
    __syncthreads();

    // ---- Phase B: khalf0 combine; khalf1 prefetch k into Q ----
    if (khalf == 0) {
      if (which == 0) {
#pragma unroll
        for (int vt = 0; vt < 4; vt++) {
          float2 p0 = *(float2*)&Pp[fr * SCS + vt * 8 + fc];
          float2 p1 = *(float2*)&Pp[(fr + 8) * SCS + vt * 8 + fc];
          *(float2*)&Pp[fr * SCS + vt * 8 + fc] =
              make_float2(acc[vt][0] + p0.x, acc[vt][1] + p0.y);
          *(float2*)&Pp[(fr + 8) * SCS + vt * 8 + fc] =
              make_float2(acc[vt][2] + p1.x, acc[vt][3] + p1.y);
        }
      } else {
        size_t ub0 = base + (size_t)(tb + fr) * DH + vb * 32;
        size_t ub1 = base + (size_t)(tb + fr + 8) * DH + vb * 32;
#pragma unroll
        for (int vt = 0; vt < 4; vt++) {
          float2 p0 = *(float2*)&Pp[fr * SCS + vt * 8 + fc];
          float2 p1 = *(float2*)&Pp[(fr + 8) * SCS + vt * 8 + fc];
          float2 u0 = *(const float2*)(ut + ub0 + vt * 8 + fc);
          float2 u1 = *(const float2*)(ut + ub1 + vt * 8 + fc);
          *(float2*)&Un[(tb + fr) * SCS + vt * 8 + fc] =
              make_float2(u0.x - (acc[vt][0] + p0.x), u0.y - (acc[vt][1] + p0.y));
          *(float2*)&Un[(tb + fr + 8) * SCS + vt * 8 + fc] =
              make_float2(u1.x - (acc[vt][2] + p1.x), u1.y - (acc[vt][3] + p1.y));
        }
      }
    } else {
      for (int i = pidx; i < 1024; i += 256) {
        int tt = i >> 4, dd = (i & 15) * 16;
        *(float4*)&Q[tt * QS + dd]      = *(const float4*)(kt + base + (size_t)tt * DH + dd);
        *(float4*)&Q[tt * QS + dd + 4]  = *(const float4*)(kt + base + (size_t)tt * DH + dd + 4);
        *(float4*)&Q[tt * QS + dd + 8]  = *(const float4*)(kt + base + (size_t)tt * DH + dd + 8);
        *(float4*)&Q[tt * QS + dd + 12] = *(const float4*)(kt + base + (size_t)tt * DH + dd + 12);
      }
    }
    __syncthreads();

    // ---- Phase C: o = q@S + T @ Un via fp16 MMA (T upper triangle is zero) ----
    {
      float cacc[4] = {0.f, 0.f, 0.f, 0.f};
#pragma unroll
      for (int kk = 0; kk < BT; kk += 16) {
        const float* t0p = &T[(ctb + fr) * TS + kk];
        const float* t1p = &T[(ctb + fr + 8) * TS + kk];
        float2 f0 = *(const float2*)(t0p + fc);
        float2 f1 = *(const float2*)(t1p + fc);
        float2 f2 = *(const float2*)(t0p + fc + 8);
        float2 f3 = *(const float2*)(t1p + fc + 8);
        uint32_t a[4];
        a[0] = h2(f0.x, f0.y);
        a[1] = h2(f1.x, f1.y);
        a[2] = h2(f2.x, f2.y);
        a[3] = h2(f3.x, f3.y);
        const float* un0 = &Un[(kk + fc) * SCS];
        const float* un1 = &Un[(kk + fc + 1) * SCS];
        const float* un8 = &Un[(kk + fc + 8) * SCS];
        const float* un9 = &Un[(kk + fc + 9) * SCS];
        int n = cnb + fr;
        uint32_t b0 = h2(un0[n], un1[n]);
        uint32_t b1 = h2(un8[n], un9[n]);
        mma16816(cacc, a, b0, b1);
      }
      int r0 = ctb + fr, r1 = ctb + fr + 8;
      float2 p0 = *(const float2*)&P[r0 * SCS + cnb + fc];
      float2 p1 = *(const float2*)&P[r1 * SCS + cnb + fc];
      size_t o0 = (((size_t)b * LL + (size_t)c * BT + r0) * HH + h) * DH + vb * 32 + cnb + fc;
      size_t o1 = (((size_t)b * LL + (size_t)c * BT + r1) * HH + h) * DH + vb * 32 + cnb + fc;
      *(float2*)&og[o0] = make_float2(p0.x + cacc[0], p0.y + cacc[1]);
      *(float2*)&og[o1] = make_float2(p1.x + cacc[2], p1.y + cacc[3]);
    }

    // ---- Phase D: S += k^T @ u_new via fp16 MMA ----
    {
      float sacc[4][4];
#pragma unroll
      for (int vt = 0; vt < 4; vt++)
#pragma unroll
        for (int e = 0; e < 4; e++) sacc[vt][e] = 0.f;
#pragma unroll
      for (int kk = 0; kk < BT; kk += 16) {
        const float* k0 = &Q[(kk + fc) * QS + dw];
        const float* k1 = &Q[(kk + fc + 1) * QS + dw];
        const float* k8 = &Q[(kk + fc + 8) * QS + dw];
        const float* k9 = &Q[(kk + fc + 9) * QS + dw];
        uint32_t a[4];
        a[0] = h2(k0[fr],     k1[fr]);
        a[1] = h2(k0[fr + 8], k1[fr + 8]);
        a[2] = h2(k8[fr],     k9[fr]);
        a[3] = h2(k8[fr + 8], k9[fr + 8]);
        const float* un0 = &Un[(kk + fc) * SCS];
        const float* un1 = &Un[(kk + fc + 1) * SCS];
        const float* un8 = &Un[(kk + fc + 8) * SCS];
        const float* un9 = &Un[(kk + fc + 9) * SCS];
#pragma unroll
        for (int vt = 0; vt < 4; vt++) {
          uint32_t b0 = h2(un0[vt * 8 + fr], un1[vt * 8 + fr]);
          uint32_t b1 = h2(un8[vt * 8 + fr], un9[vt * 8 + fr]);
          mma16816(sacc[vt], a, b0, b1);
        }
      }
#pragma unroll
      for (int vt = 0; vt < 4; vt++) {
        float2* sp0 = (float2*)&S[(dw + fr) * SCS + vt * 8 + fc];
        float2 v0r = *sp0;
        v0r.x += sacc[vt][0]; v0r.y += sacc[vt][1];
        *sp0 = v0r;
        float2* sp1 = (float2*)&S[(dw + fr + 8) * SCS + vt * 8 + fc];
        float2 v1r = *sp1;
        v1r.x += sacc[vt][2]; v1r.y += sacc[vt][3];
        *sp1 = v1r;
      }
    }
    __syncthreads();
  }
}

// -------------------- per-head RMSNorm * g_norm, warp-per-row --------------------
__global__ __launch_bounds__(256) void rms_kernel(
    const float* __restrict__ og, const float* __restrict__ gn, float* __restrict__ on)
{
  int w = threadIdx.x >> 5, lane = threadIdx.x & 31;
  size_t idx = (size_t)blockIdx.x * 8 + w;
  const float* ip = og + idx * DH;
  float v[8];
  float ss = 0.f;
#pragma unroll
  for (int j = 0; j < 8; j++) {
    v[j] = ip[lane + j * 32];
    ss += v[j] * v[j];
  }
#pragma unroll
  for (int o = 16; o; o >>= 1) ss += __shfl_xor_sync(0xffffffffu, ss, o);
  float scale = rsqrtf(ss * (1.f / DH) + 1e-5f);
  float* op = on + idx * DH;
#pragma unroll
  for (int j = 0; j < 8; j++) op[lane + j * 32] = v[j] * scale * gn[lane + j * 32];
}

// -------------------- host launch --------------------
extern "C" void kernel_launch(void* const* d_in, const int* in_sizes, int n_in,
                              void* d_out, int out_size)
{
  const float* hs = (const float*)d_in[0];
  const float* Wq = (const float*)d_in[1];
  const float* Wk = (const float*)d_in[2];
  const float* Wv = (const float*)d_in[3];
  const float* Wb = (const float*)d_in[4];
  const float* cq = (const float*)d_in[5];
  const float* ck = (const float*)d_in[6];
  const float* cv = (const float*)d_in[7];
  const float* gn = (const float*)d_in[8];
  const float* Wo = (const float*)d_in[9];
  float* out = (float*)d_out;

  float *preq, *prek, *prev, *qt, *kt, *vt, *wt, *ut, *beta, *att, *og, *on;
  __half *ah, *wh;
  cudaGetSymbolAddress((void**)&preq, g_preq);
  cudaGetSymbolAddress((void**)&prek, g_prek);
  cudaGetSymbolAddress((void**)&prev, g_prev);
  cudaGetSymbolAddress((void**)&qt, g_qt);
  cudaGetSymbolAddress((void**)&kt, g_kt);
  cudaGetSymbolAddress((void**)&vt, g_vt);
  cudaGetSymbolAddress((void**)&wt, g_wt);
  cudaGetSymbolAddress((void**)&ut, g_ut);
  cudaGetSymbolAddress((void**)&beta, g_beta);
  cudaGetSymbolAddress((void**)&att, g_att);
  cudaGetSymbolAddress((void**)&og, g_og);
  cudaGetSymbolAddress((void**)&on, g_on);
  cudaGetSymbolAddress((void**)&ah, g_ah);
  cudaGetSymbolAddress((void**)&wh, g_wh);

  cudaFuncSetAttribute(gemm_h_kernel, cudaFuncAttributeMaxDynamicSharedMemorySize, GEMM_SMEM);
  cudaFuncSetAttribute(solve_kernel, cudaFuncAttributeMaxDynamicSharedMemorySize, SOLVE_SMEM);
  cudaFuncSetAttribute(attn_kernel, cudaFuncAttributeMaxDynamicSharedMemorySize, ATTN_SMEM);
  cudaFuncSetAttribute(scan_kernel, cudaFuncAttributeMaxDynamicSharedMemorySize, SCAN_SMEM);

  dim3 gg(DDIM / 128, (BB * LL) / 128);
  const int actN4 = BLD / 4, wN4 = DD2 / 4;

  cvt_kernel<<<(actN4 + 255) / 256, 256>>>(hs, ah, actN4);
  cvt_kernel<<<(wN4 + 255) / 256, 256>>>(Wq, wh + 0 * (size_t)DD2, wN4);
  cvt_kernel<<<(wN4 + 255) / 256, 256>>>(Wk, wh + 1 * (size_t)DD2, wN4);
  gemm_h_kernel<<<gg, 256, GEMM_SMEM>>>(ah, wh + 0 * (size_t)DD2, preq, BB * LL, DDIM, DDIM);
  cvt_kernel<<<(wN4 + 255) / 256, 256>>>(Wv, wh + 2 * (size_t)DD2, wN4);
  cvt_kernel<<<(wN4 + 255) / 256, 256>>>(Wo, wh + 3 * (size_t)DD2, wN4);
  gemm_h_kernel<<<gg, 256, GEMM_SMEM>>>(ah, wh + 1 * (size_t)DD2, prek, BB * LL, DDIM, DDIM);
  gemm_h_kernel<<<gg, 256, GEMM_SMEM>>>(ah, wh + 2 * (size_t)DD2, prev, BB * LL, DDIM, DDIM);
  beta_kernel<<<BB * LL, 256>>>(hs, Wb, beta);

  conv_kernel<<<BB * HH * (LL / 8), 256>>>(preq, cq, qt, 0);
  conv_kernel<<<BB * HH * (LL / 8), 256>>>(prek, ck, kt, 1);
  conv_kernel<<<BB * HH * (LL / 8), 256>>>(prev, cv, vt, 2);

  solve_kernel<<<BB * HH * NC, 512, SOLVE_SMEM>>>(kt, vt, beta, wt, ut);
  attn_kernel<<<BB * HH * NC, 512, ATTN_SMEM>>>(qt, kt, att);
  scan_kernel<<<BB * HH * 8, 512, SCAN_SMEM>>>(qt, kt, wt, ut, att, og);

  rms_kernel<<<BB * LL * HH / 8, 256>>>(og, gn, on);
  cvt_kernel<<<(actN4 + 255) / 256, 256>>>(on, ah, actN4);
  gemm_h_kernel<<<gg, 256, GEMM_SMEM>>>(ah, wh + 3 * (size_t)DD2, out, BB * LL, DDIM, DDIM);
}

// round 13
// speedup vs baseline: 4.4465x; 1.1179x over previous
#include <cuda_runtime.h>
#include <cuda_fp16.h>
#include <math.h>
#include <stdint.h>

#define BB 2
#define LL 4096
#define DDIM 2048
#define HH 8
#define DH 256
#define BT 64
#define NC 64          // LL / BT
#define BLD (BB*LL*DDIM)
#define DD2 (DDIM*DDIM)
#define QS 260         // padded fp32 tile stride (solve/attn)
#define SCS 36         // S / Un / P row stride (floats)
#define QHS 264        // fp16 staged tile stride (halfs): 256 data + 8 pad = 528 B
#define THS 72         // fp16 T stride (halfs)

// -------------------- scratch (device globals; no allocation) --------------------
__device__ float g_preq[BLD];
__device__ float g_prek[BLD];
__device__ float g_prev[BLD];
__device__ float g_qt[BLD];       // fp32 q (attn)
__device__ float g_kt[BLD];       // fp32 k (solve, attn)
__device__ float g_vt[BLD];
__device__ float g_ut[BLD];
__device__ float g_beta[BB*HH*LL];
__device__ float g_og[BLD];
__device__ __align__(128) __half g_qh[BLD];     // fp16 q (scan, row-major [t][d])
__device__ __align__(128) __half g_khT[BLD];    // fp16 k transposed per chunk: [bh][c][d][t]
__device__ __align__(128) __half g_ws[BLD];     // fp16 W (scan)
__device__ __align__(128) __half g_atth[(size_t)BB*HH*NC*BT*BT];
__device__ __align__(128) __half g_ah[BLD];     // activation fp16 (GEMM A)
__device__ __align__(128) __half g_wh[4*DD2];   // weights fp16

// -------------------- helpers --------------------
__device__ __forceinline__ unsigned long long pack2dup(float x) {
  unsigned long long r;
  asm("mov.b64 %0, {%1,%1};" : "=l"(r) : "f"(x));
  return r;
}
__device__ __forceinline__ void unpack2(unsigned long long v, float& x, float& y) {
  asm("mov.b64 {%0,%1}, %2;" : "=f"(x), "=f"(y) : "l"(v));
}
__device__ __forceinline__ void fma2(unsigned long long& d,
                                     unsigned long long a, unsigned long long b) {
  asm("fma.rn.f32x2 %0, %1, %2, %0;" : "+l"(d) : "l"(a), "l"(b));
}
__device__ __forceinline__ uint32_t h2(float x, float y) {
  __half2 h = __floats2half2_rn(x, y);
  return *(uint32_t*)&h;
}

// ==================== convert fp32 -> fp16 ====================
__global__ __launch_bounds__(256) void cvt_kernel(
    const float* __restrict__ x, __half* __restrict__ h, int n4)
{
  int i = blockIdx.x * blockDim.x + threadIdx.x;
  if (i >= n4) return;
  float4 v = *(const float4*)(x + (size_t)i * 4);
  __half2* hp = (__half2*)(h + (size_t)i * 4);
  hp[0] = __floats2half2_rn(v.x, v.y);
  hp[1] = __floats2half2_rn(v.z, v.w);
}

// ==================== fp16 HMMA GEMM, BK=32, 4-stage cp.async ====================
#define GSTRIDE 40
#define GTILE (128*GSTRIDE)
#define ABYTES (GTILE*2)
#define STAGEB (2*ABYTES)
#define NSTAGE 4
#define GEMM_SMEM (NSTAGE*STAGEB)

__device__ __forceinline__ void cpa16(uint32_t dst, const void* src) {
  asm volatile("cp.async.ca.shared.global [%0], [%1], 16;" :: "r"(dst), "l"(src));
}
#define CP_COMMIT() asm volatile("cp.async.commit_group;" ::: "memory")
#define CP_WAIT(n)  asm volatile("cp.async.wait_group %0;" :: "n"(n) : "memory")

__device__ __forceinline__ void ldsm4(uint32_t* r, uint32_t addr) {
  asm volatile("ldmatrix.sync.aligned.m8n8.x4.shared.b16 {%0,%1,%2,%3}, [%4];"
    : "=r"(r[0]), "=r"(r[1]), "=r"(r[2]), "=r"(r[3]) : "r"(addr));
}
__device__ __forceinline__ void mma16816(float* d, const uint32_t* a, uint32_t b0, uint32_t b1) {
  asm volatile("mma.sync.aligned.m16n8k16.row.col.f32.f16.f16.f32 "
    "{%0,%1,%2,%3}, {%4,%5,%6,%7}, {%8,%9}, {%0,%1,%2,%3};"
    : "+f"(d[0]), "+f"(d[1]), "+f"(d[2]), "+f"(d[3])
    : "r"(a[0]), "r"(a[1]), "r"(a[2]), "r"(a[3]), "r"(b0), "r"(b1));
}

__device__ __forceinline__ void load_stage_async(
    const __half* __restrict__ A, const __half* __restrict__ B,
    int bm, int bn, int K, int k0, uint32_t sb, int tid)
{
  const __half* srcs[2] = {A, B};
  const int rb[2] = {bm, bn};
#pragma unroll
  for (int a = 0; a < 2; a++) {
#pragma unroll
    for (int i = 0; i < 2; i++) {
      int idx = tid + i * 256;
      int r = idx >> 2, ch = idx & 3;
      const __half* g = srcs[a] + (size_t)(rb[a] + r) * K + k0 + ch * 8;
      uint32_t dst = sb + a * ABYTES + (uint32_t)(r * 80 + ch * 16);
      cpa16(dst, g);
    }
  }
}

__global__ __launch_bounds__(256, 2) void gemm_h_kernel(
    const __half* __restrict__ A, const __half* __restrict__ B,
    float* __restrict__ C, int M, int N, int K)
{
  extern __shared__ char sm[];
  const int tid = threadIdx.x, lane = tid & 31, wid = tid >> 5;
  const int warp_m = wid >> 2, warp_n = wid & 3;
  const int bm = blockIdx.y * 128, bn = blockIdx.x * 128;
  const uint32_t sbase = (uint32_t)__cvta_generic_to_shared(sm);

  float acc[4][4][4];
#pragma unroll
  for (int i = 0; i < 4; i++)
#pragma unroll
    for (int j = 0; j < 4; j++)
#pragma unroll
      for (int e = 0; e < 4; e++) acc[i][j][e] = 0.f;

  const int NT = K / 32;
#pragma unroll
  for (int p = 0; p < NSTAGE - 1; p++) {
    load_stage_async(A, B, bm, bn, K, p * 32, sbase + p * STAGEB, tid);
    CP_COMMIT();
  }

  const int arow  = warp_m * 64 + (lane & 15);
  const int acol0 = (lane >> 4) * 8;
  const int brow  = warp_n * 32 + (lane >> 4) * 8 + (lane & 7);
  const int bcol0 = ((lane >> 3) & 1) * 8;

  for (int kt = 0; kt < NT; kt++) {
    CP_WAIT(NSTAGE - 2);
    __syncthreads();
    {
      int knext = kt + NSTAGE - 1;
      int kc = knext < NT ? knext : NT - 1;
      load_stage_async(A, B, bm, bn, K, kc * 32, sbase + (knext & (NSTAGE - 1)) * STAGEB, tid);
      CP_COMMIT();
    }
    const uint32_t stb = sbase + (kt & (NSTAGE - 1)) * STAGEB;
    const uint32_t aoff = stb;
    const uint32_t boff = stb + ABYTES;
#pragma unroll
    for (int kk = 0; kk < 32; kk += 16) {
      uint32_t af[4][4], bf[2][4];
#pragma unroll
      for (int mt = 0; mt < 4; mt++) {
        uint32_t ab = (uint32_t)(((arow + mt * 16) * GSTRIDE + kk + acol0) * 2);
        ldsm4(af[mt], aoff + ab);
      }
#pragma unroll
      for (int p = 0; p < 2; p++) {
        uint32_t bb = (uint32_t)(((brow + p * 16) * GSTRIDE + kk + bcol0) * 2);
        ldsm4(bf[p], boff + bb);
      }
#pragma unroll
      for (int mt = 0; mt < 4; mt++)
#pragma unroll
        for (int nt = 0; nt < 4; nt++) {
          const uint32_t* bp = bf[nt >> 1];
          int bi = (nt & 1) * 2;
          mma16816(acc[mt][nt], af[mt], bp[bi], bp[bi + 1]);
        }
    }
  }
  __syncthreads();
  const int row0 = bm + warp_m * 64 + (lane >> 2);
  const int col0 = bn + warp_n * 32 + (lane & 3) * 2;
#pragma unroll
  for (int mt = 0; mt < 4; mt++)
#pragma unroll
    for (int nt = 0; nt < 4; nt++) {
      int r = row0 + mt * 16;
      int c = col0 + nt * 8;
      *(float2*)(C + (size_t)r * N + c)       = make_float2(acc[mt][nt][0], acc[mt][nt][1]);
      *(float2*)(C + (size_t)(r + 8) * N + c) = make_float2(acc[mt][nt][2], acc[mt][nt][3]);
    }
}

// -------------------- beta = sigmoid(hs @ Wb^T), [B,H,L] --------------------
__global__ __launch_bounds__(256) void beta_kernel(
    const float* __restrict__ hs, const float* __restrict__ Wb, float* __restrict__ beta)
{
  int bl = blockIdx.x;
  int b = bl / LL, l = bl % LL;
  int w = threadIdx.x >> 5, lane = threadIdx.x & 31;
  const float* x = hs + (size_t)bl * DDIM;
  const float* wb = Wb + (size_t)w * DDIM;
  float s = 0.f;
  for (int d = lane; d < DDIM; d += 32) s += x[d] * wb[d];
#pragma unroll
  for (int o = 16; o; o >>= 1) s += __shfl_xor_sync(0xffffffffu, s, o);
  if (lane == 0)
    beta[((size_t)b * HH + w) * LL + l] = 1.f / (1.f + expf(-s));
}

// -------- conv + SiLU (+l2norm); mode0: +fp16 row copy (q); mode1: +fp16 transposed (k) ----
__global__ __launch_bounds__(256) void conv_kernel(
    const float* __restrict__ pre, const float* __restrict__ cw,
    float* __restrict__ out, __half* __restrict__ outh, int mode)
{
  int blk = blockIdx.x;
  int lt = blk & (LL / 8 - 1);
  int bh = blk >> 9;
  int h = bh % HH, b = bh / HH;
  int w = threadIdx.x >> 5, lane = threadIdx.x & 31;
  int l = lt * 8 + w;
  const float* base = pre + ((size_t)b * LL) * DDIM + h * DH;
  float y[2][4];
  float ss = 0.f;
  const float4 zero4 = make_float4(0, 0, 0, 0);
#pragma unroll
  for (int j = 0; j < 2; j++) {
    int dd = lane * 4 + j * 128;
    int c = h * DH + dd;
    float4 x0 = *(const float4*)(base + (size_t)l * DDIM + dd);
    float4 x1 = (l >= 1) ? *(const float4*)(base + (size_t)(l - 1) * DDIM + dd) : zero4;
    float4 x2 = (l >= 2) ? *(const float4*)(base + (size_t)(l - 2) * DDIM + dd) : zero4;
    float4 x3 = (l >= 3) ? *(const float4*)(base + (size_t)(l - 3) * DDIM + dd) : zero4;
    const float xs[4][4] = {{x0.x, x1.x, x2.x, x3.x}, {x0.y, x1.y, x2.y, x3.y},
                            {x0.z, x1.z, x2.z, x3.z}, {x0.w, x1.w, x2.w, x3.w}};
#pragma unroll
    for (int ci = 0; ci < 4; ci++) {
      float4 cv = *(const float4*)(cw + (size_t)(c + ci) * 4);
      float acc = xs[ci][0] * cv.w + xs[ci][1] * cv.z + xs[ci][2] * cv.y + xs[ci][3] * cv.x;
      float yy = acc / (1.f + expf(-acc));
      y[j][ci] = yy;
      ss += yy * yy;
    }
  }
  float scale = 1.f;
  if (mode < 2) {
#pragma unroll
    for (int o = 16; o; o >>= 1) ss += __shfl_xor_sync(0xffffffffu, ss, o);
    scale = rsqrtf(ss + 1e-6f);
    if (mode == 0) scale *= 0.0625f;
  }
  size_t ob = (((size_t)b * HH + h) * LL + l) * DH;
  float* op = out + ob;
  int cch = l >> 6, tloc = l & 63;
  __half* tp = outh + ((size_t)(b * HH + h) * NC + cch) * (DH * BT);
#pragma unroll
  for (int j = 0; j < 2; j++) {
    int dd = lane * 4 + j * 128;
    float4 yv = make_float4(y[j][0] * scale, y[j][1] * scale,
                            y[j][2] * scale, y[j][3] * scale);
    *(float4*)(op + dd) = yv;
    if (mode == 0) {
      uint2 hv;
      hv.x = h2(yv.x, yv.y);
      hv.y = h2(yv.z, yv.w);
      *(uint2*)(outh + ob + dd) = hv;
    } else if (mode == 1) {
      tp[(dd + 0) * BT + tloc] = __float2half_rn(yv.x);
      tp[(dd + 1) * BT + tloc] = __float2half_rn(yv.y);
      tp[(dd + 2) * BT + tloc] = __float2half_rn(yv.z);
      tp[(dd + 3) * BT + tloc] = __float2half_rn(yv.w);
    }
  }
}

// -------------------- per-chunk triangular solve; W stored fp16 --------------------
#define SOLVE_SMEM ((3*64*QS + 64*64 + 64) * 4)
__global__ __launch_bounds__(512) void solve_kernel(
    const float* __restrict__ kt, const float* __restrict__ vt,
    const float* __restrict__ beta, __half* __restrict__ Wh_g, float* __restrict__ Ut)
{
  extern __shared__ float sh[];
  float* sk = sh;
  float* sw = sk + 64 * QS;
  float* su = sw + 64 * QS;
  float* sM = su + 64 * QS;
  float* sbeta = sM + 64 * 64;
  int blk = blockIdx.x;
  int c = blk % NC, bh = blk / NC;
  size_t base = ((size_t)bh * LL + (size_t)c * BT) * DH;
  int tid = threadIdx.x;

  if (tid < 64) sbeta[tid] = beta[(size_t)bh * LL + c * BT + tid];
  __syncthreads();
  for (int i = tid; i < 4096; i += 512) {
    int t = i >> 6, dd = (i & 63) * 4;
    float bt = sbeta[t];
    float4 kv = *(const float4*)(kt + base + (size_t)t * DH + dd);
    float4 vv = *(const float4*)(vt + base + (size_t)t * DH + dd);
    *(float4*)&sk[t * QS + dd] = kv;
    *(float4*)&sw[t * QS + dd] = make_float4(kv.x * bt, kv.y * bt, kv.z * bt, kv.w * bt);
    *(float4*)&su[t * QS + dd] = make_float4(vv.x * bt, vv.y * bt, vv.z * bt, vv.w * bt);
  }
  __syncthreads();
  {
    int tp = tid >> 4, sb = tid & 15;
    int t0 = tp * 2, t1 = t0 + 1;
    unsigned long long acc[2][4];
#pragma unroll
    for (int ti = 0; ti < 2; ti++)
#pragma unroll
      for (int si = 0; si < 4; si++) acc[ti][si] = 0;
    if (sb < t1) {
      const float* q0 = &sw[t0 * QS];
      const float* q1 = &sw[t1 * QS];
#pragma unroll 2
      for (int d = 0; d < DH; d += 4) {
        ulonglong2 a0 = *(const ulonglong2*)(q0 + d);
        ulonglong2 a1 = *(const ulonglong2*)(q1 + d);
#pragma unroll
        for (int si = 0; si < 4; si++) {
          ulonglong2 kv = *(const ulonglong2*)(&sk[(sb + si * 16) * QS + d]);
          fma2(acc[0][si], a0.x, kv.x); fma2(acc[0][si], a0.y, kv.y);
          fma2(acc[1][si], a1.x, kv.x); fma2(acc[1][si], a1.y, kv.y);
        }
      }
    }
#pragma unroll
    for (int ti = 0; ti < 2; ti++)
#pragma unroll
      for (int si = 0; si < 4; si++) {
        int t = t0 + ti, s = sb + si * 16;
        float x0, x1;
        unpack2(acc[ti][si], x0, x1);
        sM[t * 64 + s] = (s < t) ? (x0 + x1) : 0.f;
      }
  }
  __syncthreads();
  if (tid < 128) {
    int d = tid * 2;
    for (int t = 1; t < BT; t++) {
      unsigned long long acc = 0;
      const float* Mr = &sM[t * 64];
      for (int s = 0; s < t; s++)
        fma2(acc, pack2dup(Mr[s]), *(const unsigned long long*)&sw[s * QS + d]);
      float a0, a1;
      unpack2(acc, a0, a1);
      sw[t * QS + d]     -= a0;
      sw[t * QS + d + 1] -= a1;
    }
  } else if (tid < 256) {
    int d = (tid - 128) * 2;
    for (int t = 1; t < BT; t++) {
      unsigned long long acc = 0;
      const float* Mr = &sM[t * 64];
      for (int s = 0; s < t; s++)
        fma2(acc, pack2dup(Mr[s]), *(const unsigned long long*)&su[s * QS + d]);
      float a0, a1;
      unpack2(acc, a0, a1);
      su[t * QS + d]     -= a0;
      su[t * QS + d + 1] -= a1;
    }
  }
  __syncthreads();
  for (int i = tid; i < 4096; i += 512) {
    int t = i >> 6, dd = (i & 63) * 4;
    float4 wv = *(float4*)&sw[t * QS + dd];
    uint2 hv;
    hv.x = h2(wv.x, wv.y);
    hv.y = h2(wv.z, wv.w);
    *(uint2*)(Wh_g + base + (size_t)t * DH + dd) = hv;
    *(float4*)(Ut + base + (size_t)t * DH + dd) = *(float4*)&su[t * QS + dd];
  }
}

// -------------------- attn = tril(q k^T) -> fp16 --------------------
#define ATTN_SMEM (2*64*QS*4)
__global__ __launch_bounds__(512) void attn_kernel(
    const float* __restrict__ qt, const float* __restrict__ kt, __half* __restrict__ att)
{
  extern __shared__ float sh[];
  float* sq = sh;
  float* sk = sq + 64 * QS;
  int blk = blockIdx.x;
  int c = blk % NC, bh = blk / NC;
  size_t base = ((size_t)bh * LL + (size_t)c * BT) * DH;
  int tid = threadIdx.x;
  for (int i = tid; i < 4096; i += 512) {
    int t = i >> 6, dd = (i & 63) * 4;
    *(float4*)&sq[t * QS + dd] = *(const float4*)(qt + base + (size_t)t * DH + dd);
    *(float4*)&sk[t * QS + dd] = *(const float4*)(kt + base + (size_t)t * DH + dd);
  }
  __syncthreads();
  __half* ap = att + (size_t)blk * (BT * BT);
  int tp = tid >> 4, sb = tid & 15;
  int t0 = tp * 2, t1 = t0 + 1;
  unsigned long long acc[2][4];
#pragma unroll
  for (int ti = 0; ti < 2; ti++)
#pragma unroll
    for (int si = 0; si < 4; si++) acc[ti][si] = 0;
  if (sb <= t1) {
    const float* q0 = &sq[t0 * QS];
    const float* q1 = &sq[t1 * QS];
#pragma unroll 2
    for (int d = 0; d < DH; d += 4) {
      ulonglong2 a0 = *(const ulonglong2*)(q0 + d);
      ulonglong2 a1 = *(const ulonglong2*)(q1 + d);
#pragma unroll
      for (int si = 0; si < 4; si++) {
        ulonglong2 kv = *(const ulonglong2*)(&sk[(sb + si * 16) * QS + d]);
        fma2(acc[0][si], a0.x, kv.x); fma2(acc[0][si], a0.y, kv.y);
        fma2(acc[1][si], a1.x, kv.x); fma2(acc[1][si], a1.y, kv.y);
      }
    }
  }
#pragma unroll
  for (int ti = 0; ti < 2; ti++)
#pragma unroll
    for (int si = 0; si < 4; si++) {
      int t = t0 + ti, s = sb + si * 16;
      float x0, x1;
      unpack2(acc[ti][si], x0, x1);
      ap[t * 64 + s] = __float2half_rn((s <= t) ? (x0 + x1) : 0.f);
    }
}

// -------------------- scan: fp16 tiles, cp.async double buffer (q,w,T); k in regs ------
#define STG_Q 33792                              // 64 rows * 528 B
#define STG_T 9216                               // 64 rows * 144 B
#define STG_BYTES (2*STG_Q + STG_T)              // 76800
#define SCAN_SMEM (36864 + 9216 + 18432 + 2*STG_BYTES)   // 218112

__device__ __forceinline__ void scan_stage_async(
    const __half* __restrict__ qh, const __half* __restrict__ wh,
    const __half* __restrict__ th,
    size_t base, size_t abase, uint32_t sb, int tid)
{
#pragma unroll
  for (int it = 0; it < 8; it++) {
    int i = tid + it * 512;                  // 0..4095
    int a = i >> 11;                         // 0: q, 1: w
    int r = (i >> 5) & 63;
    int d8 = i & 31;
    const __half* src = (a ? wh : qh) + base + (size_t)r * DH + d8 * 8;
    cpa16(sb + a * STG_Q + (uint32_t)(r * 528 + d8 * 16), src);
  }
  {
    int tt = tid >> 3, cc = tid & 7;
    cpa16(sb + 2 * STG_Q + (uint32_t)(tt * 144 + cc * 16), th + abase + tt * 64 + cc * 8);
  }
}

__global__ __launch_bounds__(512) void scan_kernel(
    const __half* __restrict__ qh, const __half* __restrict__ khT,
    const __half* __restrict__ wh, const float* __restrict__ ut,
    const __half* __restrict__ atth, float* __restrict__ og)
{
  extern __shared__ char smc[];
  float* S  = (float*)smc;                       // [256][36]
  float* Un = (float*)(smc + 36864);             // [64][36]
  float* P  = (float*)(smc + 46080);             // [2][64][36]
  char*  stg = smc + 64512;
  const uint32_t stg_s0 = (uint32_t)__cvta_generic_to_shared(stg);

  int blk = blockIdx.x;
  int vb = blk & 7;
  int bh = blk >> 3;
  int b = bh / HH, h = bh % HH;
  int tid = threadIdx.x;
  int lane = tid & 31, wrp = tid >> 5;
  int fr = lane >> 2;
  int fc = (lane & 3) * 2;
  int dw = wrp * 16;
  int which = wrp >> 3;
  int sub = wrp & 7;
  int ttile = sub & 3;
  int khalf = sub >> 2;
  int tb = ttile * 16;
  int cmt = wrp >> 2;
  int cnt = wrp & 3;
  int ctb = cmt * 16, cnb = cnt * 8;

  for (int i = tid; i < 256 * SCS; i += 512) S[i] = 0.f;
  __syncthreads();

  // prologue: stage chunk 0
  {
    size_t base0 = ((size_t)bh * LL) * DH;
    size_t abase0 = (size_t)bh * NC * 4096;
    scan_stage_async(qh, wh, atth, base0, abase0, stg_s0, tid);
    CP_COMMIT();
  }

  for (int c = 0; c < NC; c++) {
    CP_WAIT(0);
    __syncthreads();
    size_t base = ((size_t)bh * LL + (size_t)c * BT) * DH;
    char* sb_c = stg + (c & 1) * STG_BYTES;
    const __half* Qh = (const __half*)sb_c;
    const __half* Wh = (const __half*)(sb_c + STG_Q);
    const __half* Th = (const __half*)(sb_c + 2 * STG_Q);

    // register-prefetch k fragments for Phase D (transposed khT: [d][t])
    uint32_t ka[4][4];
    {
      const __half* ktile = khT + ((size_t)bh * NC + c) * (DH * BT);
      const __half* kr0 = ktile + (dw + fr) * BT;
      const __half* kr1 = ktile + (dw + fr + 8) * BT;
#pragma unroll
      for (int s = 0; s < 4; s++) {
        int kk = s * 16;
        ka[s][0] = *(const uint32_t*)(kr0 + kk + fc);
        ka[s][1] = *(const uint32_t*)(kr1 + kk + fc);
        ka[s][2] = *(const uint32_t*)(kr0 + kk + fc + 8);
        ka[s][3] = *(const uint32_t*)(kr1 + kk + fc + 8);
      }
    }

    // prefetch chunk c+1 stage
    if (c + 1 < NC) {
      size_t basen = ((size_t)bh * LL + (size_t)(c + 1) * BT) * DH;
      size_t abasen = ((size_t)bh * NC + (c + 1)) * 4096;
      scan_stage_async(qh, wh, atth, basen, abasen,
                       stg_s0 + ((c + 1) & 1) * STG_BYTES, tid);
      CP_COMMIT();
    }

    // ---- Phase A: MMA partials of q@S / w@S ----
    float acc[4][4];
#pragma unroll
    for (int vt = 0; vt < 4; vt++)
#pragma unroll
      for (int e = 0; e < 4; e++) acc[vt][e] = 0.f;
    {
      const __half* Ab = which ? Wh : Qh;
      const __half* ar0 = Ab + (tb + fr) * QHS;
      const __half* ar1 = Ab + (tb + fr + 8) * QHS;
      int k0 = khalf * 128;
#pragma unroll
      for (int kk = k0; kk < k0 + 128; kk += 16) {
        uint32_t a[4];
        a[0] = *(const uint32_t*)(ar0 + kk + fc);
        a[1] = *(const uint32_t*)(ar1 + kk + fc);
        a[2] = *(const uint32_t*)(ar0 + kk + fc + 8);
        a[3] = *(const uint32_t*)(ar1 + kk + fc + 8);
        const float* s0 = &S[(kk + fc) * SCS];
        const float* s1 = &S[(kk + fc + 1) * SCS];
        const float* s8 = &S[(kk + fc + 8) * SCS];
        const float* s9 = &S[(kk + fc + 9) * SCS];
#pragma unroll
        for (int vt = 0; vt < 4; vt++) {
          int vn = vt * 8 + fr;
          uint32_t b0 = h2(s0[vn], s1[vn]);
          uint32_t b1 = h2(s8[vn], s9[vn]);
          mma16816(acc[vt], a, b0, b1);
        }
      }
    }
    float* Pp = &P[which * 64 * SCS + tb * SCS];
    if (khalf == 1) {
#pragma unroll
      for (int vt = 0; vt < 4; vt++) {
        *(float2*)&Pp[fr * SCS + vt * 8 + fc]       = make_float2(acc[vt][0], acc[vt][1]);
        *(float2*)&Pp[(fr + 8) * SCS + vt * 8 + fc] = make_float2(acc[vt][2], acc[vt][3]);
      }
    }
    __syncthreads();

    // ---- Phase B: khalf0 combine (u from global, as in R11) ----
    if (khalf == 0) {
      if (which == 0) {
#pragma unroll
        for (int vt = 0; vt < 4; vt++) {
          float2 p0 = *(float2*)&Pp[fr * SCS + vt * 8 + fc];
          float2 p1 = *(float2*)&Pp[(fr + 8) * SCS + vt * 8 + fc];
          *(float2*)&Pp[fr * SCS + vt * 8 + fc] =
              make_float2(acc[vt][0] + p0.x, acc[vt][1] + p0.y);
          *(float2*)&Pp[(fr + 8) * SCS + vt * 8 + fc] =
              make_float2(acc[vt][2] + p1.x, acc[vt][3] + p1.y);
        }
      } else {
        size_t ub0 = base + (size_t)(tb + fr) * DH + vb * 32;
        size_t ub1 = base + (size_t)(tb + fr + 8) * DH + vb * 32;
#pragma unroll
        for (int vt = 0; vt < 4; vt++) {
          float2 p0 = *(float2*)&Pp[fr * SCS + vt * 8 + fc];
          float2 p1 = *(float2*)&Pp[(fr + 8) * SCS + vt * 8 + fc];
          float2 u0 = *(const float2*)(ut + ub0 + vt * 8 + fc);
          float2 u1 = *(const float2*)(ut + ub1 + vt * 8 + fc);
          *(float2*)&Un[(tb + fr) * SCS + vt * 8 + fc] =
              make_float2(u0.x - (acc[vt][0] + p0.x), u0.y - (acc[vt][1] + p0.y));
          *(float2*)&Un[(tb + fr + 8) * SCS + vt * 8 + fc] =
              make_float2(u1.x - (acc[vt][2] + p1.x), u1.y - (acc[vt][3] + p1.y));
        }
      }
    }
    __syncthreads();

    // ---- Phase C: o = q@S + T @ Un via fp16 MMA ----
    {
      float cacc[4] = {0.f, 0.f, 0.f, 0.f};
#pragma unroll
      for (int kk = 0; kk < BT; kk += 16) {
        const __half* t0p = Th + (ctb + fr) * THS + kk;
        const __half* t1p = Th + (ctb + fr + 8) * THS + kk;
        uint32_t a[4];
        a[0] = *(const uint32_t*)(t0p + fc);
        a[1] = *(const uint32_t*)(t1p + fc);
        a[2] = *(const uint32_t*)(t0p + fc + 8);
        a[3] = *(const uint32_t*)(t1p + fc + 8);
        const float* un0 = &Un[(kk + fc) * SCS];
        const float* un1 = &Un[(kk + fc + 1) * SCS];
        const float* un8 = &Un[(kk + fc + 8) * SCS];
        const float* un9 = &Un[(kk + fc + 9) * SCS];
        int n = cnb + fr;
        uint32_t b0 = h2(un0[n], un1[n]);
        uint32_t b1 = h2(un8[n], un9[n]);
        mma16816(cacc, a, b0, b1);
      }
      int r0 = ctb + fr, r1 = ctb + fr + 8;
      float2 p0 = *(const float2*)&P[r0 * SCS + cnb + fc];
      float2 p1 = *(const float2*)&P[r1 * SCS + cnb + fc];
      size_t o0 = (((size_t)b * LL + (size_t)c * BT + r0) * HH + h) * DH + vb * 32 + cnb + fc;
      size_t o1 = (((size_t)b * LL + (size_t)c * BT + r1) * HH + h) * DH + vb * 32 + cnb + fc;
      *(float2*)&og[o0] = make_float2(p0.x + cacc[0], p0.y + cacc[1]);
      *(float2*)&og[o1] = make_float2(p1.x + cacc[2], p1.y + cacc[3]);
    }

    // ---- Phase D: S += k^T @ u_new via fp16 MMA (ka regs) ----
    {
      float sacc[4][4];
#pragma unroll
      for (int vt = 0; vt < 4; vt++)
#pragma unroll
        for (int e = 0; e < 4; e++) sacc[vt][e] = 0.f;
#pragma unroll
      for (int s = 0; s < 4; s++) {
        int kk = s * 16;
        const float* un0 = &Un[(kk + fc) * SCS];
        const float* un1 = &Un[(kk + fc + 1) * SCS];
        const float* un8 = &Un[(kk + fc + 8) * SCS];
        const float* un9 = &Un[(kk + fc + 9) * SCS];
#pragma unroll
        for (int vt = 0; vt < 4; vt++) {
          uint32_t b0 = h2(un0[vt * 8 + fr], un1[vt * 8 + fr]);
          uint32_t b1 = h2(un8[vt * 8 + fr], un9[vt * 8 + fr]);
          mma16816(sacc[vt], ka[s], b0, b1);
        }
      }
#pragma unroll
      for (int vt = 0; vt < 4; vt++) {
        float2* sp0 = (float2*)&S[(dw + fr) * SCS + vt * 8 + fc];
        float2 v0r = *sp0;
        v0r.x += sacc[vt][0]; v0r.y += sacc[vt][1];
        *sp0 = v0r;
        float2* sp1 = (float2*)&S[(dw + fr + 8) * SCS + vt * 8 + fc];
        float2 v1r = *sp1;
        v1r.x += sacc[vt][2]; v1r.y += sacc[vt][3];
        *sp1 = v1r;
      }
    }
    __syncthreads();
  }
}

// -------------------- per-head RMSNorm * g_norm -> fp16 output --------------------
__global__ __launch_bounds__(256) void rms_kernel(
    const float* __restrict__ og, const float* __restrict__ gn, __half* __restrict__ on)
{
  int w = threadIdx.x >> 5, lane = threadIdx.x & 31;
  size_t idx = (size_t)blockIdx.x * 8 + w;
  const float* ip = og + idx * DH;
  float2 v[4];
  float ss = 0.f;
#pragma unroll
  for (int j = 0; j < 4; j++) {
    v[j] = *(const float2*)(ip + lane * 2 + j * 64);
    ss += v[j].x * v[j].x + v[j].y * v[j].y;
  }
#pragma unroll
  for (int o = 16; o; o >>= 1) ss += __shfl_xor_sync(0xffffffffu, ss, o);
  float scale = rsqrtf(ss * (1.f / DH) + 1e-5f);
  __half* op = on + idx * DH;
#pragma unroll
  for (int j = 0; j < 4; j++) {
    int e = lane * 2 + j * 64;
    float2 g = *(const float2*)(gn + e);
    __half2 hv = __floats2half2_rn(v[j].x * scale * g.x, v[j].y * scale * g.y);
    *(__half2*)(op + e) = hv;
  }
}

// -------------------- host launch --------------------
extern "C" void kernel_launch(void* const* d_in, const int* in_sizes, int n_in,
                              void* d_out, int out_size)
{
  const float* hs = (const float*)d_in[0];
  const float* Wq = (const float*)d_in[1];
  const float* Wk = (const float*)d_in[2];
  const float* Wv = (const float*)d_in[3];
  const float* Wb = (const float*)d_in[4];
  const float* cq = (const float*)d_in[5];
  const float* ck = (const float*)d_in[6];
  const float* cv = (const float*)d_in[7];
  const float* gn = (const float*)d_in[8];
  const float* Wo = (const float*)d_in[9];
  float* out = (float*)d_out;

  float *preq, *prek, *prev, *qt, *kt, *vt, *ut, *beta, *og;
  __half *qh, *khT, *ws, *atth, *ah, *wh;
  cudaGetSymbolAddress((void**)&preq, g_preq);
  cudaGetSymbolAddress((void**)&prek, g_prek);
  cudaGetSymbolAddress((void**)&prev, g_prev);
  cudaGetSymbolAddress((void**)&qt, g_qt);
  cudaGetSymbolAddress((void**)&kt, g_kt);
  cudaGetSymbolAddress((void**)&vt, g_vt);
  cudaGetSymbolAddress((void**)&ut, g_ut);
  cudaGetSymbolAddress((void**)&beta, g_beta);
  cudaGetSymbolAddress((void**)&og, g_og);
  cudaGetSymbolAddress((void**)&qh, g_qh);
  cudaGetSymbolAddress((void**)&khT, g_khT);
  cudaGetSymbolAddress((void**)&ws, g_ws);
  cudaGetSymbolAddress((void**)&atth, g_atth);
  cudaGetSymbolAddress((void**)&ah, g_ah);
  cudaGetSymbolAddress((void**)&wh, g_wh);

  cudaFuncSetAttribute(gemm_h_kernel, cudaFuncAttributeMaxDynamicSharedMemorySize, GEMM_SMEM);
  cudaFuncSetAttribute(solve_kernel, cudaFuncAttributeMaxDynamicSharedMemorySize, SOLVE_SMEM);
  cudaFuncSetAttribute(attn_kernel, cudaFuncAttributeMaxDynamicSharedMemorySize, ATTN_SMEM);
  cudaFuncSetAttribute(scan_kernel, cudaFuncAttributeMaxDynamicSharedMemorySize, SCAN_SMEM);

  dim3 gg(DDIM / 128, (BB * LL) / 128);
  const int actN4 = BLD / 4, wN4 = DD2 / 4;

  cvt_kernel<<<(actN4 + 255) / 256, 256>>>(hs, ah, actN4);
  cvt_kernel<<<(wN4 + 255) / 256, 256>>>(Wq, wh + 0 * (size_t)DD2, wN4);
  cvt_kernel<<<(wN4 + 255) / 256, 256>>>(Wk, wh + 1 * (size_t)DD2, wN4);
  gemm_h_kernel<<<gg, 256, GEMM_SMEM>>>(ah, wh + 0 * (size_t)DD2, preq, BB * LL, DDIM, DDIM);
  cvt_kernel<<<(wN4 + 255) / 256, 256>>>(Wv, wh + 2 * (size_t)DD2, wN4);
  cvt_kernel<<<(wN4 + 255) / 256, 256>>>(Wo, wh + 3 * (size_t)DD2, wN4);
  gemm_h_kernel<<<gg, 256, GEMM_SMEM>>>(ah, wh + 1 * (size_t)DD2, prek, BB * LL, DDIM, DDIM);
  gemm_h_kernel<<<gg, 256, GEMM_SMEM>>>(ah, wh + 2 * (size_t)DD2, prev, BB * LL, DDIM, DDIM);
  beta_kernel<<<BB * LL, 256>>>(hs, Wb, beta);

  conv_kernel<<<BB * HH * (LL / 8), 256>>>(preq, cq, qt, qh, 0);
  conv_kernel<<<BB * HH * (LL / 8), 256>>>(prek, ck, kt, khT, 1);
  conv_kernel<<<BB * HH * (LL / 8), 256>>>(prev, cv, vt, (__half*)0, 2);

  solve_kernel<<<BB * HH * NC, 512, SOLVE_SMEM>>>(kt, vt, beta, ws, ut);
  attn_kernel<<<BB * HH * NC, 512, ATTN_SMEM>>>(qt, kt, atth);
  scan_kernel<<<BB * HH * 8, 512, SCAN_SMEM>>>(qh, khT, ws, ut, atth, og);

  rms_kernel<<<BB * LL * HH / 8, 256>>>(og, gn, ah);
  gemm_h_kernel<<<gg, 256, GEMM_SMEM>>>(ah, wh + 3 * (size_t)DD2, out, BB * LL, DDIM, DDIM);
}

// round 14
// speedup vs baseline: 4.5137x; 1.0151x over previous
#include <cuda_runtime.h>
#include <cuda_fp16.h>
#include <math.h>
#include <stdint.h>

#define BB 2
#define LL 4096
#define DDIM 2048
#define HH 8
#define DH 256
#define BT 64
#define NC 64          // LL / BT
#define BLD (BB*LL*DDIM)
#define DD2 (DDIM*DDIM)
#define QS 260         // padded fp32 tile stride (solve/attn)
#define SCS 36         // S / Un / P row stride (floats)
#define QHS 264        // fp16 staged tile stride (halfs): 256 data + 8 pad = 528 B
#define THS 72         // fp16 T stride (halfs)

// -------------------- scratch (device globals; no allocation) --------------------
__device__ float g_preq[BLD];
__device__ float g_prek[BLD];
__device__ float g_prev[BLD];
__device__ float g_qt[BLD];       // fp32 q (attn)
__device__ float g_kt[BLD];       // fp32 k (solve, attn)
__device__ float g_vt[BLD];
__device__ float g_ut[BLD];
__device__ float g_beta[BB*HH*LL];
__device__ float g_og[BLD];
__device__ __align__(128) __half g_qh[BLD];     // fp16 q (scan, row-major [t][d])
__device__ __align__(128) __half g_khT[BLD];    // fp16 k transposed per chunk: [bh][c][d][t]
__device__ __align__(128) __half g_ws[BLD];     // fp16 W (scan)
__device__ __align__(128) __half g_atth[(size_t)BB*HH*NC*BT*BT];
__device__ __align__(128) __half g_ah[BLD];     // activation fp16 (GEMM A)
__device__ __align__(128) __half g_wh[4*DD2];   // weights fp16

// -------------------- helpers --------------------
__device__ __forceinline__ unsigned long long pack2dup(float x) {
  unsigned long long r;
  asm("mov.b64 %0, {%1,%1};" : "=l"(r) : "f"(x));
  return r;
}
__device__ __forceinline__ void unpack2(unsigned long long v, float& x, float& y) {
  asm("mov.b64 {%0,%1}, %2;" : "=f"(x), "=f"(y) : "l"(v));
}
__device__ __forceinline__ void fma2(unsigned long long& d,
                                     unsigned long long a, unsigned long long b) {
  asm("fma.rn.f32x2 %0, %1, %2, %0;" : "+l"(d) : "l"(a), "l"(b));
}
__device__ __forceinline__ uint32_t h2(float x, float y) {
  __half2 h = __floats2half2_rn(x, y);
  return *(uint32_t*)&h;
}

// ==================== convert fp32 -> fp16 ====================
__global__ __launch_bounds__(256) void cvt_kernel(
    const float* __restrict__ x, __half* __restrict__ h, int n4)
{
  int i = blockIdx.x * blockDim.x + threadIdx.x;
  if (i >= n4) return;
  float4 v = *(const float4*)(x + (size_t)i * 4);
  __half2* hp = (__half2*)(h + (size_t)i * 4);
  hp[0] = __floats2half2_rn(v.x, v.y);
  hp[1] = __floats2half2_rn(v.z, v.w);
}

// ==================== fp16 HMMA GEMM, BK=32, 4-stage cp.async ====================
#define GSTRIDE 40
#define GTILE (128*GSTRIDE)
#define ABYTES (GTILE*2)
#define STAGEB (2*ABYTES)
#define NSTAGE 4
#define GEMM_SMEM (NSTAGE*STAGEB)

__device__ __forceinline__ void cpa16(uint32_t dst, const void* src) {
  asm volatile("cp.async.ca.shared.global [%0], [%1], 16;" :: "r"(dst), "l"(src));
}
#define CP_COMMIT() asm volatile("cp.async.commit_group;" ::: "memory")
#define CP_WAIT(n)  asm volatile("cp.async.wait_group %0;" :: "n"(n) : "memory")

__device__ __forceinline__ void ldsm4(uint32_t* r, uint32_t addr) {
  asm volatile("ldmatrix.sync.aligned.m8n8.x4.shared.b16 {%0,%1,%2,%3}, [%4];"
    : "=r"(r[0]), "=r"(r[1]), "=r"(r[2]), "=r"(r[3]) : "r"(addr));
}
__device__ __forceinline__ void mma16816(float* d, const uint32_t* a, uint32_t b0, uint32_t b1) {
  asm volatile("mma.sync.aligned.m16n8k16.row.col.f32.f16.f16.f32 "
    "{%0,%1,%2,%3}, {%4,%5,%6,%7}, {%8,%9}, {%0,%1,%2,%3};"
    : "+f"(d[0]), "+f"(d[1]), "+f"(d[2]), "+f"(d[3])
    : "r"(a[0]), "r"(a[1]), "r"(a[2]), "r"(a[3]), "r"(b0), "r"(b1));
}

__device__ __forceinline__ void load_stage_async(
    const __half* __restrict__ A, const __half* __restrict__ B,
    int bm, int bn, int K, int k0, uint32_t sb, int tid)
{
  const __half* srcs[2] = {A, B};
  const int rb[2] = {bm, bn};
#pragma unroll
  for (int a = 0; a < 2; a++) {
#pragma unroll
    for (int i = 0; i < 2; i++) {
      int idx = tid + i * 256;
      int r = idx >> 2, ch = idx & 3;
      const __half* g = srcs[a] + (size_t)(rb[a] + r) * K + k0 + ch * 8;
      uint32_t dst = sb + a * ABYTES + (uint32_t)(r * 80 + ch * 16);
      cpa16(dst, g);
    }
  }
}

__global__ __launch_bounds__(256, 2) void gemm_h_kernel(
    const __half* __restrict__ A, const __half* __restrict__ B,
    float* __restrict__ C, int M, int N, int K)
{
  extern __shared__ char sm[];
  const int tid = threadIdx.x, lane = tid & 31, wid = tid >> 5;
  const int warp_m = wid >> 2, warp_n = wid & 3;
  const int bm = blockIdx.y * 128, bn = blockIdx.x * 128;
  const uint32_t sbase = (uint32_t)__cvta_generic_to_shared(sm);

  float acc[4][4][4];
#pragma unroll
  for (int i = 0; i < 4; i++)
#pragma unroll
    for (int j = 0; j < 4; j++)
#pragma unroll
      for (int e = 0; e < 4; e++) acc[i][j][e] = 0.f;

  const int NT = K / 32;
#pragma unroll
  for (int p = 0; p < NSTAGE - 1; p++) {
    load_stage_async(A, B, bm, bn, K, p * 32, sbase + p * STAGEB, tid);
    CP_COMMIT();
  }

  const int arow  = warp_m * 64 + (lane & 15);
  const int acol0 = (lane >> 4) * 8;
  const int brow  = warp_n * 32 + (lane >> 4) * 8 + (lane & 7);
  const int bcol0 = ((lane >> 3) & 1) * 8;

  for (int kt = 0; kt < NT; kt++) {
    CP_WAIT(NSTAGE - 2);
    __syncthreads();
    {
      int knext = kt + NSTAGE - 1;
      int kc = knext < NT ? knext : NT - 1;
      load_stage_async(A, B, bm, bn, K, kc * 32, sbase + (knext & (NSTAGE - 1)) * STAGEB, tid);
      CP_COMMIT();
    }
    const uint32_t stb = sbase + (kt & (NSTAGE - 1)) * STAGEB;
    const uint32_t aoff = stb;
    const uint32_t boff = stb + ABYTES;
#pragma unroll
    for (int kk = 0; kk < 32; kk += 16) {
      uint32_t af[4][4], bf[2][4];
#pragma unroll
      for (int mt = 0; mt < 4; mt++) {
        uint32_t ab = (uint32_t)(((arow + mt * 16) * GSTRIDE + kk + acol0) * 2);
        ldsm4(af[mt], aoff + ab);
      }
#pragma unroll
      for (int p = 0; p < 2; p++) {
        uint32_t bb = (uint32_t)(((brow + p * 16) * GSTRIDE + kk + bcol0) * 2);
        ldsm4(bf[p], boff + bb);
      }
#pragma unroll
      for (int mt = 0; mt < 4; mt++)
#pragma unroll
        for (int nt = 0; nt < 4; nt++) {
          const uint32_t* bp = bf[nt >> 1];
          int bi = (nt & 1) * 2;
          mma16816(acc[mt][nt], af[mt], bp[bi], bp[bi + 1]);
        }
    }
  }
  __syncthreads();
  const int row0 = bm + warp_m * 64 + (lane >> 2);
  const int col0 = bn + warp_n * 32 + (lane & 3) * 2;
#pragma unroll
  for (int mt = 0; mt < 4; mt++)
#pragma unroll
    for (int nt = 0; nt < 4; nt++) {
      int r = row0 + mt * 16;
      int c = col0 + nt * 8;
      *(float2*)(C + (size_t)r * N + c)       = make_float2(acc[mt][nt][0], acc[mt][nt][1]);
      *(float2*)(C + (size_t)(r + 8) * N + c) = make_float2(acc[mt][nt][2], acc[mt][nt][3]);
    }
}

// -------------------- beta = sigmoid(hs @ Wb^T), [B,H,L] --------------------
__global__ __launch_bounds__(256) void beta_kernel(
    const float* __restrict__ hs, const float* __restrict__ Wb, float* __restrict__ beta)
{
  int bl = blockIdx.x;
  int b = bl / LL, l = bl % LL;
  int w = threadIdx.x >> 5, lane = threadIdx.x & 31;
  const float* x = hs + (size_t)bl * DDIM;
  const float* wb = Wb + (size_t)w * DDIM;
  float s = 0.f;
  for (int d = lane; d < DDIM; d += 32) s += x[d] * wb[d];
#pragma unroll
  for (int o = 16; o; o >>= 1) s += __shfl_xor_sync(0xffffffffu, s, o);
  if (lane == 0)
    beta[((size_t)b * HH + w) * LL + l] = 1.f / (1.f + expf(-s));
}

// -------- conv + SiLU (+l2norm); mode0: +fp16 row copy (q); mode1: +fp16 transposed (k) ----
__global__ __launch_bounds__(256) void conv_kernel(
    const float* __restrict__ pre, const float* __restrict__ cw,
    float* __restrict__ out, __half* __restrict__ outh, int mode)
{
  int blk = blockIdx.x;
  int lt = blk & (LL / 8 - 1);
  int bh = blk >> 9;
  int h = bh % HH, b = bh / HH;
  int w = threadIdx.x >> 5, lane = threadIdx.x & 31;
  int l = lt * 8 + w;
  const float* base = pre + ((size_t)b * LL) * DDIM + h * DH;
  float y[2][4];
  float ss = 0.f;
  const float4 zero4 = make_float4(0, 0, 0, 0);
#pragma unroll
  for (int j = 0; j < 2; j++) {
    int dd = lane * 4 + j * 128;
    int c = h * DH + dd;
    float4 x0 = *(const float4*)(base + (size_t)l * DDIM + dd);
    float4 x1 = (l >= 1) ? *(const float4*)(base + (size_t)(l - 1) * DDIM + dd) : zero4;
    float4 x2 = (l >= 2) ? *(const float4*)(base + (size_t)(l - 2) * DDIM + dd) : zero4;
    float4 x3 = (l >= 3) ? *(const float4*)(base + (size_t)(l - 3) * DDIM + dd) : zero4;
    const float xs[4][4] = {{x0.x, x1.x, x2.x, x3.x}, {x0.y, x1.y, x2.y, x3.y},
                            {x0.z, x1.z, x2.z, x3.z}, {x0.w, x1.w, x2.w, x3.w}};
#pragma unroll
    for (int ci = 0; ci < 4; ci++) {
      float4 cv = *(const float4*)(cw + (size_t)(c + ci) * 4);
      float acc = xs[ci][0] * cv.w + xs[ci][1] * cv.z + xs[ci][2] * cv.y + xs[ci][3] * cv.x;
      float yy = acc / (1.f + expf(-acc));
      y[j][ci] = yy;
      ss += yy * yy;
    }
  }
  float scale = 1.f;
  if (mode < 2) {
#pragma unroll
    for (int o = 16; o; o >>= 1) ss += __shfl_xor_sync(0xffffffffu, ss, o);
    scale = rsqrtf(ss + 1e-6f);
    if (mode == 0) scale *= 0.0625f;
  }
  size_t ob = (((size_t)b * HH + h) * LL + l) * DH;
  float* op = out + ob;
  int cch = l >> 6, tloc = l & 63;
  __half* tp = outh + ((size_t)(b * HH + h) * NC + cch) * (DH * BT);
#pragma unroll
  for (int j = 0; j < 2; j++) {
    int dd = lane * 4 + j * 128;
    float4 yv = make_float4(y[j][0] * scale, y[j][1] * scale,
                            y[j][2] * scale, y[j][3] * scale);
    *(float4*)(op + dd) = yv;
    if (mode == 0) {
      uint2 hv;
      hv.x = h2(yv.x, yv.y);
      hv.y = h2(yv.z, yv.w);
      *(uint2*)(outh + ob + dd) = hv;
    } else if (mode == 1) {
      tp[(dd + 0) * BT + tloc] = __float2half_rn(yv.x);
      tp[(dd + 1) * BT + tloc] = __float2half_rn(yv.y);
      tp[(dd + 2) * BT + tloc] = __float2half_rn(yv.z);
      tp[(dd + 3) * BT + tloc] = __float2half_rn(yv.w);
    }
  }
}

// -------------------- per-chunk triangular solve; W stored fp16 --------------------
#define SOLVE_SMEM ((3*64*QS + 64*64 + 64) * 4)
__global__ __launch_bounds__(512) void solve_kernel(
    const float* __restrict__ kt, const float* __restrict__ vt,
    const float* __restrict__ beta, __half* __restrict__ Wh_g, float* __restrict__ Ut)
{
  extern __shared__ float sh[];
  float* sk = sh;
  float* sw = sk + 64 * QS;
  float* su = sw + 64 * QS;
  float* sM = su + 64 * QS;
  float* sbeta = sM + 64 * 64;
  int blk = blockIdx.x;
  int c = blk % NC, bh = blk / NC;
  size_t base = ((size_t)bh * LL + (size_t)c * BT) * DH;
  int tid = threadIdx.x;

  if (tid < 64) sbeta[tid] = beta[(size_t)bh * LL + c * BT + tid];
  __syncthreads();
  for (int i = tid; i < 4096; i += 512) {
    int t = i >> 6, dd = (i & 63) * 4;
    float bt = sbeta[t];
    float4 kv = *(const float4*)(kt + base + (size_t)t * DH + dd);
    float4 vv = *(const float4*)(vt + base + (size_t)t * DH + dd);
    *(float4*)&sk[t * QS + dd] = kv;
    *(float4*)&sw[t * QS + dd] = make_float4(kv.x * bt, kv.y * bt, kv.z * bt, kv.w * bt);
    *(float4*)&su[t * QS + dd] = make_float4(vv.x * bt, vv.y * bt, vv.z * bt, vv.w * bt);
  }
  __syncthreads();
  {
    int tp = tid >> 4, sb = tid & 15;
    int t0 = tp * 2, t1 = t0 + 1;
    unsigned long long acc[2][4];
#pragma unroll
    for (int ti = 0; ti < 2; ti++)
#pragma unroll
      for (int si = 0; si < 4; si++) acc[ti][si] = 0;
    if (sb < t1) {
      const float* q0 = &sw[t0 * QS];
      const float* q1 = &sw[t1 * QS];
#pragma unroll 2
      for (int d = 0; d < DH; d += 4) {
        ulonglong2 a0 = *(const ulonglong2*)(q0 + d);
        ulonglong2 a1 = *(const ulonglong2*)(q1 + d);
#pragma unroll
        for (int si = 0; si < 4; si++) {
          ulonglong2 kv = *(const ulonglong2*)(&sk[(sb + si * 16) * QS + d]);
          fma2(acc[0][si], a0.x, kv.x); fma2(acc[0][si], a0.y, kv.y);
          fma2(acc[1][si], a1.x, kv.x); fma2(acc[1][si], a1.y, kv.y);
        }
      }
    }
#pragma unroll
    for (int ti = 0; ti < 2; ti++)
#pragma unroll
      for (int si = 0; si < 4; si++) {
        int t = t0 + ti, s = sb + si * 16;
        float x0, x1;
        unpack2(acc[ti][si], x0, x1);
        sM[t * 64 + s] = (s < t) ? (x0 + x1) : 0.f;
      }
  }
  __syncthreads();
  if (tid < 128) {
    int d = tid * 2;
    for (int t = 1; t < BT; t++) {
      unsigned long long acc = 0;
      const float* Mr = &sM[t * 64];
      for (int s = 0; s < t; s++)
        fma2(acc, pack2dup(Mr[s]), *(const unsigned long long*)&sw[s * QS + d]);
      float a0, a1;
      unpack2(acc, a0, a1);
      sw[t * QS + d]     -= a0;
      sw[t * QS + d + 1] -= a1;
    }
  } else if (tid < 256) {
    int d = (tid - 128) * 2;
    for (int t = 1; t < BT; t++) {
      unsigned long long acc = 0;
      const float* Mr = &sM[t * 64];
      for (int s = 0; s < t; s++)
        fma2(acc, pack2dup(Mr[s]), *(const unsigned long long*)&su[s * QS + d]);
      float a0, a1;
      unpack2(acc, a0, a1);
      su[t * QS + d]     -= a0;
      su[t * QS + d + 1] -= a1;
    }
  }
  __syncthreads();
  for (int i = tid; i < 4096; i += 512) {
    int t = i >> 6, dd = (i & 63) * 4;
    float4 wv = *(float4*)&sw[t * QS + dd];
    uint2 hv;
    hv.x = h2(wv.x, wv.y);
    hv.y = h2(wv.z, wv.w);
    *(uint2*)(Wh_g + base + (size_t)t * DH + dd) = hv;
    *(float4*)(Ut + base + (size_t)t * DH + dd) = *(float4*)&su[t * QS + dd];
  }
}

// -------------------- attn = tril(q k^T) -> fp16 --------------------
#define ATTN_SMEM (2*64*QS*4)
__global__ __launch_bounds__(512) void attn_kernel(
    const float* __restrict__ qt, const float* __restrict__ kt, __half* __restrict__ att)
{
  extern __shared__ float sh[];
  float* sq = sh;
  float* sk = sq + 64 * QS;
  int blk = blockIdx.x;
  int c = blk % NC, bh = blk / NC;
  size_t base = ((size_t)bh * LL + (size_t)c * BT) * DH;
  int tid = threadIdx.x;
  for (int i = tid; i < 4096; i += 512) {
    int t = i >> 6, dd = (i & 63) * 4;
    *(float4*)&sq[t * QS + dd] = *(const float4*)(qt + base + (size_t)t * DH + dd);
    *(float4*)&sk[t * QS + dd] = *(const float4*)(kt + base + (size_t)t * DH + dd);
  }
  __syncthreads();
  __half* ap = att + (size_t)blk * (BT * BT);
  int tp = tid >> 4, sb = tid & 15;
  int t0 = tp * 2, t1 = t0 + 1;
  unsigned long long acc[2][4];
#pragma unroll
  for (int ti = 0; ti < 2; ti++)
#pragma unroll
    for (int si = 0; si < 4; si++) acc[ti][si] = 0;
  if (sb <= t1) {
    const float* q0 = &sq[t0 * QS];
    const float* q1 = &sq[t1 * QS];
#pragma unroll 2
    for (int d = 0; d < DH; d += 4) {
      ulonglong2 a0 = *(const ulonglong2*)(q0 + d);
      ulonglong2 a1 = *(const ulonglong2*)(q1 + d);
#pragma unroll
      for (int si = 0; si < 4; si++) {
        ulonglong2 kv = *(const ulonglong2*)(&sk[(sb + si * 16) * QS + d]);
        fma2(acc[0][si], a0.x, kv.x); fma2(acc[0][si], a0.y, kv.y);
        fma2(acc[1][si], a1.x, kv.x); fma2(acc[1][si], a1.y, kv.y);
      }
    }
  }
#pragma unroll
  for (int ti = 0; ti < 2; ti++)
#pragma unroll
    for (int si = 0; si < 4; si++) {
      int t = t0 + ti, s = sb + si * 16;
      float x0, x1;
      unpack2(acc[ti][si], x0, x1);
      ap[t * 64 + s] = __float2half_rn((s <= t) ? (x0 + x1) : 0.f);
    }
}

// -------------------- scan: fused A+B (full-K warps), 2 syncs/chunk --------------------
#define STG_Q 33792                              // 64 rows * 528 B
#define STG_T 9216                               // 64 rows * 144 B
#define STG_BYTES (2*STG_Q + STG_T)              // 76800
#define SCAN_SMEM (36864 + 9216 + 9216 + 2*STG_BYTES)   // 208896

__device__ __forceinline__ void scan_stage_async(
    const __half* __restrict__ qh, const __half* __restrict__ wh,
    const __half* __restrict__ th,
    size_t base, size_t abase, uint32_t sb, int tid)
{
#pragma unroll
  for (int it = 0; it < 8; it++) {
    int i = tid + it * 512;                  // 0..4095
    int a = i >> 11;                         // 0: q, 1: w
    int r = (i >> 5) & 63;
    int d8 = i & 31;
    const __half* src = (a ? wh : qh) + base + (size_t)r * DH + d8 * 8;
    cpa16(sb + a * STG_Q + (uint32_t)(r * 528 + d8 * 16), src);
  }
  {
    int tt = tid >> 3, cc = tid & 7;
    cpa16(sb + 2 * STG_Q + (uint32_t)(tt * 144 + cc * 16), th + abase + tt * 64 + cc * 8);
  }
}

__global__ __launch_bounds__(512) void scan_kernel(
    const __half* __restrict__ qh, const __half* __restrict__ khT,
    const __half* __restrict__ wh, const float* __restrict__ ut,
    const __half* __restrict__ atth, float* __restrict__ og)
{
  extern __shared__ char smc[];
  float* S  = (float*)smc;                       // [256][36]
  float* Un = (float*)(smc + 36864);             // [64][36]
  float* P  = (float*)(smc + 46080);             // [64][36] (q@S final)
  char*  stg = smc + 55296;
  const uint32_t stg_s0 = (uint32_t)__cvta_generic_to_shared(stg);

  int blk = blockIdx.x;
  int vb = blk & 7;
  int bh = blk >> 3;
  int b = bh / HH, h = bh % HH;
  int tid = threadIdx.x;
  int lane = tid & 31, wrp = tid >> 5;
  int fr = lane >> 2;
  int fc = (lane & 3) * 2;
  int dw = wrp * 16;
  // fused A+B mapping: which x ttile x nhalf
  int which = wrp >> 3;           // 0: q@S, 1: w@S (->Un)
  int sub = wrp & 7;
  int ttile = sub >> 1;           // 0..3
  int nh = sub & 1;               // 0..1 (16 v-cols each)
  int tb = ttile * 16;
  // phase-C mapping
  int cmt = wrp >> 2;
  int cnt = wrp & 3;
  int ctb = cmt * 16, cnb = cnt * 8;

  for (int i = tid; i < 256 * SCS; i += 512) S[i] = 0.f;

  // prologue: stage chunk 0
  {
    size_t base0 = ((size_t)bh * LL) * DH;
    size_t abase0 = (size_t)bh * NC * 4096;
    scan_stage_async(qh, wh, atth, base0, abase0, stg_s0, tid);
    CP_COMMIT();
  }
  CP_WAIT(0);
  __syncthreads();

  for (int c = 0; c < NC; c++) {
    size_t base = ((size_t)bh * LL + (size_t)c * BT) * DH;
    char* sb_c = stg + (c & 1) * STG_BYTES;
    const __half* Qh = (const __half*)sb_c;
    const __half* Wh = (const __half*)(sb_c + STG_Q);
    const __half* Th = (const __half*)(sb_c + 2 * STG_Q);

    // prefetch chunk c+1 stage (opposite buffer; safe across this chunk)
    if (c + 1 < NC) {
      size_t basen = ((size_t)bh * LL + (size_t)(c + 1) * BT) * DH;
      size_t abasen = ((size_t)bh * NC + (c + 1)) * 4096;
      scan_stage_async(qh, wh, atth, basen, abasen,
                       stg_s0 + ((c + 1) & 1) * STG_BYTES, tid);
      CP_COMMIT();
    }

    // register-prefetch k fragments for Phase D (transposed khT: [d][t])
    uint32_t ka[4][4];
    {
      const __half* ktile = khT + ((size_t)bh * NC + c) * (DH * BT);
      const __half* kr0 = ktile + (dw + fr) * BT;
      const __half* kr1 = ktile + (dw + fr + 8) * BT;
#pragma unroll
      for (int s = 0; s < 4; s++) {
        int kk = s * 16;
        ka[s][0] = *(const uint32_t*)(kr0 + kk + fc);
        ka[s][1] = *(const uint32_t*)(kr1 + kk + fc);
        ka[s][2] = *(const uint32_t*)(kr0 + kk + fc + 8);
        ka[s][3] = *(const uint32_t*)(kr1 + kk + fc + 8);
      }
    }

    // ---- Phase A+B fused: full-K MMA; q -> P final, w -> Un = u - w@S ----
    {
      float acc[2][4];
#pragma unroll
      for (int vt = 0; vt < 2; vt++)
#pragma unroll
        for (int e = 0; e < 4; e++) acc[vt][e] = 0.f;
      const __half* Ab = which ? Wh : Qh;
      const __half* ar0 = Ab + (tb + fr) * QHS;
      const __half* ar1 = Ab + (tb + fr + 8) * QHS;
#pragma unroll
      for (int kk = 0; kk < DH; kk += 16) {
        uint32_t a[4];
        a[0] = *(const uint32_t*)(ar0 + kk + fc);
        a[1] = *(const uint32_t*)(ar1 + kk + fc);
        a[2] = *(const uint32_t*)(ar0 + kk + fc + 8);
        a[3] = *(const uint32_t*)(ar1 + kk + fc + 8);
        const float* s0 = &S[(kk + fc) * SCS];
        const float* s1 = &S[(kk + fc + 1) * SCS];
        const float* s8 = &S[(kk + fc + 8) * SCS];
        const float* s9 = &S[(kk + fc + 9) * SCS];
#pragma unroll
        for (int vt = 0; vt < 2; vt++) {
          int vn = (nh * 2 + vt) * 8 + fr;
          uint32_t b0 = h2(s0[vn], s1[vn]);
          uint32_t b1 = h2(s8[vn], s9[vn]);
          mma16816(acc[vt], a, b0, b1);
        }
      }
      if (which == 0) {
#pragma unroll
        for (int vt = 0; vt < 2; vt++) {
          int vc = (nh * 2 + vt) * 8 + fc;
          *(float2*)&P[(tb + fr) * SCS + vc]       = make_float2(acc[vt][0], acc[vt][1]);
          *(float2*)&P[(tb + fr + 8) * SCS + vc]   = make_float2(acc[vt][2], acc[vt][3]);
        }
      } else {
        size_t ub0 = base + (size_t)(tb + fr) * DH + vb * 32;
        size_t ub1 = base + (size_t)(tb + fr + 8) * DH + vb * 32;
#pragma unroll
        for (int vt = 0; vt < 2; vt++) {
          int vc = (nh * 2 + vt) * 8 + fc;
          float2 u0 = *(const float2*)(ut + ub0 + vc);
          float2 u1 = *(const float2*)(ut + ub1 + vc);
          *(float2*)&Un[(tb + fr) * SCS + vc] =
              make_float2(u0.x - acc[vt][0], u0.y - acc[vt][1]);
          *(float2*)&Un[(tb + fr + 8) * SCS + vc] =
              make_float2(u1.x - acc[vt][2], u1.y - acc[vt][3]);
        }
      }
    }
    __syncthreads();

    // ---- Phase C: o = q@S + T @ Un via fp16 MMA (T upper triangle is zero) ----
    {
      float cacc[4] = {0.f, 0.f, 0.f, 0.f};
#pragma unroll
      for (int kk = 0; kk < BT; kk += 16) {
        const __half* t0p = Th + (ctb + fr) * THS + kk;
        const __half* t1p = Th + (ctb + fr + 8) * THS + kk;
        uint32_t a[4];
        a[0] = *(const uint32_t*)(t0p + fc);
        a[1] = *(const uint32_t*)(t1p + fc);
        a[2] = *(const uint32_t*)(t0p + fc + 8);
        a[3] = *(const uint32_t*)(t1p + fc + 8);
        const float* un0 = &Un[(kk + fc) * SCS];
        const float* un1 = &Un[(kk + fc + 1) * SCS];
        const float* un8 = &Un[(kk + fc + 8) * SCS];
        const float* un9 = &Un[(kk + fc + 9) * SCS];
        int n = cnb + fr;
        uint32_t b0 = h2(un0[n], un1[n]);
        uint32_t b1 = h2(un8[n], un9[n]);
        mma16816(cacc, a, b0, b1);
      }
      int r0 = ctb + fr, r1 = ctb + fr + 8;
      float2 p0 = *(const float2*)&P[r0 * SCS + cnb + fc];
      float2 p1 = *(const float2*)&P[r1 * SCS + cnb + fc];
      size_t o0 = (((size_t)b * LL + (size_t)c * BT + r0) * HH + h) * DH + vb * 32 + cnb + fc;
      size_t o1 = (((size_t)b * LL + (size_t)c * BT + r1) * HH + h) * DH + vb * 32 + cnb + fc;
      *(float2*)&og[o0] = make_float2(p0.x + cacc[0], p0.y + cacc[1]);
      *(float2*)&og[o1] = make_float2(p1.x + cacc[2], p1.y + cacc[3]);
    }

    // ---- Phase D: S += k^T @ u_new via fp16 MMA (ka regs) ----
    {
      float sacc[4][4];
#pragma unroll
      for (int vt = 0; vt < 4; vt++)
#pragma unroll
        for (int e = 0; e < 4; e++) sacc[vt][e] = 0.f;
#pragma unroll
      for (int s = 0; s < 4; s++) {
        int kk = s * 16;
        const float* un0 = &Un[(kk + fc) * SCS];
        const float* un1 = &Un[(kk + fc + 1) * SCS];
        const float* un8 = &Un[(kk + fc + 8) * SCS];
        const float* un9 = &Un[(kk + fc + 9) * SCS];
#pragma unroll
        for (int vt = 0; vt < 4; vt++) {
          uint32_t b0 = h2(un0[vt * 8 + fr], un1[vt * 8 + fr]);
          uint32_t b1 = h2(un8[vt * 8 + fr], un9[vt * 8 + fr]);
          mma16816(sacc[vt], ka[s], b0, b1);
        }
      }
#pragma unroll
      for (int vt = 0; vt < 4; vt++) {
        float2* sp0 = (float2*)&S[(dw + fr) * SCS + vt * 8 + fc];
        float2 v0r = *sp0;
        v0r.x += sacc[vt][0]; v0r.y += sacc[vt][1];
        *sp0 = v0r;
        float2* sp1 = (float2*)&S[(dw + fr + 8) * SCS + vt * 8 + fc];
        float2 v1r = *sp1;
        v1r.x += sacc[vt][2]; v1r.y += sacc[vt][3];
        *sp1 = v1r;
      }
    }
    CP_WAIT(0);
    __syncthreads();
  }
}

// -------------------- per-head RMSNorm * g_norm -> fp16 output --------------------
__global__ __launch_bounds__(256) void rms_kernel(
    const float* __restrict__ og, const float* __restrict__ gn, __half* __restrict__ on)
{
  int w = threadIdx.x >> 5, lane = threadIdx.x & 31;
  size_t idx = (size_t)blockIdx.x * 8 + w;
  const float* ip = og + idx * DH;
  float2 v[4];
  float ss = 0.f;
#pragma unroll
  for (int j = 0; j < 4; j++) {
    v[j] = *(const float2*)(ip + lane * 2 + j * 64);
    ss += v[j].x * v[j].x + v[j].y * v[j].y;
  }
#pragma unroll
  for (int o = 16; o; o >>= 1) ss += __shfl_xor_sync(0xffffffffu, ss, o);
  float scale = rsqrtf(ss * (1.f / DH) + 1e-5f);
  __half* op = on + idx * DH;
#pragma unroll
  for (int j = 0; j < 4; j++) {
    int e = lane * 2 + j * 64;
    float2 g = *(const float2*)(gn + e);
    __half2 hv = __floats2half2_rn(v[j].x * scale * g.x, v[j].y * scale * g.y);
    *(__half2*)(op + e) = hv;
  }
}

// -------------------- host launch --------------------
extern "C" void kernel_launch(void* const* d_in, const int* in_sizes, int n_in,
                              void* d_out, int out_size)
{
  const float* hs = (const float*)d_in[0];
  const float* Wq = (const float*)d_in[1];
  const float* Wk = (const float*)d_in[2];
  const float* Wv = (const float*)d_in[3];
  const float* Wb = (const float*)d_in[4];
  const float* cq = (const float*)d_in[5];
  const float* ck = (const float*)d_in[6];
  const float* cv = (const float*)d_in[7];
  const float* gn = (const float*)d_in[8];
  const float* Wo = (const float*)d_in[9];
  float* out = (float*)d_out;

  float *preq, *prek, *prev, *qt, *kt, *vt, *ut, *beta, *og;
  __half *qh, *khT, *ws, *atth, *ah, *wh;
  cudaGetSymbolAddress((void**)&preq, g_preq);
  cudaGetSymbolAddress((void**)&prek, g_prek);
  cudaGetSymbolAddress((void**)&prev, g_prev);
  cudaGetSymbolAddress((void**)&qt, g_qt);
  cudaGetSymbolAddress((void**)&kt, g_kt);
  cudaGetSymbolAddress((void**)&vt, g_vt);
  cudaGetSymbolAddress((void**)&ut, g_ut);
  cudaGetSymbolAddress((void**)&beta, g_beta);
  cudaGetSymbolAddress((void**)&og, g_og);
  cudaGetSymbolAddress((void**)&qh, g_qh);
  cudaGetSymbolAddress((void**)&khT, g_khT);
  cudaGetSymbolAddress((void**)&ws, g_ws);
  cudaGetSymbolAddress((void**)&atth, g_atth);
  cudaGetSymbolAddress((void**)&ah, g_ah);
  cudaGetSymbolAddress((void**)&wh, g_wh);

  cudaFuncSetAttribute(gemm_h_kernel, cudaFuncAttributeMaxDynamicSharedMemorySize, GEMM_SMEM);
  cudaFuncSetAttribute(solve_kernel, cudaFuncAttributeMaxDynamicSharedMemorySize, SOLVE_SMEM);
  cudaFuncSetAttribute(attn_kernel, cudaFuncAttributeMaxDynamicSharedMemorySize, ATTN_SMEM);
  cudaFuncSetAttribute(scan_kernel, cudaFuncAttributeMaxDynamicSharedMemorySize, SCAN_SMEM);

  dim3 gg(DDIM / 128, (BB * LL) / 128);
  const int actN4 = BLD / 4, wN4 = DD2 / 4;

  cvt_kernel<<<(actN4 + 255) / 256, 256>>>(hs, ah, actN4);
  cvt_kernel<<<(wN4 + 255) / 256, 256>>>(Wq, wh + 0 * (size_t)DD2, wN4);
  cvt_kernel<<<(wN4 + 255) / 256, 256>>>(Wk, wh + 1 * (size_t)DD2, wN4);
  gemm_h_kernel<<<gg, 256, GEMM_SMEM>>>(ah, wh + 0 * (size_t)DD2, preq, BB * LL, DDIM, DDIM);
  cvt_kernel<<<(wN4 + 255) / 256, 256>>>(Wv, wh + 2 * (size_t)DD2, wN4);
  cvt_kernel<<<(wN4 + 255) / 256, 256>>>(Wo, wh + 3 * (size_t)DD2, wN4);
  gemm_h_kernel<<<gg, 256, GEMM_SMEM>>>(ah, wh + 1 * (size_t)DD2, prek, BB * LL, DDIM, DDIM);
  gemm_h_kernel<<<gg, 256, GEMM_SMEM>>>(ah, wh + 2 * (size_t)DD2, prev, BB * LL, DDIM, DDIM);
  beta_kernel<<<BB * LL, 256>>>(hs, Wb, beta);

  conv_kernel<<<BB * HH * (LL / 8), 256>>>(preq, cq, qt, qh, 0);
  conv_kernel<<<BB * HH * (LL / 8), 256>>>(prek, ck, kt, khT, 1);
  conv_kernel<<<BB * HH * (LL / 8), 256>>>(prev, cv, vt, (__half*)0, 2);

  solve_kernel<<<BB * HH * NC, 512, SOLVE_SMEM>>>(kt, vt, beta, ws, ut);
  attn_kernel<<<BB * HH * NC, 512, ATTN_SMEM>>>(qt, kt, atth);
  scan_kernel<<<BB * HH * 8, 512, SCAN_SMEM>>>(qh, khT, ws, ut, atth, og);

  rms_kernel<<<BB * LL * HH / 8, 256>>>(og, gn, ah);
  gemm_h_kernel<<<gg, 256, GEMM_SMEM>>>(ah, wh + 3 * (size_t)DD2, out, BB * LL, DDIM, DDIM);
}

// round 16
// speedup vs baseline: 4.5746x; 1.0135x over previous
#include <cuda_runtime.h>
#include <cuda_fp16.h>
#include <math.h>
#include <stdint.h>

#define BB 2
#define LL 4096
#define DDIM 2048
#define D3 (3*DDIM)
#define HH 8
#define DH 256
#define BT 64
#define NC 64          // LL / BT
#define BLD (BB*LL*DDIM)
#define DD2 (DDIM*DDIM)
#define QS 260         // padded fp32 tile stride (solve/attn)
#define SCS 36         // S / Un / P row stride (floats)
#define QHS 264        // fp16 staged tile stride (halfs): 256 data + 8 pad = 528 B
#define THS 72         // fp16 T stride (halfs)

// -------------------- scratch (device globals; no allocation) --------------------
__device__ __align__(128) __half g_preh[(size_t)BB*LL*D3];  // fused QKV pre-activations fp16
__device__ float g_qt[BLD];       // fp32 q (attn)
__device__ float g_kt[BLD];       // fp32 k (solve, attn)
__device__ float g_vt[BLD];
__device__ float g_ut[BLD];
__device__ float g_beta[BB*HH*LL];
__device__ float g_og[BLD];
__device__ __align__(128) __half g_qh[BLD];     // fp16 q (scan, row-major [t][d])
__device__ __align__(128) __half g_khT[BLD];    // fp16 k transposed per chunk: [bh][c][d][t]
__device__ __align__(128) __half g_ws[BLD];     // fp16 W (scan)
__device__ __align__(128) __half g_atth[(size_t)BB*HH*NC*BT*BT];
__device__ __align__(128) __half g_ah[BLD];     // activation fp16 (GEMM A)
__device__ __align__(128) __half g_wh[4*DD2];   // weights fp16 (Wq,Wk,Wv,Wo)

// -------------------- helpers --------------------
__device__ __forceinline__ unsigned long long pack2dup(float x) {
  unsigned long long r;
  asm("mov.b64 %0, {%1,%1};" : "=l"(r) : "f"(x));
  return r;
}
__device__ __forceinline__ void unpack2(unsigned long long v, float& x, float& y) {
  asm("mov.b64 {%0,%1}, %2;" : "=f"(x), "=f"(y) : "l"(v));
}
__device__ __forceinline__ void fma2(unsigned long long& d,
                                     unsigned long long a, unsigned long long b) {
  asm("fma.rn.f32x2 %0, %1, %2, %0;" : "+l"(d) : "l"(a), "l"(b));
}
__device__ __forceinline__ uint32_t h2(float x, float y) {
  __half2 h = __floats2half2_rn(x, y);
  return *(uint32_t*)&h;
}

// ==================== convert fp32 -> fp16 ====================
__global__ __launch_bounds__(256) void cvt_kernel(
    const float* __restrict__ x, __half* __restrict__ h, int n4)
{
  int i = blockIdx.x * blockDim.x + threadIdx.x;
  if (i >= n4) return;
  float4 v = *(const float4*)(x + (size_t)i * 4);
  __half2* hp = (__half2*)(h + (size_t)i * 4);
  hp[0] = __floats2half2_rn(v.x, v.y);
  hp[1] = __floats2half2_rn(v.z, v.w);
}

// ==================== fp16 HMMA GEMM, BK=32, 4-stage cp.async ====================
#define GSTRIDE 40
#define GTILE (128*GSTRIDE)
#define ABYTES (GTILE*2)
#define STAGEB (2*ABYTES)
#define NSTAGE 4
#define GEMM_SMEM (NSTAGE*STAGEB)

__device__ __forceinline__ void cpa16(uint32_t dst, const void* src) {
  asm volatile("cp.async.ca.shared.global [%0], [%1], 16;" :: "r"(dst), "l"(src));
}
#define CP_COMMIT() asm volatile("cp.async.commit_group;" ::: "memory")
#define CP_WAIT(n)  asm volatile("cp.async.wait_group %0;" :: "n"(n) : "memory")

__device__ __forceinline__ void ldsm4(uint32_t* r, uint32_t addr) {
  asm volatile("ldmatrix.sync.aligned.m8n8.x4.shared.b16 {%0,%1,%2,%3}, [%4];"
    : "=r"(r[0]), "=r"(r[1]), "=r"(r[2]), "=r"(r[3]) : "r"(addr));
}
__device__ __forceinline__ void mma16816(float* d, const uint32_t* a, uint32_t b0, uint32_t b1) {
  asm volatile("mma.sync.aligned.m16n8k16.row.col.f32.f16.f16.f32 "
    "{%0,%1,%2,%3}, {%4,%5,%6,%7}, {%8,%9}, {%0,%1,%2,%3};"
    : "+f"(d[0]), "+f"(d[1]), "+f"(d[2]), "+f"(d[3])
    : "r"(a[0]), "r"(a[1]), "r"(a[2]), "r"(a[3]), "r"(b0), "r"(b1));
}

__device__ __forceinline__ void load_stage_async(
    const __half* __restrict__ A, const __half* __restrict__ B,
    int bm, int bn, int K, int k0, uint32_t sb, int tid)
{
  const __half* srcs[2] = {A, B};
  const int rb[2] = {bm, bn};
#pragma unroll
  for (int a = 0; a < 2; a++) {
#pragma unroll
    for (int i = 0; i < 2; i++) {
      int idx = tid + i * 256;
      int r = idx >> 2, ch = idx & 3;
      const __half* g = srcs[a] + (size_t)(rb[a] + r) * K + k0 + ch * 8;
      uint32_t dst = sb + a * ABYTES + (uint32_t)(r * 80 + ch * 16);
      cpa16(dst, g);
    }
  }
}

__global__ __launch_bounds__(256, 2) void gemm_h_kernel(
    const __half* __restrict__ A, const __half* __restrict__ B,
    float* __restrict__ C, __half* __restrict__ Ch,
    int M, int N, int K, int out_half)
{
  extern __shared__ char sm[];
  const int tid = threadIdx.x, lane = tid & 31, wid = tid >> 5;
  const int warp_m = wid >> 2, warp_n = wid & 3;
  const int bm = blockIdx.y * 128, bn = blockIdx.x * 128;
  const uint32_t sbase = (uint32_t)__cvta_generic_to_shared(sm);

  float acc[4][4][4];
#pragma unroll
  for (int i = 0; i < 4; i++)
#pragma unroll
    for (int j = 0; j < 4; j++)
#pragma unroll
      for (int e = 0; e < 4; e++) acc[i][j][e] = 0.f;

  const int NT = K / 32;
#pragma unroll
  for (int p = 0; p < NSTAGE - 1; p++) {
    load_stage_async(A, B, bm, bn, K, p * 32, sbase + p * STAGEB, tid);
    CP_COMMIT();
  }

  const int arow  = warp_m * 64 + (lane & 15);
  const int acol0 = (lane >> 4) * 8;
  const int brow  = warp_n * 32 + (lane >> 4) * 8 + (lane & 7);
  const int bcol0 = ((lane >> 3) & 1) * 8;

  for (int kt = 0; kt < NT; kt++) {
    CP_WAIT(NSTAGE - 2);
    __syncthreads();
    {
      int knext = kt + NSTAGE - 1;
      int kc = knext < NT ? knext : NT - 1;
      load_stage_async(A, B, bm, bn, K, kc * 32, sbase + (knext & (NSTAGE - 1)) * STAGEB, tid);
      CP_COMMIT();
    }
    const uint32_t stb = sbase + (kt & (NSTAGE - 1)) * STAGEB;
    const uint32_t aoff = stb;
    const uint32_t boff = stb + ABYTES;
#pragma unroll
    for (int kk = 0; kk < 32; kk += 16) {
      uint32_t af[4][4], bf[2][4];
#pragma unroll
      for (int mt = 0; mt < 4; mt++) {
        uint32_t ab = (uint32_t)(((arow + mt * 16) * GSTRIDE + kk + acol0) * 2);
        ldsm4(af[mt], aoff + ab);
      }
#pragma unroll
      for (int p = 0; p < 2; p++) {
        uint32_t bb = (uint32_t)(((brow + p * 16) * GSTRIDE + kk + bcol0) * 2);
        ldsm4(bf[p], boff + bb);
      }
#pragma unroll
      for (int mt = 0; mt < 4; mt++)
#pragma unroll
        for (int nt = 0; nt < 4; nt++) {
          const uint32_t* bp = bf[nt >> 1];
          int bi = (nt & 1) * 2;
          mma16816(acc[mt][nt], af[mt], bp[bi], bp[bi + 1]);
        }
    }
  }
  __syncthreads();
  const int row0 = bm + warp_m * 64 + (lane >> 2);
  const int col0 = bn + warp_n * 32 + (lane & 3) * 2;
  if (out_half) {
#pragma unroll
    for (int mt = 0; mt < 4; mt++)
#pragma unroll
      for (int nt = 0; nt < 4; nt++) {
        int r = row0 + mt * 16;
        int c = col0 + nt * 8;
        *(__half2*)(Ch + (size_t)r * N + c) =
            __floats2half2_rn(acc[mt][nt][0], acc[mt][nt][1]);
        *(__half2*)(Ch + (size_t)(r + 8) * N + c) =
            __floats2half2_rn(acc[mt][nt][2], acc[mt][nt][3]);
      }
  } else {
#pragma unroll
    for (int mt = 0; mt < 4; mt++)
#pragma unroll
      for (int nt = 0; nt < 4; nt++) {
        int r = row0 + mt * 16;
        int c = col0 + nt * 8;
        *(float2*)(C + (size_t)r * N + c)       = make_float2(acc[mt][nt][0], acc[mt][nt][1]);
        *(float2*)(C + (size_t)(r + 8) * N + c) = make_float2(acc[mt][nt][2], acc[mt][nt][3]);
      }
  }
}

// -------------------- beta = sigmoid(hs @ Wb^T), [B,H,L] --------------------
__global__ __launch_bounds__(256) void beta_kernel(
    const float* __restrict__ hs, const float* __restrict__ Wb, float* __restrict__ beta)
{
  int bl = blockIdx.x;
  int b = bl / LL, l = bl % LL;
  int w = threadIdx.x >> 5, lane = threadIdx.x & 31;
  const float* x = hs + (size_t)bl * DDIM;
  const float* wb = Wb + (size_t)w * DDIM;
  float s = 0.f;
  for (int d = lane; d < DDIM; d += 32) s += x[d] * wb[d];
#pragma unroll
  for (int o = 16; o; o >>= 1) s += __shfl_xor_sync(0xffffffffu, s, o);
  if (lane == 0)
    beta[((size_t)b * HH + w) * LL + l] = 1.f / (1.f + expf(-s));
}

// -------- conv + SiLU (+l2norm), fp16 input (fused QKV layout [M][6144]) ----------
// mode0: q (+fp16 row copy); mode1: k (+fp16 transposed); mode2: v
__global__ __launch_bounds__(256) void conv_kernel(
    const __half* __restrict__ pre, const float* __restrict__ cw,
    float* __restrict__ out, __half* __restrict__ outh, int mode)
{
  int blk = blockIdx.x;
  int lt = blk & (LL / 8 - 1);
  int bh = blk >> 9;
  int h = bh % HH, b = bh / HH;
  int w = threadIdx.x >> 5, lane = threadIdx.x & 31;
  int l = lt * 8 + w;
  const __half* base = pre + (size_t)(b * LL) * D3 + mode * DDIM + h * DH;
  float y[2][4];
  float ss = 0.f;
#pragma unroll
  for (int j = 0; j < 2; j++) {
    int dd = lane * 4 + j * 128;
    int c = h * DH + dd;
    float xs[4][4];
#pragma unroll
    for (int tap = 0; tap < 4; tap++) {
      if (l >= tap) {
        uint2 raw = *(const uint2*)(base + (size_t)(l - tap) * D3 + dd);
        float2 f01 = __half22float2(*(__half2*)&raw.x);
        float2 f23 = __half22float2(*(__half2*)&raw.y);
        xs[0][tap] = f01.x; xs[1][tap] = f01.y; xs[2][tap] = f23.x; xs[3][tap] = f23.y;
      } else {
        xs[0][tap] = 0.f; xs[1][tap] = 0.f; xs[2][tap] = 0.f; xs[3][tap] = 0.f;
      }
    }
#pragma unroll
    for (int ci = 0; ci < 4; ci++) {
      float4 cv = *(const float4*)(cw + (size_t)(c + ci) * 4);
      float acc = xs[ci][0] * cv.w + xs[ci][1] * cv.z + xs[ci][2] * cv.y + xs[ci][3] * cv.x;
      float yy = acc / (1.f + expf(-acc));
      y[j][ci] = yy;
      ss += yy * yy;
    }
  }
  float scale = 1.f;
  if (mode < 2) {
#pragma unroll
    for (int o = 16; o; o >>= 1) ss += __shfl_xor_sync(0xffffffffu, ss, o);
    scale = rsqrtf(ss + 1e-6f);
    if (mode == 0) scale *= 0.0625f;
  }
  size_t ob = (((size_t)b * HH + h) * LL + l) * DH;
  float* op = out + ob;
  int cch = l >> 6, tloc = l & 63;
  __half* tp = outh + ((size_t)(b * HH + h) * NC + cch) * (DH * BT);
#pragma unroll
  for (int j = 0; j < 2; j++) {
    int dd = lane * 4 + j * 128;
    float4 yv = make_float4(y[j][0] * scale, y[j][1] * scale,
                            y[j][2] * scale, y[j][3] * scale);
    *(float4*)(op + dd) = yv;
    if (mode == 0) {
      uint2 hv;
      hv.x = h2(yv.x, yv.y);
      hv.y = h2(yv.z, yv.w);
      *(uint2*)(outh + ob + dd) = hv;
    } else if (mode == 1) {
      tp[(dd + 0) * BT + tloc] = __float2half_rn(yv.x);
      tp[(dd + 1) * BT + tloc] = __float2half_rn(yv.y);
      tp[(dd + 2) * BT + tloc] = __float2half_rn(yv.z);
      tp[(dd + 3) * BT + tloc] = __float2half_rn(yv.w);
    }
  }
}

// -------------------- per-chunk triangular solve; W stored fp16 --------------------
#define SOLVE_SMEM ((3*64*QS + 64*64 + 64) * 4)
__global__ __launch_bounds__(512) void solve_kernel(
    const float* __restrict__ kt, const float* __restrict__ vt,
    const float* __restrict__ beta, __half* __restrict__ Wh_g, float* __restrict__ Ut)
{
  extern __shared__ float sh[];
  float* sk = sh;
  float* sw = sk + 64 * QS;
  float* su = sw + 64 * QS;
  float* sM = su + 64 * QS;
  float* sbeta = sM + 64 * 64;
  int blk = blockIdx.x;
  int c = blk % NC, bh = blk / NC;
  size_t base = ((size_t)bh * LL + (size_t)c * BT) * DH;
  int tid = threadIdx.x;

  if (tid < 64) sbeta[tid] = beta[(size_t)bh * LL + c * BT + tid];
  __syncthreads();
  for (int i = tid; i < 4096; i += 512) {
    int t = i >> 6, dd = (i & 63) * 4;
    float bt = sbeta[t];
    float4 kv = *(const float4*)(kt + base + (size_t)t * DH + dd);
    float4 vv = *(const float4*)(vt + base + (size_t)t * DH + dd);
    *(float4*)&sk[t * QS + dd] = kv;
    *(float4*)&sw[t * QS + dd] = make_float4(kv.x * bt, kv.y * bt, kv.z * bt, kv.w * bt);
    *(float4*)&su[t * QS + dd] = make_float4(vv.x * bt, vv.y * bt, vv.z * bt, vv.w * bt);
  }
  __syncthreads();
  {
    int tp = tid >> 4, sb = tid & 15;
    int t0 = tp * 2, t1 = t0 + 1;
    unsigned long long acc[2][4];
#pragma unroll
    for (int ti = 0; ti < 2; ti++)
#pragma unroll
      for (int si = 0; si < 4; si++) acc[ti][si] = 0;
    if (sb < t1) {
      const float* q0 = &sw[t0 * QS];
      const float* q1 = &sw[t1 * QS];
#pragma unroll 2
      for (int d = 0; d < DH; d += 4) {
        ulonglong2 a0 = *(const ulonglong2*)(q0 + d);
        ulonglong2 a1 = *(const ulonglong2*)(q1 + d);
#pragma unroll
        for (int si = 0; si < 4; si++) {
          ulonglong2 kv = *(const ulonglong2*)(&sk[(sb + si * 16) * QS + d]);
          fma2(acc[0][si], a0.x, kv.x); fma2(acc[0][si], a0.y, kv.y);
          fma2(acc[1][si], a1.x, kv.x); fma2(acc[1][si], a1.y, kv.y);
        }
      }
    }
#pragma unroll
    for (int ti = 0; ti < 2; ti++)
#pragma unroll
      for (int si = 0; si < 4; si++) {
        int t = t0 + ti, s = sb + si * 16;
        float x0, x1;
        unpack2(acc[ti][si], x0, x1);
        sM[t * 64 + s] = (s < t) ? (x0 + x1) : 0.f;
      }
  }
  __syncthreads();
  if (tid < 128) {
    int d = tid * 2;
    for (int t = 1; t < BT; t++) {
      unsigned long long acc = 0;
      const float* Mr = &sM[t * 64];
      for (int s = 0; s < t; s++)
        fma2(acc, pack2dup(Mr[s]), *(const unsigned long long*)&sw[s * QS + d]);
      float a0, a1;
      unpack2(acc, a0, a1);
      sw[t * QS + d]     -= a0;
      sw[t * QS + d + 1] -= a1;
    }
  } else if (tid < 256) {
    int d = (tid - 128) * 2;
    for (int t = 1; t < BT; t++) {
      unsigned long long acc = 0;
      const float* Mr = &sM[t * 64];
      for (int s = 0; s < t; s++)
        fma2(acc, pack2dup(Mr[s]), *(const unsigned long long*)&su[s * QS + d]);
      float a0, a1;
      unpack2(acc, a0, a1);
      su[t * QS + d]     -= a0;
      su[t * QS + d + 1] -= a1;
    }
  }
  __syncthreads();
  for (int i = tid; i < 4096; i += 512) {
    int t = i >> 6, dd = (i & 63) * 4;
    float4 wv = *(float4*)&sw[t * QS + dd];
    uint2 hv;
    hv.x = h2(wv.x, wv.y);
    hv.y = h2(wv.z, wv.w);
    *(uint2*)(Wh_g + base + (size_t)t * DH + dd) = hv;
    *(float4*)(Ut + base + (size_t)t * DH + dd) = *(float4*)&su[t * QS + dd];
  }
}

// -------------------- attn = tril(q k^T) -> fp16 --------------------
#define ATTN_SMEM (2*64*QS*4)
__global__ __launch_bounds__(512) void attn_kernel(
    const float* __restrict__ qt, const float* __restrict__ kt, __half* __restrict__ att)
{
  extern __shared__ float sh[];
  float* sq = sh;
  float* sk = sq + 64 * QS;
  int blk = blockIdx.x;
  int c = blk % NC, bh = blk / NC;
  size_t base = ((size_t)bh * LL + (size_t)c * BT) * DH;
  int tid = threadIdx.x;
  for (int i = tid; i < 4096; i += 512) {
    int t = i >> 6, dd = (i & 63) * 4;
    *(float4*)&sq[t * QS + dd] = *(const float4*)(qt + base + (size_t)t * DH + dd);
    *(float4*)&sk[t * QS + dd] = *(const float4*)(kt + base + (size_t)t * DH + dd);
  }
  __syncthreads();
  __half* ap = att + (size_t)blk * (BT * BT);
  int tp = tid >> 4, sb = tid & 15;
  int t0 = tp * 2, t1 = t0 + 1;
  unsigned long long acc[2][4];
#pragma unroll
  for (int ti = 0; ti < 2; ti++)
#pragma unroll
    for (int si = 0; si < 4; si++) acc[ti][si] = 0;
  if (sb <= t1) {
    const float* q0 = &sq[t0 * QS];
    const float* q1 = &sq[t1 * QS];
#pragma unroll 2
    for (int d = 0; d < DH; d += 4) {
      ulonglong2 a0 = *(const ulonglong2*)(q0 + d);
      ulonglong2 a1 = *(const ulonglong2*)(q1 + d);
#pragma unroll
      for (int si = 0; si < 4; si++) {
        ulonglong2 kv = *(const ulonglong2*)(&sk[(sb + si * 16) * QS + d]);
        fma2(acc[0][si], a0.x, kv.x); fma2(acc[0][si], a0.y, kv.y);
        fma2(acc[1][si], a1.x, kv.x); fma2(acc[1][si], a1.y, kv.y);
      }
    }
  }
#pragma unroll
  for (int ti = 0; ti < 2; ti++)
#pragma unroll
    for (int si = 0; si < 4; si++) {
      int t = t0 + ti, s = sb + si * 16;
      float x0, x1;
      unpack2(acc[ti][si], x0, x1);
      ap[t * 64 + s] = __float2half_rn((s <= t) ? (x0 + x1) : 0.f);
    }
}

// -------------------- scan: fused A+B (full-K warps), 2 syncs/chunk --------------------
#define STG_Q 33792                              // 64 rows * 528 B
#define STG_T 9216                               // 64 rows * 144 B
#define STG_BYTES (2*STG_Q + STG_T)              // 76800
#define SCAN_SMEM (36864 + 9216 + 9216 + 2*STG_BYTES)   // 208896

__device__ __forceinline__ void scan_stage_async(
    const __half* __restrict__ qh, const __half* __restrict__ wh,
    const __half* __restrict__ th,
    size_t base, size_t abase, uint32_t sb, int tid)
{
#pragma unroll
  for (int it = 0; it < 8; it++) {
    int i = tid + it * 512;                  // 0..4095
    int a = i >> 11;                         // 0: q, 1: w
    int r = (i >> 5) & 63;
    int d8 = i & 31;
    const __half* src = (a ? wh : qh) + base + (size_t)r * DH + d8 * 8;
    cpa16(sb + a * STG_Q + (uint32_t)(r * 528 + d8 * 16), src);
  }
  {
    int tt = tid >> 3, cc = tid & 7;
    cpa16(sb + 2 * STG_Q + (uint32_t)(tt * 144 + cc * 16), th + abase + tt * 64 + cc * 8);
  }
}

__global__ __launch_bounds__(512) void scan_kernel(
    const __half* __restrict__ qh, const __half* __restrict__ khT,
    const __half* __restrict__ wh, const float* __restrict__ ut,
    const __half* __restrict__ atth, float* __restrict__ og)
{
  extern __shared__ char smc[];
  float* S  = (float*)smc;                       // [256][36]
  float* Un = (float*)(smc + 36864);             // [64][36]
  float* P  = (float*)(smc + 46080);             // [64][36] (q@S final)
  char*  stg = smc + 55296;
  const uint32_t stg_s0 = (uint32_t)__cvta_generic_to_shared(stg);

  int blk = blockIdx.x;
  int vb = blk & 7;
  int bh = blk >> 3;
  int b = bh / HH, h = bh % HH;
  int tid = threadIdx.x;
  int lane = tid & 31, wrp = tid >> 5;
  int fr = lane >> 2;
  int fc = (lane & 3) * 2;
  int dw = wrp * 16;
  int which = wrp >> 3;
  int sub = wrp & 7;
  int ttile = sub >> 1;
  int nh = sub & 1;
  int tb = ttile * 16;
  int cmt = wrp >> 2;
  int cnt = wrp & 3;
  int ctb = cmt * 16, cnb = cnt * 8;

  for (int i = tid; i < 256 * SCS; i += 512) S[i] = 0.f;

  {
    size_t base0 = ((size_t)bh * LL) * DH;
    size_t abase0 = (size_t)bh * NC * 4096;
    scan_stage_async(qh, wh, atth, base0, abase0, stg_s0, tid);
    CP_COMMIT();
  }
  CP_WAIT(0);
  __syncthreads();

  for (int c = 0; c < NC; c++) {
    size_t base = ((size_t)bh * LL + (size_t)c * BT) * DH;
    char* sb_c = stg + (c & 1) * STG_BYTES;
    const __half* Qh = (const __half*)sb_c;
    const __half* Wh = (const __half*)(sb_c + STG_Q);
    const __half* Th = (const __half*)(sb_c + 2 * STG_Q);

    if (c + 1 < NC) {
      size_t basen = ((size_t)bh * LL + (size_t)(c + 1) * BT) * DH;
      size_t abasen = ((size_t)bh * NC + (c + 1)) * 4096;
      scan_stage_async(qh, wh, atth, basen, abasen,
                       stg_s0 + ((c + 1) & 1) * STG_BYTES, tid);
      CP_COMMIT();
    }

    uint32_t ka[4][4];
    {
      const __half* ktile = khT + ((size_t)bh * NC + c) * (DH * BT);
      const __half* kr0 = ktile + (dw + fr) * BT;
      const __half* kr1 = ktile + (dw + fr + 8) * BT;
#pragma unroll
      for (int s = 0; s < 4; s++) {
        int kk = s * 16;
        ka[s][0] = *(const uint32_t*)(kr0 + kk + fc);
        ka[s][1] = *(const uint32_t*)(kr1 + kk + fc);
        ka[s][2] = *(const uint32_t*)(kr0 + kk + fc + 8);
        ka[s][3] = *(const uint32_t*)(kr1 + kk + fc + 8);
      }
    }

    // ---- Phase A+B fused ----
    {
      float acc[2][4];
#pragma unroll
      for (int vt = 0; vt < 2; vt++)
#pragma unroll
        for (int e = 0; e < 4; e++) acc[vt][e] = 0.f;
      const __half* Ab = which ? Wh : Qh;
      const __half* ar0 = Ab + (tb + fr) * QHS;
      const __half* ar1 = Ab + (tb + fr + 8) * QHS;
#pragma unroll
      for (int kk = 0; kk < DH; kk += 16) {
        uint32_t a[4];
        a[0] = *(const uint32_t*)(ar0 + kk + fc);
        a[1] = *(const uint32_t*)(ar1 + kk + fc);
        a[2] = *(const uint32_t*)(ar0 + kk + fc + 8);
        a[3] = *(const uint32_t*)(ar1 + kk + fc + 8);
        const float* s0 = &S[(kk + fc) * SCS];
        const float* s1 = &S[(kk + fc + 1) * SCS];
        const float* s8 = &S[(kk + fc + 8) * SCS];
        const float* s9 = &S[(kk + fc + 9) * SCS];
#pragma unroll
        for (int vt = 0; vt < 2; vt++) {
          int vn = (nh * 2 + vt) * 8 + fr;
          uint32_t b0 = h2(s0[vn], s1[vn]);
          uint32_t b1 = h2(s8[vn], s9[vn]);
          mma16816(acc[vt], a, b0, b1);
        }
      }
      if (which == 0) {
#pragma unroll
        for (int vt = 0; vt < 2; vt++) {
          int vc = (nh * 2 + vt) * 8 + fc;
          *(float2*)&P[(tb + fr) * SCS + vc]       = make_float2(acc[vt][0], acc[vt][1]);
          *(float2*)&P[(tb + fr + 8) * SCS + vc]   = make_float2(acc[vt][2], acc[vt][3]);
        }
      } else {
        size_t ub0 = base + (size_t)(tb + fr) * DH + vb * 32;
        size_t ub1 = base + (size_t)(tb + fr + 8) * DH + vb * 32;
#pragma unroll
        for (int vt = 0; vt < 2; vt++) {
          int vc = (nh * 2 + vt) * 8 + fc;
          float2 u0 = *(const float2*)(ut + ub0 + vc);
          float2 u1 = *(const float2*)(ut + ub1 + vc);
          *(float2*)&Un[(tb + fr) * SCS + vc] =
              make_float2(u0.x - acc[vt][0], u0.y - acc[vt][1]);
          *(float2*)&Un[(tb + fr + 8) * SCS + vc] =
              make_float2(u1.x - acc[vt][2], u1.y - acc[vt][3]);
        }
      }
    }
    __syncthreads();

    // ---- Phase C ----
    {
      float cacc[4] = {0.f, 0.f, 0.f, 0.f};
#pragma unroll
      for (int kk = 0; kk < BT; kk += 16) {
        const __half* t0p = Th + (ctb + fr) * THS + kk;
        const __half* t1p = Th + (ctb + fr + 8) * THS + kk;
        uint32_t a[4];
        a[0] = *(const uint32_t*)(t0p + fc);
        a[1] = *(const uint32_t*)(t1p + fc);
        a[2] = *(const uint32_t*)(t0p + fc + 8);
        a[3] = *(const uint32_t*)(t1p + fc + 8);
        const float* un0 = &Un[(kk + fc) * SCS];
        const float* un1 = &Un[(kk + fc + 1) * SCS];
        const float* un8 = &Un[(kk + fc + 8) * SCS];
        const float* un9 = &Un[(kk + fc + 9) * SCS];
        int n = cnb + fr;
        uint32_t b0 = h2(un0[n], un1[n]);
        uint32_t b1 = h2(un8[n], un9[n]);
        mma16816(cacc, a, b0, b1);
      }
      int r0 = ctb + fr, r1 = ctb + fr + 8;
      float2 p0 = *(const float2*)&P[r0 * SCS + cnb + fc];
      float2 p1 = *(const float2*)&P[r1 * SCS + cnb + fc];
      size_t o0 = (((size_t)b * LL + (size_t)c * BT + r0) * HH + h) * DH + vb * 32 + cnb + fc;
      size_t o1 = (((size_t)b * LL + (size_t)c * BT + r1) * HH + h) * DH + vb * 32 + cnb + fc;
      *(float2*)&og[o0] = make_float2(p0.x + cacc[0], p0.y + cacc[1]);
      *(float2*)&og[o1] = make_float2(p1.x + cacc[2], p1.y + cacc[3]);
    }

    // ---- Phase D ----
    {
      float sacc[4][4];
#pragma unroll
      for (int vt = 0; vt < 4; vt++)
#pragma unroll
        for (int e = 0; e < 4; e++) sacc[vt][e] = 0.f;
#pragma unroll
      for (int s = 0; s < 4; s++) {
        int kk = s * 16;
        const float* un0 = &Un[(kk + fc) * SCS];
        const float* un1 = &Un[(kk + fc + 1) * SCS];
        const float* un8 = &Un[(kk + fc + 8) * SCS];
        const float* un9 = &Un[(kk + fc + 9) * SCS];
#pragma unroll
        for (int vt = 0; vt < 4; vt++) {
          uint32_t b0 = h2(un0[vt * 8 + fr], un1[vt * 8 + fr]);
          uint32_t b1 = h2(un8[vt * 8 + fr], un9[vt * 8 + fr]);
          mma16816(sacc[vt], ka[s], b0, b1);
        }
      }
#pragma unroll
      for (int vt = 0; vt < 4; vt++) {
        float2* sp0 = (float2*)&S[(dw + fr) * SCS + vt * 8 + fc];
        float2 v0r = *sp0;
        v0r.x += sacc[vt][0]; v0r.y += sacc[vt][1];
        *sp0 = v0r;
        float2* sp1 = (float2*)&S[(dw + fr + 8) * SCS + vt * 8 + fc];
        float2 v1r = *sp1;
        v1r.x += sacc[vt][2]; v1r.y += sacc[vt][3];
        *sp1 = v1r;
      }
    }
    CP_WAIT(0);
    __syncthreads();
  }
}

// -------------------- per-head RMSNorm * g_norm -> fp16 output --------------------
__global__ __launch_bounds__(256) void rms_kernel(
    const float* __restrict__ og, const float* __restrict__ gn, __half* __restrict__ on)
{
  int w = threadIdx.x >> 5, lane = threadIdx.x & 31;
  size_t idx = (size_t)blockIdx.x * 8 + w;
  const float* ip = og + idx * DH;
  float2 v[4];
  float ss = 0.f;
#pragma unroll
  for (int j = 0; j < 4; j++) {
    v[j] = *(const float2*)(ip + lane * 2 + j * 64);
    ss += v[j].x * v[j].x + v[j].y * v[j].y;
  }
#pragma unroll
  for (int o = 16; o; o >>= 1) ss += __shfl_xor_sync(0xffffffffu, ss, o);
  float scale = rsqrtf(ss * (1.f / DH) + 1e-5f);
  __half* op = on + idx * DH;
#pragma unroll
  for (int j = 0; j < 4; j++) {
    int e = lane * 2 + j * 64;
    float2 g = *(const float2*)(gn + e);
    __half2 hv = __floats2half2_rn(v[j].x * scale * g.x, v[j].y * scale * g.y);
    *(__half2*)(op + e) = hv;
  }
}

// -------------------- host launch --------------------
extern "C" void kernel_launch(void* const* d_in, const int* in_sizes, int n_in,
                              void* d_out, int out_size)
{
  const float* hs = (const float*)d_in[0];
  const float* Wq = (const float*)d_in[1];
  const float* Wk = (const float*)d_in[2];
  const float* Wv = (const float*)d_in[3];
  const float* Wb = (const float*)d_in[4];
  const float* cq = (const float*)d_in[5];
  const float* ck = (const float*)d_in[6];
  const float* cv = (const float*)d_in[7];
  const float* gn = (const float*)d_in[8];
  const float* Wo = (const float*)d_in[9];
  float* out = (float*)d_out;

  float *qt, *kt, *vt, *ut, *beta, *og;
  __half *preh, *qh, *khT, *ws, *atth, *ah, *wh;
  cudaGetSymbolAddress((void**)&preh, g_preh);
  cudaGetSymbolAddress((void**)&qt, g_qt);
  cudaGetSymbolAddress((void**)&kt, g_kt);
  cudaGetSymbolAddress((void**)&vt, g_vt);
  cudaGetSymbolAddress((void**)&ut, g_ut);
  cudaGetSymbolAddress((void**)&beta, g_beta);
  cudaGetSymbolAddress((void**)&og, g_og);
  cudaGetSymbolAddress((void**)&qh, g_qh);
  cudaGetSymbolAddress((void**)&khT, g_khT);
  cudaGetSymbolAddress((void**)&ws, g_ws);
  cudaGetSymbolAddress((void**)&atth, g_atth);
  cudaGetSymbolAddress((void**)&ah, g_ah);
  cudaGetSymbolAddress((void**)&wh, g_wh);

  cudaFuncSetAttribute(gemm_h_kernel, cudaFuncAttributeMaxDynamicSharedMemorySize, GEMM_SMEM);
  cudaFuncSetAttribute(solve_kernel, cudaFuncAttributeMaxDynamicSharedMemorySize, SOLVE_SMEM);
  cudaFuncSetAttribute(attn_kernel, cudaFuncAttributeMaxDynamicSharedMemorySize, ATTN_SMEM);
  cudaFuncSetAttribute(scan_kernel, cudaFuncAttributeMaxDynamicSharedMemorySize, SCAN_SMEM);

  const int actN4 = BLD / 4, wN4 = DD2 / 4;

  // ALL QKV weights must be converted BEFORE the fused GEMM (R15 bug: Wv was after)
  cvt_kernel<<<(actN4 + 255) / 256, 256>>>(hs, ah, actN4);
  cvt_kernel<<<(wN4 + 255) / 256, 256>>>(Wq, wh + 0 * (size_t)DD2, wN4);
  cvt_kernel<<<(wN4 + 255) / 256, 256>>>(Wk, wh + 1 * (size_t)DD2, wN4);
  cvt_kernel<<<(wN4 + 255) / 256, 256>>>(Wv, wh + 2 * (size_t)DD2, wN4);
  // fused QKV GEMM: C_half[M][6144]
  {
    dim3 gqkv(D3 / 128, (BB * LL) / 128);   // (48, 64)
    gemm_h_kernel<<<gqkv, 256, GEMM_SMEM>>>(ah, wh, (float*)0, preh,
                                            BB * LL, D3, DDIM, 1);
  }
  cvt_kernel<<<(wN4 + 255) / 256, 256>>>(Wo, wh + 3 * (size_t)DD2, wN4);
  beta_kernel<<<BB * LL, 256>>>(hs, Wb, beta);

  conv_kernel<<<BB * HH * (LL / 8), 256>>>(preh, cq, qt, qh, 0);
  conv_kernel<<<BB * HH * (LL / 8), 256>>>(preh, ck, kt, khT, 1);
  conv_kernel<<<BB * HH * (LL / 8), 256>>>(preh, cv, vt, (__half*)0, 2);

  solve_kernel<<<BB * HH * NC, 512, SOLVE_SMEM>>>(kt, vt, beta, ws, ut);
  attn_kernel<<<BB * HH * NC, 512, ATTN_SMEM>>>(qt, kt, atth);
  scan_kernel<<<BB * HH * 8, 512, SCAN_SMEM>>>(qh, khT, ws, ut, atth, og);

  rms_kernel<<<BB * LL * HH / 8, 256>>>(og, gn, ah);
  {
    dim3 go(DDIM / 128, (BB * LL) / 128);
    gemm_h_kernel<<<go, 256, GEMM_SMEM>>>(ah, wh + 3 * (size_t)DD2, out, (__half*)0,
                                          BB * LL, DDIM, DDIM, 0);
  }
}